// round 7
// baseline (speedup 1.0000x reference)
#include <cuda_runtime.h>
#include <cstdint>
#include <math.h>

// Problem constants
#define Bn 2048
#define Sn 50
#define En 256
#define Hn 512
#define Gn 2048        // 4*H
#define Wn 256
#define Ln 50
#define ND (Gn + Wn)   // 2304 : [interleaved dec gates | W2 rows]
#define Vn 51
#define BSn (Bn * Sn)

// ---------------- device scratch (fragment-order layouts) ----------------
__device__ float g_hhi0[Bn * Hn];
__device__ float g_hlo0[Bn * Hn];
__device__ float g_hhi1[Bn * Hn];
__device__ float g_hlo1[Bn * Hn];
__device__ float g_cE[Bn * Hn];                    // encoder cell state [m][j]
__device__ float g_cD[Bn * Hn];                    // decoder cell state
__device__ float g_enchi[(size_t)BSn * Hn];        // enc states, A-frag layout
__device__ float g_enclo[(size_t)BSn * Hn];
__device__ float g_blend1[(size_t)BSn * Wn];       // [(t*Bn+b)][w] row-major
__device__ float g_blend2[Bn * Wn];
__device__ unsigned char g_mask[Bn * Sn];
__device__ float g_eWhi[Gn * Hn];                  // enc Whh, B-frag layout
__device__ float g_eWlo[Gn * Hn];
__device__ float g_dWhi[ND * Hn];                  // dec Whh | W2, B-frag layout
__device__ float g_dWlo[ND * Hn];
__device__ float g_W1hi[Wn * Hn];
__device__ float g_W1lo[Wn * Hn];
__device__ float g_bias_dec2[Gn];
__device__ float g_P[Vn * Gn];                     // emb@Wih^T + enc bias (fp32 exact)

// ---------------- helpers ----------------
__device__ __forceinline__ float sigf(float x) { return 1.0f / (1.0f + expf(-x)); }

__device__ __forceinline__ void tfsplit(float x, float& hi, float& lo) {
    uint32_t u;
    asm("cvt.rna.tf32.f32 %0, %1;" : "=r"(u) : "f"(x));
    hi = __uint_as_float(u);
    float d = x - hi;
    asm("cvt.rna.tf32.f32 %0, %1;" : "=r"(u) : "f"(d));
    lo = __uint_as_float(u);
}

__device__ __forceinline__ void cp16(uint32_t dst, const float* src) {
    asm volatile("cp.async.cg.shared.global [%0], [%1], 16;\n" :: "r"(dst), "l"(src));
}

// mma.sync m16n8k8 tf32: D += A*B  (row.col)
#define MMA(accp, av, b0, b1)                                              \
    asm volatile(                                                          \
        "mma.sync.aligned.m16n8k8.row.col.f32.tf32.tf32.f32 "              \
        "{%0,%1,%2,%3}, {%4,%5,%6,%7}, {%8,%9}, {%0,%1,%2,%3};"            \
        : "+f"((accp)[0]), "+f"((accp)[1]), "+f"((accp)[2]), "+f"((accp)[3]) \
        : "r"((av).x), "r"((av).y), "r"((av).z), "r"((av).w),              \
          "r"(b0), "r"(b1))

// A-fragment global layout: off(m,k) for m16n8k8 A regs
__device__ __forceinline__ size_t afrag(size_t m, int k, int mtiles) {
    int kc = k >> 5, s = (k >> 3) & 3;
    size_t mt = m >> 4;
    int tt = ((int)(m & 7)) * 4 + (k & 3);
    int r = (int)((m >> 3) & 1) + 2 * ((k >> 2) & 1);
    return (((size_t)(kc * 4 + s) * mtiles + mt) * 32 + tt) * 4 + r;
}
// B-fragment global layout (two k8 steps packed per 16B)
__device__ __forceinline__ size_t bfrag(int n, int k, int ntiles) {
    int kc = k >> 5, sp = (k >> 4) & 1, nt = n >> 3;
    int tt = (n & 7) * 4 + (k & 3);
    int r = ((k >> 3) & 1) * 2 + ((k >> 2) & 1);
    return (((size_t)(kc * 2 + sp) * ntiles + nt) * 32 + tt) * 4 + r;
}

// ---------------- prep kernels ----------------
__global__ void k_prep(const float* __restrict__ eWhh,
                       const float* __restrict__ dWhh, const float* __restrict__ dbih,
                       const float* __restrict__ dbhh, const float* __restrict__ W2,
                       const float* __restrict__ W1) {
    int idx = blockIdx.x * blockDim.x + threadIdx.x;
    if (idx < Gn * Hn) {
        int n2 = idx / Hn, k = idx % Hn;
        int g = n2 & 3, j = n2 >> 2;
        float hi, lo;
        tfsplit(eWhh[(g * Hn + j) * Hn + k], hi, lo);
        size_t o = bfrag(n2, k, Gn / 8);
        g_eWhi[o] = hi; g_eWlo[o] = lo;
    }
    if (idx < ND * Hn) {
        int n2 = idx / Hn, k = idx % Hn;
        float v;
        if (n2 < Gn) {
            int g = n2 & 3, j = n2 >> 2;
            v = dWhh[(g * Hn + j) * Hn + k];
        } else {
            v = W2[(size_t)(n2 - Gn) * Hn + k];
        }
        float hi, lo;
        tfsplit(v, hi, lo);
        size_t o = bfrag(n2, k, ND / 8);
        g_dWhi[o] = hi; g_dWlo[o] = lo;
    }
    if (idx < Wn * Hn) {
        int w = idx / Hn, k = idx % Hn;
        float hi, lo;
        tfsplit(W1[idx], hi, lo);
        size_t o = bfrag(w, k, Wn / 8);
        g_W1hi[o] = hi; g_W1lo[o] = lo;
    }
    if (idx < Gn) {
        int g = idx & 3, j = idx >> 2;
        int r = g * Hn + j;
        g_bias_dec2[idx] = dbih[r] + dbhh[r];
    }
}

__global__ void k_prep_P(const float* __restrict__ emb, const float* __restrict__ eWih,
                         const float* __restrict__ ebih, const float* __restrict__ ebhh) {
    int idx = blockIdx.x * blockDim.x + threadIdx.x;
    if (idx >= Vn * Gn) return;
    int v = idx / Gn, n2 = idx % Gn;
    int g = n2 & 3, j = n2 >> 2;
    int r = g * Hn + j;
    const float4* e = reinterpret_cast<const float4*>(emb + (size_t)v * En);
    const float4* w = reinterpret_cast<const float4*>(eWih + (size_t)r * En);
    float s = 0.0f;
    #pragma unroll 8
    for (int k = 0; k < En / 4; k++) {
        float4 a = __ldg(e + k), b = __ldg(w + k);
        s += a.x * b.x + a.y * b.y + a.z * b.z + a.w * b.w;
    }
    g_P[idx] = s + ebih[r] + ebhh[r];
}

__global__ void k_init() {
    int idx = blockIdx.x * blockDim.x + threadIdx.x;
    if (idx < Bn * Hn) { g_hhi0[idx] = 0.0f; g_hlo0[idx] = 0.0f; g_cE[idx] = 0.0f; }
    if (idx < Bn * Sn) g_mask[idx] = 0;
}

// decoder first cell: gates = bias only; c0 already in g_cD (enc h49)
__global__ void k_dec0() {
    int idx = blockIdx.x * blockDim.x + threadIdx.x;
    if (idx >= Bn * Hn) return;
    int b = idx / Hn, j = idx % Hn;
    float gi = g_bias_dec2[4 * j + 0], gf = g_bias_dec2[4 * j + 1];
    float gg = g_bias_dec2[4 * j + 2], go = g_bias_dec2[4 * j + 3];
    float c0 = g_cD[idx];
    float cn = sigf(gf) * c0 + sigf(gi) * tanhf(gg);
    float hn = sigf(go) * tanhf(cn);
    g_cD[idx] = cn;
    float hi, lo;
    tfsplit(hn, hi, lo);
    size_t ao = afrag((size_t)b, j, Bn / 16);
    g_hhi0[ao] = hi; g_hlo0[ao] = lo;
}

// ---------------- tf32 mma.sync GEMM, 4-product split, fused epilogue -------
// C[128,128] = (Ahi+Alo) @ (Bhi+Blo)^T over K=512
// MODE 0: plain store (blend1)  MODE 1: encoder LSTM  MODE 2: dec LSTM | blend2
template <int MODE>
__global__ __launch_bounds__(256, 1) void gemm_mma(
    const float* __restrict__ Ahi, const float* __restrict__ Alo, int Mtiles,
    const float* __restrict__ Bhi, const float* __restrict__ Blo, int Ntiles,
    const float* __restrict__ bias2, const float* __restrict__ P,
    const int* __restrict__ tok,
    float* __restrict__ Cout,
    float* __restrict__ hhi, float* __restrict__ hlo,
    float* __restrict__ cst,
    float* __restrict__ enchi, float* __restrict__ enclo,
    float* __restrict__ cD, int t) {
    extern __shared__ char smem[];
    const int tid = threadIdx.x;
    const int lane = tid & 31, wid = tid >> 5;
    const int bm = blockIdx.y * 128, bn = blockIdx.x * 128;
    const int bm16 = bm >> 4, bn8 = bn >> 3;
    const int mw = wid & 3, nw = wid >> 1 >> 1;   // mw 0..3, nw 0..1

    float acc[2][8][4];
#pragma unroll
    for (int i = 0; i < 2; i++)
#pragma unroll
        for (int jn = 0; jn < 8; jn++)
#pragma unroll
            for (int p = 0; p < 4; p++) acc[i][jn][p] = 0.0f;

    auto issue = [&](int c, int buf) {
#pragma unroll
        for (int q = 0; q < 16; q++) {
            int cid = tid + q * 256;
            int arr = cid >> 10;
            int within = cid & 1023;
            const float* src;
            uint32_t dof;
            if (arr < 2) {
                int s = within >> 8, rest = within & 255;
                const float* base = arr ? Alo : Ahi;
                src = base + ((size_t)(c * 4 + s) * Mtiles + bm16) * 128 + rest * 4;
                dof = (uint32_t)(buf * 65536 + arr * 16384 + within * 16);
            } else {
                int sp = within >> 9, rest = within & 511;
                const float* base = (arr == 2) ? Bhi : Blo;
                src = base + ((size_t)(c * 2 + sp) * Ntiles + bn8) * 128 + rest * 4;
                dof = (uint32_t)(buf * 65536 + 32768 + (arr - 2) * 16384 + within * 16);
            }
            cp16((uint32_t)__cvta_generic_to_shared(smem + dof), src);
        }
        asm volatile("cp.async.commit_group;\n");
    };

    issue(0, 0);
#pragma unroll 1
    for (int c = 0; c < 16; c++) {
        const int buf = c & 1;
        if (c + 1 < 16) {
            issue(c + 1, buf ^ 1);
            asm volatile("cp.async.wait_group 1;\n");
        } else {
            asm volatile("cp.async.wait_group 0;\n");
        }
        __syncthreads();
#pragma unroll
        for (int sp = 0; sp < 2; sp++) {
            uint4 ah[2][2], al[2][2];
#pragma unroll
            for (int st = 0; st < 2; st++) {
                int s = sp * 2 + st;
#pragma unroll
                for (int mt = 0; mt < 2; mt++) {
                    int moff = buf * 65536 + (s * 8 + mw * 2 + mt) * 512 + lane * 16;
                    ah[st][mt] = *reinterpret_cast<const uint4*>(smem + moff);
                    al[st][mt] = *reinterpret_cast<const uint4*>(smem + moff + 16384);
                }
            }
#pragma unroll
            for (int nt = 0; nt < 8; nt++) {
                int boff = buf * 65536 + 32768 + (sp * 16 + nw * 8 + nt) * 512 + lane * 16;
                uint4 bh = *reinterpret_cast<const uint4*>(smem + boff);
                uint4 bl = *reinterpret_cast<const uint4*>(smem + boff + 16384);
#pragma unroll
                for (int st = 0; st < 2; st++) {
                    uint32_t bh0 = st ? bh.z : bh.x, bh1 = st ? bh.w : bh.y;
                    uint32_t bl0 = st ? bl.z : bl.x, bl1 = st ? bl.w : bl.y;
#pragma unroll
                    for (int mt = 0; mt < 2; mt++) {
                        MMA(acc[mt][nt], ah[st][mt], bh0, bh1);
                        MMA(acc[mt][nt], ah[st][mt], bl0, bl1);
                        MMA(acc[mt][nt], al[st][mt], bh0, bh1);
                        MMA(acc[mt][nt], al[st][mt], bl0, bl1);
                    }
                }
            }
        }
        __syncthreads();
    }

    // ---------------- epilogue ----------------
    if (MODE == 0 || (MODE == 2 && bn >= Gn)) {
#pragma unroll
        for (int mt = 0; mt < 2; mt++)
#pragma unroll
            for (int nt = 0; nt < 8; nt++) {
                int row = bm + mw * 32 + mt * 16 + (lane >> 2);
                int col = bn + nw * 64 + nt * 8 + (lane & 3) * 2;
                if (MODE == 2) col -= Gn;
                float* dst = Cout + (size_t)row * Wn + col;
                *reinterpret_cast<float2*>(dst) =
                    make_float2(acc[mt][nt][0], acc[mt][nt][1]);
                *reinterpret_cast<float2*>(dst + 8 * Wn) =
                    make_float2(acc[mt][nt][2], acc[mt][nt][3]);
            }
    } else {
        float* gsm = reinterpret_cast<float*>(smem);
#pragma unroll
        for (int mt = 0; mt < 2; mt++)
#pragma unroll
            for (int nt = 0; nt < 8; nt++) {
                int rl = mw * 32 + mt * 16 + (lane >> 2);
                int cl = nw * 64 + nt * 8 + (lane & 3) * 2;
                *reinterpret_cast<float2*>(&gsm[rl * 132 + cl]) =
                    make_float2(acc[mt][nt][0], acc[mt][nt][1]);
                *reinterpret_cast<float2*>(&gsm[(rl + 8) * 132 + cl]) =
                    make_float2(acc[mt][nt][2], acc[mt][nt][3]);
            }
        __syncthreads();
#pragma unroll 1
        for (int q = 0; q < 16; q++) {
            int idx = q * 256 + tid;
            int ml = idx >> 5, j4 = idx & 31;
            float4 gv = *reinterpret_cast<const float4*>(&gsm[ml * 132 + j4 * 4]);
            int mrow = bm + ml;
            int n = bn + j4 * 4;
            int j = n >> 2;
            float g0 = gv.x, g1 = gv.y, g2 = gv.z, g3 = gv.w;
            if (MODE == 1) {
                int tokv = tok[mrow * Sn + t];
                float4 pv = *reinterpret_cast<const float4*>(P + (size_t)tokv * Gn + n);
                g0 += pv.x; g1 += pv.y; g2 += pv.z; g3 += pv.w;
            } else {
                float4 bv = *reinterpret_cast<const float4*>(bias2 + n);
                g0 += bv.x; g1 += bv.y; g2 += bv.z; g3 += bv.w;
            }
            float co = cst[mrow * Hn + j];
            float cn = sigf(g1) * co + sigf(g0) * tanhf(g2);
            float hn = sigf(g3) * tanhf(cn);
            cst[mrow * Hn + j] = cn;
            float hi, lo;
            tfsplit(hn, hi, lo);
            size_t ao = afrag((size_t)mrow, j, Bn / 16);
            hhi[ao] = hi; hlo[ao] = lo;
            if (MODE == 1) {
                size_t er = (size_t)t * Bn + mrow;
                size_t eo = afrag(er, j, BSn / 16);
                enchi[eo] = hi; enclo[eo] = lo;
                if (t == Sn - 1) cD[mrow * Hn + j] = hn;
            }
        }
    }
}

// ---------------- threefry2x32 (JAX-compatible) ----------------
__device__ __forceinline__ uint32_t rotl32(uint32_t v, int d) { return (v << d) | (v >> (32 - d)); }

__device__ uint32_t threefry_xor(uint32_t k0, uint32_t k1, uint32_t x0, uint32_t x1) {
    uint32_t ks2 = k0 ^ k1 ^ 0x1BD11BDAu;
    x0 += k0; x1 += k1;
    const int ra[4] = {13, 15, 26, 6}, rb[4] = {17, 29, 16, 24};
#pragma unroll
    for (int i = 0; i < 4; i++) { x0 += x1; x1 = rotl32(x1, ra[i]); x1 ^= x0; }
    x0 += k1; x1 += ks2 + 1u;
#pragma unroll
    for (int i = 0; i < 4; i++) { x0 += x1; x1 = rotl32(x1, rb[i]); x1 ^= x0; }
    x0 += ks2; x1 += k0 + 2u;
#pragma unroll
    for (int i = 0; i < 4; i++) { x0 += x1; x1 = rotl32(x1, ra[i]); x1 ^= x0; }
    x0 += k0; x1 += k1 + 3u;
#pragma unroll
    for (int i = 0; i < 4; i++) { x0 += x1; x1 = rotl32(x1, rb[i]); x1 ^= x0; }
    x0 += k1; x1 += ks2 + 4u;
#pragma unroll
    for (int i = 0; i < 4; i++) { x0 += x1; x1 = rotl32(x1, ra[i]); x1 ^= x0; }
    x0 += ks2; x1 += k0 + 5u;
    return x0 ^ x1;  // partitionable 32-bit random_bits = out0 ^ out1
}

__device__ __forceinline__ float gumbel_from_bits(uint32_t bits) {
    const float TINY = 1.17549435e-38f;
    float f = __uint_as_float((bits >> 9) | 0x3f800000u) - 1.0f;
    float u = f * (1.0f - TINY) + TINY;
    u = fmaxf(TINY, u);
    return -logf(-logf(u));
}

// ---------------- fused scores + masked log-softmax + sample ----------------
__global__ void k_attn(const float* __restrict__ vt, int l,
                       uint32_t key0, uint32_t key1,
                       float* __restrict__ probs, float* __restrict__ tour) {
    int b = blockIdx.x, tid = threadIdx.x;  // 256 threads
    __shared__ float sb[Wn], sv[Wn], ssc[64];
    sb[tid] = g_blend2[b * Wn + tid];
    sv[tid] = vt[tid];
    __syncthreads();
    int warp = tid >> 5, lane = tid & 31;
    for (int s = warp; s < Sn; s += 8) {
        const float* row = g_blend1 + ((size_t)s * Bn + b) * Wn;
        float acc = 0.0f;
#pragma unroll
        for (int q = 0; q < 8; q++) {
            int w = lane + q * 32;
            acc += tanhf(row[w] + sb[w]) * sv[w];
        }
        for (int off = 16; off; off >>= 1) acc += __shfl_xor_sync(0xffffffffu, acc, off);
        if (lane == 0) ssc[s] = acc;
    }
    __syncthreads();
    if (warp != 0) return;
    int s0 = lane, s1 = lane + 32;
    const float NEG = -3.4e38f;
    float x0 = g_mask[b * Sn + s0] ? -100000.0f : ssc[s0];
    float x1 = NEG;
    if (s1 < Sn) x1 = g_mask[b * Sn + s1] ? -100000.0f : ssc[s1];
    float m = fmaxf(x0, x1);
    for (int off = 16; off; off >>= 1) m = fmaxf(m, __shfl_xor_sync(0xffffffffu, m, off));
    float sum = expf(x0 - m) + ((s1 < Sn) ? expf(x1 - m) : 0.0f);
    for (int off = 16; off; off >>= 1) sum += __shfl_xor_sync(0xffffffffu, sum, off);
    float lse = logf(sum);
    float lp0 = x0 - m - lse;
    float lp1 = x1 - m - lse;
    float* prow = probs + ((size_t)b * Ln + l) * Sn;
    prow[s0] = lp0;
    if (s1 < Sn) prow[s1] = lp1;
    float v0 = lp0 + gumbel_from_bits(threefry_xor(key0, key1, 0u, (uint32_t)(b * Sn + s0)));
    float v1 = NEG;
    if (s1 < Sn) v1 = lp1 + gumbel_from_bits(threefry_xor(key0, key1, 0u, (uint32_t)(b * Sn + s1)));
    float bv; int bi;
    if (v1 > v0) { bv = v1; bi = s1; } else { bv = v0; bi = s0; }
    for (int off = 16; off; off >>= 1) {
        float ov = __shfl_xor_sync(0xffffffffu, bv, off);
        int   oi = __shfl_xor_sync(0xffffffffu, bi, off);
        if (ov > bv || (ov == bv && oi < bi)) { bv = ov; bi = oi; }
    }
    if (lane == 0) {
        tour[(size_t)b * Ln + l] = (float)bi;
        g_mask[b * Sn + bi] = 1;
    }
}

// ---------------- host threefry ----------------
static void tf_host(uint32_t k0, uint32_t k1, uint32_t x0, uint32_t x1,
                    uint32_t& o0, uint32_t& o1) {
    uint32_t ks2 = k0 ^ k1 ^ 0x1BD11BDAu;
    x0 += k0; x1 += k1;
    const int ra[4] = {13, 15, 26, 6}, rb[4] = {17, 29, 16, 24};
    auto rl = [](uint32_t v, int d) { return (v << d) | (v >> (32 - d)); };
    for (int i = 0; i < 4; i++) { x0 += x1; x1 = rl(x1, ra[i]); x1 ^= x0; }
    x0 += k1; x1 += ks2 + 1u;
    for (int i = 0; i < 4; i++) { x0 += x1; x1 = rl(x1, rb[i]); x1 ^= x0; }
    x0 += ks2; x1 += k0 + 2u;
    for (int i = 0; i < 4; i++) { x0 += x1; x1 = rl(x1, ra[i]); x1 ^= x0; }
    x0 += k0; x1 += k1 + 3u;
    for (int i = 0; i < 4; i++) { x0 += x1; x1 = rl(x1, rb[i]); x1 ^= x0; }
    x0 += k1; x1 += ks2 + 4u;
    for (int i = 0; i < 4; i++) { x0 += x1; x1 = rl(x1, ra[i]); x1 ^= x0; }
    x0 += ks2; x1 += k0 + 5u;
    o0 = x0; o1 = x1;
}

#define SM_TOTAL 131072

extern "C" void kernel_launch(void* const* d_in, const int* in_sizes, int n_in,
                              void* d_out, int out_size) {
    const int*   input = (const int*)d_in[0];
    const float* emb   = (const float*)d_in[1];
    const float* eWih  = (const float*)d_in[2];
    const float* eWhh  = (const float*)d_in[3];
    const float* ebih  = (const float*)d_in[4];
    const float* ebhh  = (const float*)d_in[5];
    // d_in[6] = dec_Wih (unused: decoder input is always zero)
    const float* dWhh  = (const float*)d_in[7];
    const float* dbih  = (const float*)d_in[8];
    const float* dbhh  = (const float*)d_in[9];
    const float* W1    = (const float*)d_in[10];
    const float* W2    = (const float*)d_in[11];
    const float* vt    = (const float*)d_in[12];

    float* out   = (float*)d_out;
    float* probs = out;                               // [B, L, S]
    float* tour  = out + (size_t)Bn * Ln * Sn;        // [B, L] as float

    cudaFuncSetAttribute(gemm_mma<0>, cudaFuncAttributeMaxDynamicSharedMemorySize, SM_TOTAL);
    cudaFuncSetAttribute(gemm_mma<1>, cudaFuncAttributeMaxDynamicSharedMemorySize, SM_TOTAL);
    cudaFuncSetAttribute(gemm_mma<2>, cudaFuncAttributeMaxDynamicSharedMemorySize, SM_TOTAL);

    float *p_hhi0, *p_hlo0, *p_hhi1, *p_hlo1, *p_cE, *p_cD;
    float *p_enchi, *p_enclo, *p_b1, *p_b2;
    float *p_eWhi, *p_eWlo, *p_dWhi, *p_dWlo, *p_W1hi, *p_W1lo, *p_bd2, *p_P;
    cudaGetSymbolAddress((void**)&p_hhi0, g_hhi0);
    cudaGetSymbolAddress((void**)&p_hlo0, g_hlo0);
    cudaGetSymbolAddress((void**)&p_hhi1, g_hhi1);
    cudaGetSymbolAddress((void**)&p_hlo1, g_hlo1);
    cudaGetSymbolAddress((void**)&p_cE, g_cE);
    cudaGetSymbolAddress((void**)&p_cD, g_cD);
    cudaGetSymbolAddress((void**)&p_enchi, g_enchi);
    cudaGetSymbolAddress((void**)&p_enclo, g_enclo);
    cudaGetSymbolAddress((void**)&p_b1, g_blend1);
    cudaGetSymbolAddress((void**)&p_b2, g_blend2);
    cudaGetSymbolAddress((void**)&p_eWhi, g_eWhi);
    cudaGetSymbolAddress((void**)&p_eWlo, g_eWlo);
    cudaGetSymbolAddress((void**)&p_dWhi, g_dWhi);
    cudaGetSymbolAddress((void**)&p_dWlo, g_dWlo);
    cudaGetSymbolAddress((void**)&p_W1hi, g_W1hi);
    cudaGetSymbolAddress((void**)&p_W1lo, g_W1lo);
    cudaGetSymbolAddress((void**)&p_bd2, g_bias_dec2);
    cudaGetSymbolAddress((void**)&p_P, g_P);

    const int BHB = (Bn * Hn + 255) / 256;

    k_prep<<<(ND * Hn + 255) / 256, 256>>>(eWhh, dWhh, dbih, dbhh, W2, W1);
    k_prep_P<<<(Vn * Gn + 255) / 256, 256>>>(emb, eWih, ebih, ebhh);
    k_init<<<BHB, 256>>>();

    // -------- encoder: 50 fused mma GEMM+cell steps --------
    for (int t = 0; t < Sn; t++) {
        float* ihi = (t & 1) ? p_hhi1 : p_hhi0;
        float* ilo = (t & 1) ? p_hlo1 : p_hlo0;
        float* ohi = (t & 1) ? p_hhi0 : p_hhi1;
        float* olo = (t & 1) ? p_hlo0 : p_hlo1;
        gemm_mma<1><<<dim3(Gn / 128, Bn / 128), 256, SM_TOTAL>>>(
            ihi, ilo, Bn / 16, p_eWhi, p_eWlo, Gn / 8,
            nullptr, p_P, input, nullptr,
            ohi, olo, p_cE, p_enchi, p_enclo, p_cD, t);
    }

    // -------- blend1 = enc_states @ W1^T : [(t*Bn+b)][W] --------
    gemm_mma<0><<<dim3(Wn / 128, BSn / 128), 256, SM_TOTAL>>>(
        p_enchi, p_enclo, BSn / 16, p_W1hi, p_W1lo, Wn / 8,
        nullptr, nullptr, nullptr, p_b1,
        nullptr, nullptr, nullptr, nullptr, nullptr, nullptr, 0);

    // -------- decoder first cell (h_prev = 0), c0 = enc h49 --------
    k_dec0<<<BHB, 256>>>();

    uint32_t K0[Ln], K1[Ln];
    for (int l = 0; l < Ln; l++) tf_host(0u, 42u, 0u, (uint32_t)l, K0[l], K1[l]);

    for (int l = 0; l < Ln; l++) {
        float* ihi = (l & 1) ? p_hhi1 : p_hhi0;
        float* ilo = (l & 1) ? p_hlo1 : p_hlo0;
        float* ohi = (l & 1) ? p_hhi0 : p_hhi1;
        float* olo = (l & 1) ? p_hlo0 : p_hlo1;
        gemm_mma<2><<<dim3(ND / 128, Bn / 128), 256, SM_TOTAL>>>(
            ihi, ilo, Bn / 16, p_dWhi, p_dWlo, ND / 8,
            p_bd2, nullptr, nullptr, p_b2,
            ohi, olo, p_cD, nullptr, nullptr, nullptr, 0);
        k_attn<<<Bn, 256>>>(vt, l, K0[l], K1[l], probs, tour);
    }
    (void)in_sizes; (void)n_in; (void)out_size;
}

// round 8
// speedup vs baseline: 1.0207x; 1.0207x over previous
#include <cuda_runtime.h>
#include <cstdint>
#include <math.h>

// Problem constants
#define Bn 2048
#define Sn 50
#define En 256
#define Hn 512
#define Gn 2048        // 4*H
#define Wn 256
#define Ln 50
#define ND (Gn + Wn)   // 2304 : [interleaved dec gates | W2 rows]
#define Vn 51
#define BSn (Bn * Sn)

// ---------------- device scratch (fragment-order layouts) ----------------
__device__ float g_hhi0[Bn * Hn];
__device__ float g_hlo0[Bn * Hn];
__device__ float g_hhi1[Bn * Hn];
__device__ float g_hlo1[Bn * Hn];
__device__ float g_cE[Bn * Hn];                    // encoder cell state [m][j]
__device__ float g_cD[Bn * Hn];                    // decoder cell state
__device__ float g_enchi[(size_t)BSn * Hn];        // enc states, A-frag layout
__device__ float g_enclo[(size_t)BSn * Hn];
__device__ float g_blend1[(size_t)BSn * Wn];       // [(t*Bn+b)][w] row-major
__device__ float g_blend2[Bn * Wn];
__device__ unsigned char g_mask[Bn * Sn];
__device__ float g_eWhi[Gn * Hn];                  // enc Whh, B-frag layout
__device__ float g_eWlo[Gn * Hn];
__device__ float g_dWhi[ND * Hn];                  // dec Whh | W2, B-frag layout
__device__ float g_dWlo[ND * Hn];
__device__ float g_W1hi[Wn * Hn];
__device__ float g_W1lo[Wn * Hn];
__device__ float g_bias_dec2[Gn];
__device__ float g_P[Vn * Gn];                     // emb@Wih^T + enc bias (fp32 exact)

// ---------------- helpers ----------------
__device__ __forceinline__ float sigf(float x) { return 1.0f / (1.0f + expf(-x)); }

__device__ __forceinline__ void tfsplit(float x, float& hi, float& lo) {
    uint32_t u;
    asm("cvt.rna.tf32.f32 %0, %1;" : "=r"(u) : "f"(x));
    hi = __uint_as_float(u);
    float d = x - hi;
    asm("cvt.rna.tf32.f32 %0, %1;" : "=r"(u) : "f"(d));
    lo = __uint_as_float(u);
}

__device__ __forceinline__ void cp16(uint32_t dst, const float* src) {
    asm volatile("cp.async.cg.shared.global [%0], [%1], 16;\n" :: "r"(dst), "l"(src));
}

// mma.sync m16n8k8 tf32: D += A*B  (row.col)
#define MMA(accp, av, b0, b1)                                              \
    asm volatile(                                                          \
        "mma.sync.aligned.m16n8k8.row.col.f32.tf32.tf32.f32 "              \
        "{%0,%1,%2,%3}, {%4,%5,%6,%7}, {%8,%9}, {%0,%1,%2,%3};"            \
        : "+f"((accp)[0]), "+f"((accp)[1]), "+f"((accp)[2]), "+f"((accp)[3]) \
        : "r"((av).x), "r"((av).y), "r"((av).z), "r"((av).w),              \
          "r"(b0), "r"(b1))

// A-fragment global layout: off(m,k) for m16n8k8 A regs
__device__ __forceinline__ size_t afrag(size_t m, int k, int mtiles) {
    int kc = k >> 5, s = (k >> 3) & 3;
    size_t mt = m >> 4;
    int tt = ((int)(m & 7)) * 4 + (k & 3);
    int r = (int)((m >> 3) & 1) + 2 * ((k >> 2) & 1);
    return (((size_t)(kc * 4 + s) * mtiles + mt) * 32 + tt) * 4 + r;
}
// B-fragment global layout (two k8 steps packed per 16B)
__device__ __forceinline__ size_t bfrag(int n, int k, int ntiles) {
    int kc = k >> 5, sp = (k >> 4) & 1, nt = n >> 3;
    int tt = (n & 7) * 4 + (k & 3);
    int r = ((k >> 3) & 1) * 2 + ((k >> 2) & 1);
    return (((size_t)(kc * 2 + sp) * ntiles + nt) * 32 + tt) * 4 + r;
}

// ---------------- prep kernels ----------------
__global__ void k_prep(const float* __restrict__ eWhh,
                       const float* __restrict__ dWhh, const float* __restrict__ dbih,
                       const float* __restrict__ dbhh, const float* __restrict__ W2,
                       const float* __restrict__ W1) {
    int idx = blockIdx.x * blockDim.x + threadIdx.x;
    if (idx < Gn * Hn) {
        int n2 = idx / Hn, k = idx % Hn;
        int g = n2 & 3, j = n2 >> 2;
        float hi, lo;
        tfsplit(eWhh[(g * Hn + j) * Hn + k], hi, lo);
        size_t o = bfrag(n2, k, Gn / 8);
        g_eWhi[o] = hi; g_eWlo[o] = lo;
    }
    if (idx < ND * Hn) {
        int n2 = idx / Hn, k = idx % Hn;
        float v;
        if (n2 < Gn) {
            int g = n2 & 3, j = n2 >> 2;
            v = dWhh[(g * Hn + j) * Hn + k];
        } else {
            v = W2[(size_t)(n2 - Gn) * Hn + k];
        }
        float hi, lo;
        tfsplit(v, hi, lo);
        size_t o = bfrag(n2, k, ND / 8);
        g_dWhi[o] = hi; g_dWlo[o] = lo;
    }
    if (idx < Wn * Hn) {
        int w = idx / Hn, k = idx % Hn;
        float hi, lo;
        tfsplit(W1[idx], hi, lo);
        size_t o = bfrag(w, k, Wn / 8);
        g_W1hi[o] = hi; g_W1lo[o] = lo;
    }
    if (idx < Gn) {
        int g = idx & 3, j = idx >> 2;
        int r = g * Hn + j;
        g_bias_dec2[idx] = dbih[r] + dbhh[r];
    }
}

__global__ void k_prep_P(const float* __restrict__ emb, const float* __restrict__ eWih,
                         const float* __restrict__ ebih, const float* __restrict__ ebhh) {
    int idx = blockIdx.x * blockDim.x + threadIdx.x;
    if (idx >= Vn * Gn) return;
    int v = idx / Gn, n2 = idx % Gn;
    int g = n2 & 3, j = n2 >> 2;
    int r = g * Hn + j;
    const float4* e = reinterpret_cast<const float4*>(emb + (size_t)v * En);
    const float4* w = reinterpret_cast<const float4*>(eWih + (size_t)r * En);
    float s = 0.0f;
    #pragma unroll 8
    for (int k = 0; k < En / 4; k++) {
        float4 a = __ldg(e + k), b = __ldg(w + k);
        s += a.x * b.x + a.y * b.y + a.z * b.z + a.w * b.w;
    }
    g_P[idx] = s + ebih[r] + ebhh[r];
}

__global__ void k_init() {
    int idx = blockIdx.x * blockDim.x + threadIdx.x;
    if (idx < Bn * Hn) { g_hhi0[idx] = 0.0f; g_hlo0[idx] = 0.0f; g_cE[idx] = 0.0f; }
    if (idx < Bn * Sn) g_mask[idx] = 0;
}

// decoder first cell: gates = bias only; c0 already in g_cD (enc h49)
__global__ void k_dec0() {
    int idx = blockIdx.x * blockDim.x + threadIdx.x;
    if (idx >= Bn * Hn) return;
    int b = idx / Hn, j = idx % Hn;
    float gi = g_bias_dec2[4 * j + 0], gf = g_bias_dec2[4 * j + 1];
    float gg = g_bias_dec2[4 * j + 2], go = g_bias_dec2[4 * j + 3];
    float c0 = g_cD[idx];
    float cn = sigf(gf) * c0 + sigf(gi) * tanhf(gg);
    float hn = sigf(go) * tanhf(cn);
    g_cD[idx] = cn;
    float hi, lo;
    tfsplit(hn, hi, lo);
    size_t ao = afrag((size_t)b, j, Bn / 16);
    g_hhi0[ao] = hi; g_hlo0[ao] = lo;
}

// ---------------- tf32 mma.sync GEMM, 4-product split, fused epilogue -------
// 512 threads, 16 warps in 4x4 grid, each warp 32x32 of the 128x128 CTA tile.
// MODE 0: plain store (blend1)  MODE 1: encoder LSTM  MODE 2: dec LSTM | blend2
template <int MODE>
__global__ __launch_bounds__(512, 1) void gemm_mma(
    const float* __restrict__ Ahi, const float* __restrict__ Alo, int Mtiles,
    const float* __restrict__ Bhi, const float* __restrict__ Blo, int Ntiles,
    const float* __restrict__ bias2, const float* __restrict__ P,
    const int* __restrict__ tok,
    float* __restrict__ Cout,
    float* __restrict__ hhi, float* __restrict__ hlo,
    float* __restrict__ cst,
    float* __restrict__ enchi, float* __restrict__ enclo,
    float* __restrict__ cD, int t) {
    extern __shared__ char smem[];
    const int tid = threadIdx.x;
    const int lane = tid & 31, wid = tid >> 5;
    const int bm = blockIdx.y * 128, bn = blockIdx.x * 128;
    const int bm16 = bm >> 4, bn8 = bn >> 3;
    const int mw = wid & 3, nw = wid >> 2;        // mw 0..3, nw 0..3

    float acc[2][4][4];
#pragma unroll
    for (int i = 0; i < 2; i++)
#pragma unroll
        for (int jn = 0; jn < 4; jn++)
#pragma unroll
            for (int p = 0; p < 4; p++) acc[i][jn][p] = 0.0f;

    auto issue = [&](int c, int buf) {
#pragma unroll
        for (int q = 0; q < 8; q++) {
            int cid = tid + q * 512;
            int arr = cid >> 10;
            int within = cid & 1023;
            const float* src;
            uint32_t dof;
            if (arr < 2) {
                int s = within >> 8, rest = within & 255;
                const float* base = arr ? Alo : Ahi;
                src = base + ((size_t)(c * 4 + s) * Mtiles + bm16) * 128 + rest * 4;
                dof = (uint32_t)(buf * 65536 + arr * 16384 + within * 16);
            } else {
                int sp = within >> 9, rest = within & 511;
                const float* base = (arr == 2) ? Bhi : Blo;
                src = base + ((size_t)(c * 2 + sp) * Ntiles + bn8) * 128 + rest * 4;
                dof = (uint32_t)(buf * 65536 + 32768 + (arr - 2) * 16384 + within * 16);
            }
            cp16((uint32_t)__cvta_generic_to_shared(smem + dof), src);
        }
        asm volatile("cp.async.commit_group;\n");
    };

    issue(0, 0);
#pragma unroll 1
    for (int c = 0; c < 16; c++) {
        const int buf = c & 1;
        if (c + 1 < 16) {
            issue(c + 1, buf ^ 1);
            asm volatile("cp.async.wait_group 1;\n");
        } else {
            asm volatile("cp.async.wait_group 0;\n");
        }
        __syncthreads();
#pragma unroll
        for (int sp = 0; sp < 2; sp++) {
            uint4 ah[2][2], al[2][2];
#pragma unroll
            for (int st = 0; st < 2; st++) {
                int s = sp * 2 + st;
#pragma unroll
                for (int mt = 0; mt < 2; mt++) {
                    int moff = buf * 65536 + (s * 8 + mw * 2 + mt) * 512 + lane * 16;
                    ah[st][mt] = *reinterpret_cast<const uint4*>(smem + moff);
                    al[st][mt] = *reinterpret_cast<const uint4*>(smem + moff + 16384);
                }
            }
#pragma unroll
            for (int nt = 0; nt < 4; nt++) {
                int boff = buf * 65536 + 32768 + (sp * 16 + nw * 4 + nt) * 512 + lane * 16;
                uint4 bh = *reinterpret_cast<const uint4*>(smem + boff);
                uint4 bl = *reinterpret_cast<const uint4*>(smem + boff + 16384);
#pragma unroll
                for (int st = 0; st < 2; st++) {
                    uint32_t bh0 = st ? bh.z : bh.x, bh1 = st ? bh.w : bh.y;
                    uint32_t bl0 = st ? bl.z : bl.x, bl1 = st ? bl.w : bl.y;
                    // product-major, mt innermost: same-acc reuse distance = 2
                    MMA(acc[0][nt], ah[st][0], bh0, bh1);
                    MMA(acc[1][nt], ah[st][1], bh0, bh1);
                    MMA(acc[0][nt], ah[st][0], bl0, bl1);
                    MMA(acc[1][nt], ah[st][1], bl0, bl1);
                    MMA(acc[0][nt], al[st][0], bh0, bh1);
                    MMA(acc[1][nt], al[st][1], bh0, bh1);
                    MMA(acc[0][nt], al[st][0], bl0, bl1);
                    MMA(acc[1][nt], al[st][1], bl0, bl1);
                }
            }
        }
        __syncthreads();
    }

    // ---------------- epilogue ----------------
    if (MODE == 0 || (MODE == 2 && bn >= Gn)) {
#pragma unroll
        for (int mt = 0; mt < 2; mt++)
#pragma unroll
            for (int nt = 0; nt < 4; nt++) {
                int row = bm + mw * 32 + mt * 16 + (lane >> 2);
                int col = bn + nw * 32 + nt * 8 + (lane & 3) * 2;
                if (MODE == 2) col -= Gn;
                float* dst = Cout + (size_t)row * Wn + col;
                *reinterpret_cast<float2*>(dst) =
                    make_float2(acc[mt][nt][0], acc[mt][nt][1]);
                *reinterpret_cast<float2*>(dst + 8 * Wn) =
                    make_float2(acc[mt][nt][2], acc[mt][nt][3]);
            }
    } else {
        float* gsm = reinterpret_cast<float*>(smem);
#pragma unroll
        for (int mt = 0; mt < 2; mt++)
#pragma unroll
            for (int nt = 0; nt < 4; nt++) {
                int rl = mw * 32 + mt * 16 + (lane >> 2);
                int cl = nw * 32 + nt * 8 + (lane & 3) * 2;
                *reinterpret_cast<float2*>(&gsm[rl * 132 + cl]) =
                    make_float2(acc[mt][nt][0], acc[mt][nt][1]);
                *reinterpret_cast<float2*>(&gsm[(rl + 8) * 132 + cl]) =
                    make_float2(acc[mt][nt][2], acc[mt][nt][3]);
            }
        __syncthreads();
#pragma unroll 1
        for (int q = 0; q < 8; q++) {
            int idx = q * 512 + tid;
            int ml = idx >> 5, j4 = idx & 31;
            float4 gv = *reinterpret_cast<const float4*>(&gsm[ml * 132 + j4 * 4]);
            int mrow = bm + ml;
            int n = bn + j4 * 4;
            int j = n >> 2;
            float g0 = gv.x, g1 = gv.y, g2 = gv.z, g3 = gv.w;
            if (MODE == 1) {
                int tokv = tok[mrow * Sn + t];
                float4 pv = *reinterpret_cast<const float4*>(P + (size_t)tokv * Gn + n);
                g0 += pv.x; g1 += pv.y; g2 += pv.z; g3 += pv.w;
            } else {
                float4 bv = *reinterpret_cast<const float4*>(bias2 + n);
                g0 += bv.x; g1 += bv.y; g2 += bv.z; g3 += bv.w;
            }
            float co = cst[mrow * Hn + j];
            float cn = sigf(g1) * co + sigf(g0) * tanhf(g2);
            float hn = sigf(g3) * tanhf(cn);
            cst[mrow * Hn + j] = cn;
            float hi, lo;
            tfsplit(hn, hi, lo);
            size_t ao = afrag((size_t)mrow, j, Bn / 16);
            hhi[ao] = hi; hlo[ao] = lo;
            if (MODE == 1) {
                size_t er = (size_t)t * Bn + mrow;
                size_t eo = afrag(er, j, BSn / 16);
                enchi[eo] = hi; enclo[eo] = lo;
                if (t == Sn - 1) cD[mrow * Hn + j] = hn;
            }
        }
    }
}

// ---------------- threefry2x32 (JAX-compatible) ----------------
__device__ __forceinline__ uint32_t rotl32(uint32_t v, int d) { return (v << d) | (v >> (32 - d)); }

__device__ uint32_t threefry_xor(uint32_t k0, uint32_t k1, uint32_t x0, uint32_t x1) {
    uint32_t ks2 = k0 ^ k1 ^ 0x1BD11BDAu;
    x0 += k0; x1 += k1;
    const int ra[4] = {13, 15, 26, 6}, rb[4] = {17, 29, 16, 24};
#pragma unroll
    for (int i = 0; i < 4; i++) { x0 += x1; x1 = rotl32(x1, ra[i]); x1 ^= x0; }
    x0 += k1; x1 += ks2 + 1u;
#pragma unroll
    for (int i = 0; i < 4; i++) { x0 += x1; x1 = rotl32(x1, rb[i]); x1 ^= x0; }
    x0 += ks2; x1 += k0 + 2u;
#pragma unroll
    for (int i = 0; i < 4; i++) { x0 += x1; x1 = rotl32(x1, ra[i]); x1 ^= x0; }
    x0 += k0; x1 += k1 + 3u;
#pragma unroll
    for (int i = 0; i < 4; i++) { x0 += x1; x1 = rotl32(x1, rb[i]); x1 ^= x0; }
    x0 += k1; x1 += ks2 + 4u;
#pragma unroll
    for (int i = 0; i < 4; i++) { x0 += x1; x1 = rotl32(x1, ra[i]); x1 ^= x0; }
    x0 += ks2; x1 += k0 + 5u;
    return x0 ^ x1;  // partitionable 32-bit random_bits = out0 ^ out1
}

__device__ __forceinline__ float gumbel_from_bits(uint32_t bits) {
    const float TINY = 1.17549435e-38f;
    float f = __uint_as_float((bits >> 9) | 0x3f800000u) - 1.0f;
    float u = f * (1.0f - TINY) + TINY;
    u = fmaxf(TINY, u);
    return -logf(-logf(u));
}

// ---------------- fused scores + masked log-softmax + sample ----------------
__global__ void k_attn(const float* __restrict__ vt, int l,
                       uint32_t key0, uint32_t key1,
                       float* __restrict__ probs, float* __restrict__ tour) {
    int b = blockIdx.x, tid = threadIdx.x;  // 256 threads
    __shared__ float sb[Wn], sv[Wn], ssc[64];
    sb[tid] = g_blend2[b * Wn + tid];
    sv[tid] = vt[tid];
    __syncthreads();
    int warp = tid >> 5, lane = tid & 31;
    for (int s = warp; s < Sn; s += 8) {
        const float* row = g_blend1 + ((size_t)s * Bn + b) * Wn;
        float acc = 0.0f;
#pragma unroll
        for (int q = 0; q < 8; q++) {
            int w = lane + q * 32;
            acc += tanhf(row[w] + sb[w]) * sv[w];
        }
        for (int off = 16; off; off >>= 1) acc += __shfl_xor_sync(0xffffffffu, acc, off);
        if (lane == 0) ssc[s] = acc;
    }
    __syncthreads();
    if (warp != 0) return;
    int s0 = lane, s1 = lane + 32;
    const float NEG = -3.4e38f;
    float x0 = g_mask[b * Sn + s0] ? -100000.0f : ssc[s0];
    float x1 = NEG;
    if (s1 < Sn) x1 = g_mask[b * Sn + s1] ? -100000.0f : ssc[s1];
    float m = fmaxf(x0, x1);
    for (int off = 16; off; off >>= 1) m = fmaxf(m, __shfl_xor_sync(0xffffffffu, m, off));
    float sum = expf(x0 - m) + ((s1 < Sn) ? expf(x1 - m) : 0.0f);
    for (int off = 16; off; off >>= 1) sum += __shfl_xor_sync(0xffffffffu, sum, off);
    float lse = logf(sum);
    float lp0 = x0 - m - lse;
    float lp1 = x1 - m - lse;
    float* prow = probs + ((size_t)b * Ln + l) * Sn;
    prow[s0] = lp0;
    if (s1 < Sn) prow[s1] = lp1;
    float v0 = lp0 + gumbel_from_bits(threefry_xor(key0, key1, 0u, (uint32_t)(b * Sn + s0)));
    float v1 = NEG;
    if (s1 < Sn) v1 = lp1 + gumbel_from_bits(threefry_xor(key0, key1, 0u, (uint32_t)(b * Sn + s1)));
    float bv; int bi;
    if (v1 > v0) { bv = v1; bi = s1; } else { bv = v0; bi = s0; }
    for (int off = 16; off; off >>= 1) {
        float ov = __shfl_xor_sync(0xffffffffu, bv, off);
        int   oi = __shfl_xor_sync(0xffffffffu, bi, off);
        if (ov > bv || (ov == bv && oi < bi)) { bv = ov; bi = oi; }
    }
    if (lane == 0) {
        tour[(size_t)b * Ln + l] = (float)bi;
        g_mask[b * Sn + bi] = 1;
    }
}

// ---------------- host threefry ----------------
static void tf_host(uint32_t k0, uint32_t k1, uint32_t x0, uint32_t x1,
                    uint32_t& o0, uint32_t& o1) {
    uint32_t ks2 = k0 ^ k1 ^ 0x1BD11BDAu;
    x0 += k0; x1 += k1;
    const int ra[4] = {13, 15, 26, 6}, rb[4] = {17, 29, 16, 24};
    auto rl = [](uint32_t v, int d) { return (v << d) | (v >> (32 - d)); };
    for (int i = 0; i < 4; i++) { x0 += x1; x1 = rl(x1, ra[i]); x1 ^= x0; }
    x0 += k1; x1 += ks2 + 1u;
    for (int i = 0; i < 4; i++) { x0 += x1; x1 = rl(x1, rb[i]); x1 ^= x0; }
    x0 += ks2; x1 += k0 + 2u;
    for (int i = 0; i < 4; i++) { x0 += x1; x1 = rl(x1, ra[i]); x1 ^= x0; }
    x0 += k0; x1 += k1 + 3u;
    for (int i = 0; i < 4; i++) { x0 += x1; x1 = rl(x1, rb[i]); x1 ^= x0; }
    x0 += k1; x1 += ks2 + 4u;
    for (int i = 0; i < 4; i++) { x0 += x1; x1 = rl(x1, ra[i]); x1 ^= x0; }
    x0 += ks2; x1 += k0 + 5u;
    o0 = x0; o1 = x1;
}

#define SM_TOTAL 131072

extern "C" void kernel_launch(void* const* d_in, const int* in_sizes, int n_in,
                              void* d_out, int out_size) {
    const int*   input = (const int*)d_in[0];
    const float* emb   = (const float*)d_in[1];
    const float* eWih  = (const float*)d_in[2];
    const float* eWhh  = (const float*)d_in[3];
    const float* ebih  = (const float*)d_in[4];
    const float* ebhh  = (const float*)d_in[5];
    // d_in[6] = dec_Wih (unused: decoder input is always zero)
    const float* dWhh  = (const float*)d_in[7];
    const float* dbih  = (const float*)d_in[8];
    const float* dbhh  = (const float*)d_in[9];
    const float* W1    = (const float*)d_in[10];
    const float* W2    = (const float*)d_in[11];
    const float* vt    = (const float*)d_in[12];

    float* out   = (float*)d_out;
    float* probs = out;                               // [B, L, S]
    float* tour  = out + (size_t)Bn * Ln * Sn;        // [B, L] as float

    cudaFuncSetAttribute(gemm_mma<0>, cudaFuncAttributeMaxDynamicSharedMemorySize, SM_TOTAL);
    cudaFuncSetAttribute(gemm_mma<1>, cudaFuncAttributeMaxDynamicSharedMemorySize, SM_TOTAL);
    cudaFuncSetAttribute(gemm_mma<2>, cudaFuncAttributeMaxDynamicSharedMemorySize, SM_TOTAL);

    float *p_hhi0, *p_hlo0, *p_hhi1, *p_hlo1, *p_cE, *p_cD;
    float *p_enchi, *p_enclo, *p_b1, *p_b2;
    float *p_eWhi, *p_eWlo, *p_dWhi, *p_dWlo, *p_W1hi, *p_W1lo, *p_bd2, *p_P;
    cudaGetSymbolAddress((void**)&p_hhi0, g_hhi0);
    cudaGetSymbolAddress((void**)&p_hlo0, g_hlo0);
    cudaGetSymbolAddress((void**)&p_hhi1, g_hhi1);
    cudaGetSymbolAddress((void**)&p_hlo1, g_hlo1);
    cudaGetSymbolAddress((void**)&p_cE, g_cE);
    cudaGetSymbolAddress((void**)&p_cD, g_cD);
    cudaGetSymbolAddress((void**)&p_enchi, g_enchi);
    cudaGetSymbolAddress((void**)&p_enclo, g_enclo);
    cudaGetSymbolAddress((void**)&p_b1, g_blend1);
    cudaGetSymbolAddress((void**)&p_b2, g_blend2);
    cudaGetSymbolAddress((void**)&p_eWhi, g_eWhi);
    cudaGetSymbolAddress((void**)&p_eWlo, g_eWlo);
    cudaGetSymbolAddress((void**)&p_dWhi, g_dWhi);
    cudaGetSymbolAddress((void**)&p_dWlo, g_dWlo);
    cudaGetSymbolAddress((void**)&p_W1hi, g_W1hi);
    cudaGetSymbolAddress((void**)&p_W1lo, g_W1lo);
    cudaGetSymbolAddress((void**)&p_bd2, g_bias_dec2);
    cudaGetSymbolAddress((void**)&p_P, g_P);

    const int BHB = (Bn * Hn + 255) / 256;

    k_prep<<<(ND * Hn + 255) / 256, 256>>>(eWhh, dWhh, dbih, dbhh, W2, W1);
    k_prep_P<<<(Vn * Gn + 255) / 256, 256>>>(emb, eWih, ebih, ebhh);
    k_init<<<BHB, 256>>>();

    // -------- encoder: 50 fused mma GEMM+cell steps --------
    for (int t = 0; t < Sn; t++) {
        float* ihi = (t & 1) ? p_hhi1 : p_hhi0;
        float* ilo = (t & 1) ? p_hlo1 : p_hlo0;
        float* ohi = (t & 1) ? p_hhi0 : p_hhi1;
        float* olo = (t & 1) ? p_hlo0 : p_hlo1;
        gemm_mma<1><<<dim3(Gn / 128, Bn / 128), 512, SM_TOTAL>>>(
            ihi, ilo, Bn / 16, p_eWhi, p_eWlo, Gn / 8,
            nullptr, p_P, input, nullptr,
            ohi, olo, p_cE, p_enchi, p_enclo, p_cD, t);
    }

    // -------- blend1 = enc_states @ W1^T : [(t*Bn+b)][W] --------
    gemm_mma<0><<<dim3(Wn / 128, BSn / 128), 512, SM_TOTAL>>>(
        p_enchi, p_enclo, BSn / 16, p_W1hi, p_W1lo, Wn / 8,
        nullptr, nullptr, nullptr, p_b1,
        nullptr, nullptr, nullptr, nullptr, nullptr, nullptr, 0);

    // -------- decoder first cell (h_prev = 0), c0 = enc h49 --------
    k_dec0<<<BHB, 256>>>();

    uint32_t K0[Ln], K1[Ln];
    for (int l = 0; l < Ln; l++) tf_host(0u, 42u, 0u, (uint32_t)l, K0[l], K1[l]);

    for (int l = 0; l < Ln; l++) {
        float* ihi = (l & 1) ? p_hhi1 : p_hhi0;
        float* ilo = (l & 1) ? p_hlo1 : p_hlo0;
        float* ohi = (l & 1) ? p_hhi0 : p_hhi1;
        float* olo = (l & 1) ? p_hlo0 : p_hlo1;
        gemm_mma<2><<<dim3(ND / 128, Bn / 128), 512, SM_TOTAL>>>(
            ihi, ilo, Bn / 16, p_dWhi, p_dWlo, ND / 8,
            p_bd2, nullptr, nullptr, p_b2,
            ohi, olo, p_cD, nullptr, nullptr, nullptr, 0);
        k_attn<<<Bn, 256>>>(vt, l, K0[l], K1[l], probs, tour);
    }
    (void)in_sizes; (void)n_in; (void)out_size;
}

// round 9
// speedup vs baseline: 1.2001x; 1.1757x over previous
#include <cuda_runtime.h>
#include <cstdint>
#include <math.h>

// Problem constants
#define Bn 2048
#define Sn 50
#define En 256
#define Hn 512
#define Gn 2048        // 4*H
#define Wn 256
#define Ln 50
#define ND (Gn + Wn)   // 2304 : [interleaved dec gates | W2 rows]
#define Vn 51
#define BSn (Bn * Sn)

// ---------------- device scratch (fragment-order layouts) ----------------
__device__ float g_hhi0[Bn * Hn];
__device__ float g_hlo0[Bn * Hn];
__device__ float g_hhi1[Bn * Hn];
__device__ float g_hlo1[Bn * Hn];
__device__ float g_cE[Bn * Hn];                    // encoder cell state [m][j]
__device__ float g_cD[Bn * Hn];                    // decoder cell state
__device__ float g_enchi[(size_t)BSn * Hn];        // enc states, A-frag layout
__device__ float g_enclo[(size_t)BSn * Hn];
__device__ float g_blend1[(size_t)BSn * Wn];       // [(t*Bn+b)][w] row-major
__device__ float g_blend2[Bn * Wn];
__device__ unsigned char g_mask[Bn * Sn];
__device__ float g_eWhi[Gn * Hn];                  // enc Whh, B-frag layout
__device__ float g_eWlo[Gn * Hn];
__device__ float g_dWhi[ND * Hn];                  // dec Whh | W2, B-frag layout
__device__ float g_dWlo[ND * Hn];
__device__ float g_W1hi[Wn * Hn];
__device__ float g_W1lo[Wn * Hn];
__device__ float g_bias_dec2[Gn];
__device__ float g_P[Vn * Gn];                     // emb@Wih^T + enc bias (fp32 exact)

// ---------------- helpers ----------------
__device__ __forceinline__ float sigf(float x) { return 1.0f / (1.0f + expf(-x)); }

__device__ __forceinline__ void tfsplit(float x, float& hi, float& lo) {
    uint32_t u;
    asm("cvt.rna.tf32.f32 %0, %1;" : "=r"(u) : "f"(x));
    hi = __uint_as_float(u);
    float d = x - hi;
    asm("cvt.rna.tf32.f32 %0, %1;" : "=r"(u) : "f"(d));
    lo = __uint_as_float(u);
}

__device__ __forceinline__ void cp16(uint32_t dst, const float* src) {
    asm volatile("cp.async.cg.shared.global [%0], [%1], 16;\n" :: "r"(dst), "l"(src));
}

// mma.sync m16n8k8 tf32: D += A*B  (row.col)
#define MMA(accp, av, b0, b1)                                              \
    asm volatile(                                                          \
        "mma.sync.aligned.m16n8k8.row.col.f32.tf32.tf32.f32 "              \
        "{%0,%1,%2,%3}, {%4,%5,%6,%7}, {%8,%9}, {%0,%1,%2,%3};"            \
        : "+f"((accp)[0]), "+f"((accp)[1]), "+f"((accp)[2]), "+f"((accp)[3]) \
        : "r"((av).x), "r"((av).y), "r"((av).z), "r"((av).w),              \
          "r"(b0), "r"(b1))

// A-fragment global layout: off(m,k) for m16n8k8 A regs
__device__ __forceinline__ size_t afrag(size_t m, int k, int mtiles) {
    int kc = k >> 5, s = (k >> 3) & 3;
    size_t mt = m >> 4;
    int tt = ((int)(m & 7)) * 4 + (k & 3);
    int r = (int)((m >> 3) & 1) + 2 * ((k >> 2) & 1);
    return (((size_t)(kc * 4 + s) * mtiles + mt) * 32 + tt) * 4 + r;
}
// B-fragment global layout (two k8 steps packed per 16B)
__device__ __forceinline__ size_t bfrag(int n, int k, int ntiles) {
    int kc = k >> 5, sp = (k >> 4) & 1, nt = n >> 3;
    int tt = (n & 7) * 4 + (k & 3);
    int r = ((k >> 3) & 1) * 2 + ((k >> 2) & 1);
    return (((size_t)(kc * 2 + sp) * ntiles + nt) * 32 + tt) * 4 + r;
}

// ---------------- prep kernels ----------------
__global__ void k_prep(const float* __restrict__ eWhh,
                       const float* __restrict__ dWhh, const float* __restrict__ dbih,
                       const float* __restrict__ dbhh, const float* __restrict__ W2,
                       const float* __restrict__ W1) {
    int idx = blockIdx.x * blockDim.x + threadIdx.x;
    if (idx < Gn * Hn) {
        int n2 = idx / Hn, k = idx % Hn;
        int g = n2 & 3, j = n2 >> 2;
        float hi, lo;
        tfsplit(eWhh[(g * Hn + j) * Hn + k], hi, lo);
        size_t o = bfrag(n2, k, Gn / 8);
        g_eWhi[o] = hi; g_eWlo[o] = lo;
    }
    if (idx < ND * Hn) {
        int n2 = idx / Hn, k = idx % Hn;
        float v;
        if (n2 < Gn) {
            int g = n2 & 3, j = n2 >> 2;
            v = dWhh[(g * Hn + j) * Hn + k];
        } else {
            v = W2[(size_t)(n2 - Gn) * Hn + k];
        }
        float hi, lo;
        tfsplit(v, hi, lo);
        size_t o = bfrag(n2, k, ND / 8);
        g_dWhi[o] = hi; g_dWlo[o] = lo;
    }
    if (idx < Wn * Hn) {
        int w = idx / Hn, k = idx % Hn;
        float hi, lo;
        tfsplit(W1[idx], hi, lo);
        size_t o = bfrag(w, k, Wn / 8);
        g_W1hi[o] = hi; g_W1lo[o] = lo;
    }
    if (idx < Gn) {
        int g = idx & 3, j = idx >> 2;
        int r = g * Hn + j;
        g_bias_dec2[idx] = dbih[r] + dbhh[r];
    }
}

__global__ void k_prep_P(const float* __restrict__ emb, const float* __restrict__ eWih,
                         const float* __restrict__ ebih, const float* __restrict__ ebhh) {
    int idx = blockIdx.x * blockDim.x + threadIdx.x;
    if (idx >= Vn * Gn) return;
    int v = idx / Gn, n2 = idx % Gn;
    int g = n2 & 3, j = n2 >> 2;
    int r = g * Hn + j;
    const float4* e = reinterpret_cast<const float4*>(emb + (size_t)v * En);
    const float4* w = reinterpret_cast<const float4*>(eWih + (size_t)r * En);
    float s = 0.0f;
    #pragma unroll 8
    for (int k = 0; k < En / 4; k++) {
        float4 a = __ldg(e + k), b = __ldg(w + k);
        s += a.x * b.x + a.y * b.y + a.z * b.z + a.w * b.w;
    }
    g_P[idx] = s + ebih[r] + ebhh[r];
}

__global__ void k_init() {
    int idx = blockIdx.x * blockDim.x + threadIdx.x;
    if (idx < Bn * Hn) { g_hhi0[idx] = 0.0f; g_hlo0[idx] = 0.0f; g_cE[idx] = 0.0f; }
    if (idx < Bn * Sn) g_mask[idx] = 0;
}

// decoder first cell: gates = bias only; c0 already in g_cD (enc h49)
__global__ void k_dec0() {
    int idx = blockIdx.x * blockDim.x + threadIdx.x;
    if (idx >= Bn * Hn) return;
    int b = idx / Hn, j = idx % Hn;
    float gi = g_bias_dec2[4 * j + 0], gf = g_bias_dec2[4 * j + 1];
    float gg = g_bias_dec2[4 * j + 2], go = g_bias_dec2[4 * j + 3];
    float c0 = g_cD[idx];
    float cn = sigf(gf) * c0 + sigf(gi) * tanhf(gg);
    float hn = sigf(go) * tanhf(cn);
    g_cD[idx] = cn;
    float hi, lo;
    tfsplit(hn, hi, lo);
    size_t ao = afrag((size_t)b, j, Bn / 16);
    g_hhi0[ao] = hi; g_hlo0[ao] = lo;
}

// ---------------- tf32 mma.sync GEMM, 3-product split, fused epilogue -------
// 512 threads, 16 warps in 4x4 grid, each warp 32x32 of the 128x128 CTA tile.
// Triple-buffered cp.async, one __syncthreads per chunk, hoisted frag loads.
// MODE 0: plain store (blend1)  MODE 1: encoder LSTM  MODE 2: dec LSTM | blend2
template <int MODE>
__global__ __launch_bounds__(512, 1) void gemm_mma(
    const float* __restrict__ Ahi, const float* __restrict__ Alo, int Mtiles,
    const float* __restrict__ Bhi, const float* __restrict__ Blo, int Ntiles,
    const float* __restrict__ bias2, const float* __restrict__ P,
    const int* __restrict__ tok,
    float* __restrict__ Cout,
    float* __restrict__ hhi, float* __restrict__ hlo,
    float* __restrict__ cst,
    float* __restrict__ enchi, float* __restrict__ enclo,
    float* __restrict__ cD, int t) {
    extern __shared__ char smem[];
    const int tid = threadIdx.x;
    const int lane = tid & 31, wid = tid >> 5;
    const int bm = blockIdx.y * 128, bn = blockIdx.x * 128;
    const int bm16 = bm >> 4, bn8 = bn >> 3;
    const int mw = wid & 3, nw = wid >> 2;        // mw 0..3, nw 0..3

    float acc[2][4][4];
#pragma unroll
    for (int i = 0; i < 2; i++)
#pragma unroll
        for (int jn = 0; jn < 4; jn++)
#pragma unroll
            for (int p = 0; p < 4; p++) acc[i][jn][p] = 0.0f;

    auto issue = [&](int c, int buf) {
#pragma unroll
        for (int q = 0; q < 8; q++) {
            int cid = tid + q * 512;
            int arr = cid >> 10;
            int within = cid & 1023;
            const float* src;
            uint32_t dof;
            if (arr < 2) {
                int s = within >> 8, rest = within & 255;
                const float* base = arr ? Alo : Ahi;
                src = base + ((size_t)(c * 4 + s) * Mtiles + bm16) * 128 + rest * 4;
                dof = (uint32_t)(buf * 65536 + arr * 16384 + within * 16);
            } else {
                int sp = within >> 9, rest = within & 511;
                const float* base = (arr == 2) ? Bhi : Blo;
                src = base + ((size_t)(c * 2 + sp) * Ntiles + bn8) * 128 + rest * 4;
                dof = (uint32_t)(buf * 65536 + 32768 + (arr - 2) * 16384 + within * 16);
            }
            cp16((uint32_t)__cvta_generic_to_shared(smem + dof), src);
        }
        asm volatile("cp.async.commit_group;\n");
    };

    issue(0, 0);
    issue(1, 1);
#pragma unroll 1
    for (int c = 0; c < 16; c++) {
        const int buf = c % 3;
        if (c < 15) { asm volatile("cp.async.wait_group 1;\n"); }
        else        { asm volatile("cp.async.wait_group 0;\n"); }
        __syncthreads();
        if (c + 2 < 16) issue(c + 2, (c + 2) % 3);
#pragma unroll
        for (int sp = 0; sp < 2; sp++) {
            uint4 ah[2][2], al[2][2];
#pragma unroll
            for (int st = 0; st < 2; st++) {
                int s = sp * 2 + st;
#pragma unroll
                for (int mt = 0; mt < 2; mt++) {
                    int moff = buf * 65536 + (s * 8 + mw * 2 + mt) * 512 + lane * 16;
                    ah[st][mt] = *reinterpret_cast<const uint4*>(smem + moff);
                    al[st][mt] = *reinterpret_cast<const uint4*>(smem + moff + 16384);
                }
            }
            uint4 bh[4], bl[4];
#pragma unroll
            for (int nt = 0; nt < 4; nt++) {
                int boff = buf * 65536 + 32768 + (sp * 16 + nw * 4 + nt) * 512 + lane * 16;
                bh[nt] = *reinterpret_cast<const uint4*>(smem + boff);
                bl[nt] = *reinterpret_cast<const uint4*>(smem + boff + 16384);
            }
#pragma unroll
            for (int st = 0; st < 2; st++) {
                // product hh : acc reuse distance 8
#pragma unroll
                for (int nt = 0; nt < 4; nt++) {
                    uint32_t b0 = st ? bh[nt].z : bh[nt].x;
                    uint32_t b1 = st ? bh[nt].w : bh[nt].y;
                    MMA(acc[0][nt], ah[st][0], b0, b1);
                    MMA(acc[1][nt], ah[st][1], b0, b1);
                }
                // product hi*lo
#pragma unroll
                for (int nt = 0; nt < 4; nt++) {
                    uint32_t b0 = st ? bl[nt].z : bl[nt].x;
                    uint32_t b1 = st ? bl[nt].w : bl[nt].y;
                    MMA(acc[0][nt], ah[st][0], b0, b1);
                    MMA(acc[1][nt], ah[st][1], b0, b1);
                }
                // product lo*hi   (lo*lo dropped: same 2^-22 error class as
                //                  the two-term split residual already present)
#pragma unroll
                for (int nt = 0; nt < 4; nt++) {
                    uint32_t b0 = st ? bh[nt].z : bh[nt].x;
                    uint32_t b1 = st ? bh[nt].w : bh[nt].y;
                    MMA(acc[0][nt], al[st][0], b0, b1);
                    MMA(acc[1][nt], al[st][1], b0, b1);
                }
            }
        }
    }

    // ---------------- epilogue ----------------
    if (MODE == 0 || (MODE == 2 && bn >= Gn)) {
#pragma unroll
        for (int mt = 0; mt < 2; mt++)
#pragma unroll
            for (int nt = 0; nt < 4; nt++) {
                int row = bm + mw * 32 + mt * 16 + (lane >> 2);
                int col = bn + nw * 32 + nt * 8 + (lane & 3) * 2;
                if (MODE == 2) col -= Gn;
                float* dst = Cout + (size_t)row * Wn + col;
                *reinterpret_cast<float2*>(dst) =
                    make_float2(acc[mt][nt][0], acc[mt][nt][1]);
                *reinterpret_cast<float2*>(dst + 8 * Wn) =
                    make_float2(acc[mt][nt][2], acc[mt][nt][3]);
            }
    } else {
        float* gsm = reinterpret_cast<float*>(smem);
        __syncthreads();   // all warps done reading smem buffers before reuse
#pragma unroll
        for (int mt = 0; mt < 2; mt++)
#pragma unroll
            for (int nt = 0; nt < 4; nt++) {
                int rl = mw * 32 + mt * 16 + (lane >> 2);
                int cl = nw * 32 + nt * 8 + (lane & 3) * 2;
                *reinterpret_cast<float2*>(&gsm[rl * 132 + cl]) =
                    make_float2(acc[mt][nt][0], acc[mt][nt][1]);
                *reinterpret_cast<float2*>(&gsm[(rl + 8) * 132 + cl]) =
                    make_float2(acc[mt][nt][2], acc[mt][nt][3]);
            }
        __syncthreads();
#pragma unroll 1
        for (int q = 0; q < 8; q++) {
            int idx = q * 512 + tid;
            int ml = idx >> 5, j4 = idx & 31;
            float4 gv = *reinterpret_cast<const float4*>(&gsm[ml * 132 + j4 * 4]);
            int mrow = bm + ml;
            int n = bn + j4 * 4;
            int j = n >> 2;
            float g0 = gv.x, g1 = gv.y, g2 = gv.z, g3 = gv.w;
            if (MODE == 1) {
                int tokv = tok[mrow * Sn + t];
                float4 pv = *reinterpret_cast<const float4*>(P + (size_t)tokv * Gn + n);
                g0 += pv.x; g1 += pv.y; g2 += pv.z; g3 += pv.w;
            } else {
                float4 bv = *reinterpret_cast<const float4*>(bias2 + n);
                g0 += bv.x; g1 += bv.y; g2 += bv.z; g3 += bv.w;
            }
            float co = cst[mrow * Hn + j];
            float cn = sigf(g1) * co + sigf(g0) * tanhf(g2);
            float hn = sigf(g3) * tanhf(cn);
            cst[mrow * Hn + j] = cn;
            float hi, lo;
            tfsplit(hn, hi, lo);
            size_t ao = afrag((size_t)mrow, j, Bn / 16);
            hhi[ao] = hi; hlo[ao] = lo;
            if (MODE == 1) {
                size_t er = (size_t)t * Bn + mrow;
                size_t eo = afrag(er, j, BSn / 16);
                enchi[eo] = hi; enclo[eo] = lo;
                if (t == Sn - 1) cD[mrow * Hn + j] = hn;
            }
        }
    }
}

// ---------------- threefry2x32 (JAX-compatible) ----------------
__device__ __forceinline__ uint32_t rotl32(uint32_t v, int d) { return (v << d) | (v >> (32 - d)); }

__device__ uint32_t threefry_xor(uint32_t k0, uint32_t k1, uint32_t x0, uint32_t x1) {
    uint32_t ks2 = k0 ^ k1 ^ 0x1BD11BDAu;
    x0 += k0; x1 += k1;
    const int ra[4] = {13, 15, 26, 6}, rb[4] = {17, 29, 16, 24};
#pragma unroll
    for (int i = 0; i < 4; i++) { x0 += x1; x1 = rotl32(x1, ra[i]); x1 ^= x0; }
    x0 += k1; x1 += ks2 + 1u;
#pragma unroll
    for (int i = 0; i < 4; i++) { x0 += x1; x1 = rotl32(x1, rb[i]); x1 ^= x0; }
    x0 += ks2; x1 += k0 + 2u;
#pragma unroll
    for (int i = 0; i < 4; i++) { x0 += x1; x1 = rotl32(x1, ra[i]); x1 ^= x0; }
    x0 += k0; x1 += k1 + 3u;
#pragma unroll
    for (int i = 0; i < 4; i++) { x0 += x1; x1 = rotl32(x1, rb[i]); x1 ^= x0; }
    x0 += k1; x1 += ks2 + 4u;
#pragma unroll
    for (int i = 0; i < 4; i++) { x0 += x1; x1 = rotl32(x1, ra[i]); x1 ^= x0; }
    x0 += ks2; x1 += k0 + 5u;
    return x0 ^ x1;  // partitionable 32-bit random_bits = out0 ^ out1
}

__device__ __forceinline__ float gumbel_from_bits(uint32_t bits) {
    const float TINY = 1.17549435e-38f;
    float f = __uint_as_float((bits >> 9) | 0x3f800000u) - 1.0f;
    float u = f * (1.0f - TINY) + TINY;
    u = fmaxf(TINY, u);
    return -logf(-logf(u));
}

// ---------------- fused scores + masked log-softmax + sample ----------------
__global__ void k_attn(const float* __restrict__ vt, int l,
                       uint32_t key0, uint32_t key1,
                       float* __restrict__ probs, float* __restrict__ tour) {
    int b = blockIdx.x, tid = threadIdx.x;  // 256 threads
    __shared__ float sb[Wn], sv[Wn], ssc[64];
    sb[tid] = g_blend2[b * Wn + tid];
    sv[tid] = vt[tid];
    __syncthreads();
    int warp = tid >> 5, lane = tid & 31;
    for (int s = warp; s < Sn; s += 8) {
        const float* row = g_blend1 + ((size_t)s * Bn + b) * Wn;
        float acc = 0.0f;
#pragma unroll
        for (int q = 0; q < 8; q++) {
            int w = lane + q * 32;
            acc += tanhf(row[w] + sb[w]) * sv[w];
        }
        for (int off = 16; off; off >>= 1) acc += __shfl_xor_sync(0xffffffffu, acc, off);
        if (lane == 0) ssc[s] = acc;
    }
    __syncthreads();
    if (warp != 0) return;
    int s0 = lane, s1 = lane + 32;
    const float NEG = -3.4e38f;
    float x0 = g_mask[b * Sn + s0] ? -100000.0f : ssc[s0];
    float x1 = NEG;
    if (s1 < Sn) x1 = g_mask[b * Sn + s1] ? -100000.0f : ssc[s1];
    float m = fmaxf(x0, x1);
    for (int off = 16; off; off >>= 1) m = fmaxf(m, __shfl_xor_sync(0xffffffffu, m, off));
    float sum = expf(x0 - m) + ((s1 < Sn) ? expf(x1 - m) : 0.0f);
    for (int off = 16; off; off >>= 1) sum += __shfl_xor_sync(0xffffffffu, sum, off);
    float lse = logf(sum);
    float lp0 = x0 - m - lse;
    float lp1 = x1 - m - lse;
    float* prow = probs + ((size_t)b * Ln + l) * Sn;
    prow[s0] = lp0;
    if (s1 < Sn) prow[s1] = lp1;
    float v0 = lp0 + gumbel_from_bits(threefry_xor(key0, key1, 0u, (uint32_t)(b * Sn + s0)));
    float v1 = NEG;
    if (s1 < Sn) v1 = lp1 + gumbel_from_bits(threefry_xor(key0, key1, 0u, (uint32_t)(b * Sn + s1)));
    float bv; int bi;
    if (v1 > v0) { bv = v1; bi = s1; } else { bv = v0; bi = s0; }
    for (int off = 16; off; off >>= 1) {
        float ov = __shfl_xor_sync(0xffffffffu, bv, off);
        int   oi = __shfl_xor_sync(0xffffffffu, bi, off);
        if (ov > bv || (ov == bv && oi < bi)) { bv = ov; bi = oi; }
    }
    if (lane == 0) {
        tour[(size_t)b * Ln + l] = (float)bi;
        g_mask[b * Sn + bi] = 1;
    }
}

// ---------------- host threefry ----------------
static void tf_host(uint32_t k0, uint32_t k1, uint32_t x0, uint32_t x1,
                    uint32_t& o0, uint32_t& o1) {
    uint32_t ks2 = k0 ^ k1 ^ 0x1BD11BDAu;
    x0 += k0; x1 += k1;
    const int ra[4] = {13, 15, 26, 6}, rb[4] = {17, 29, 16, 24};
    auto rl = [](uint32_t v, int d) { return (v << d) | (v >> (32 - d)); };
    for (int i = 0; i < 4; i++) { x0 += x1; x1 = rl(x1, ra[i]); x1 ^= x0; }
    x0 += k1; x1 += ks2 + 1u;
    for (int i = 0; i < 4; i++) { x0 += x1; x1 = rl(x1, rb[i]); x1 ^= x0; }
    x0 += ks2; x1 += k0 + 2u;
    for (int i = 0; i < 4; i++) { x0 += x1; x1 = rl(x1, ra[i]); x1 ^= x0; }
    x0 += k0; x1 += k1 + 3u;
    for (int i = 0; i < 4; i++) { x0 += x1; x1 = rl(x1, rb[i]); x1 ^= x0; }
    x0 += k1; x1 += ks2 + 4u;
    for (int i = 0; i < 4; i++) { x0 += x1; x1 = rl(x1, ra[i]); x1 ^= x0; }
    x0 += ks2; x1 += k0 + 5u;
    o0 = x0; o1 = x1;
}

#define SM_TOTAL 196608

extern "C" void kernel_launch(void* const* d_in, const int* in_sizes, int n_in,
                              void* d_out, int out_size) {
    const int*   input = (const int*)d_in[0];
    const float* emb   = (const float*)d_in[1];
    const float* eWih  = (const float*)d_in[2];
    const float* eWhh  = (const float*)d_in[3];
    const float* ebih  = (const float*)d_in[4];
    const float* ebhh  = (const float*)d_in[5];
    // d_in[6] = dec_Wih (unused: decoder input is always zero)
    const float* dWhh  = (const float*)d_in[7];
    const float* dbih  = (const float*)d_in[8];
    const float* dbhh  = (const float*)d_in[9];
    const float* W1    = (const float*)d_in[10];
    const float* W2    = (const float*)d_in[11];
    const float* vt    = (const float*)d_in[12];

    float* out   = (float*)d_out;
    float* probs = out;                               // [B, L, S]
    float* tour  = out + (size_t)Bn * Ln * Sn;        // [B, L] as float

    cudaFuncSetAttribute(gemm_mma<0>, cudaFuncAttributeMaxDynamicSharedMemorySize, SM_TOTAL);
    cudaFuncSetAttribute(gemm_mma<1>, cudaFuncAttributeMaxDynamicSharedMemorySize, SM_TOTAL);
    cudaFuncSetAttribute(gemm_mma<2>, cudaFuncAttributeMaxDynamicSharedMemorySize, SM_TOTAL);

    float *p_hhi0, *p_hlo0, *p_hhi1, *p_hlo1, *p_cE, *p_cD;
    float *p_enchi, *p_enclo, *p_b1, *p_b2;
    float *p_eWhi, *p_eWlo, *p_dWhi, *p_dWlo, *p_W1hi, *p_W1lo, *p_bd2, *p_P;
    cudaGetSymbolAddress((void**)&p_hhi0, g_hhi0);
    cudaGetSymbolAddress((void**)&p_hlo0, g_hlo0);
    cudaGetSymbolAddress((void**)&p_hhi1, g_hhi1);
    cudaGetSymbolAddress((void**)&p_hlo1, g_hlo1);
    cudaGetSymbolAddress((void**)&p_cE, g_cE);
    cudaGetSymbolAddress((void**)&p_cD, g_cD);
    cudaGetSymbolAddress((void**)&p_enchi, g_enchi);
    cudaGetSymbolAddress((void**)&p_enclo, g_enclo);
    cudaGetSymbolAddress((void**)&p_b1, g_blend1);
    cudaGetSymbolAddress((void**)&p_b2, g_blend2);
    cudaGetSymbolAddress((void**)&p_eWhi, g_eWhi);
    cudaGetSymbolAddress((void**)&p_eWlo, g_eWlo);
    cudaGetSymbolAddress((void**)&p_dWhi, g_dWhi);
    cudaGetSymbolAddress((void**)&p_dWlo, g_dWlo);
    cudaGetSymbolAddress((void**)&p_W1hi, g_W1hi);
    cudaGetSymbolAddress((void**)&p_W1lo, g_W1lo);
    cudaGetSymbolAddress((void**)&p_bd2, g_bias_dec2);
    cudaGetSymbolAddress((void**)&p_P, g_P);

    const int BHB = (Bn * Hn + 255) / 256;

    k_prep<<<(ND * Hn + 255) / 256, 256>>>(eWhh, dWhh, dbih, dbhh, W2, W1);
    k_prep_P<<<(Vn * Gn + 255) / 256, 256>>>(emb, eWih, ebih, ebhh);
    k_init<<<BHB, 256>>>();

    // -------- encoder: 50 fused mma GEMM+cell steps --------
    for (int t = 0; t < Sn; t++) {
        float* ihi = (t & 1) ? p_hhi1 : p_hhi0;
        float* ilo = (t & 1) ? p_hlo1 : p_hlo0;
        float* ohi = (t & 1) ? p_hhi0 : p_hhi1;
        float* olo = (t & 1) ? p_hlo0 : p_hlo1;
        gemm_mma<1><<<dim3(Gn / 128, Bn / 128), 512, SM_TOTAL>>>(
            ihi, ilo, Bn / 16, p_eWhi, p_eWlo, Gn / 8,
            nullptr, p_P, input, nullptr,
            ohi, olo, p_cE, p_enchi, p_enclo, p_cD, t);
    }

    // -------- blend1 = enc_states @ W1^T : [(t*Bn+b)][W] --------
    gemm_mma<0><<<dim3(Wn / 128, BSn / 128), 512, SM_TOTAL>>>(
        p_enchi, p_enclo, BSn / 16, p_W1hi, p_W1lo, Wn / 8,
        nullptr, nullptr, nullptr, p_b1,
        nullptr, nullptr, nullptr, nullptr, nullptr, nullptr, 0);

    // -------- decoder first cell (h_prev = 0), c0 = enc h49 --------
    k_dec0<<<BHB, 256>>>();

    uint32_t K0[Ln], K1[Ln];
    for (int l = 0; l < Ln; l++) tf_host(0u, 42u, 0u, (uint32_t)l, K0[l], K1[l]);

    for (int l = 0; l < Ln; l++) {
        float* ihi = (l & 1) ? p_hhi1 : p_hhi0;
        float* ilo = (l & 1) ? p_hlo1 : p_hlo0;
        float* ohi = (l & 1) ? p_hhi0 : p_hhi1;
        float* olo = (l & 1) ? p_hlo0 : p_hlo1;
        gemm_mma<2><<<dim3(ND / 128, Bn / 128), 512, SM_TOTAL>>>(
            ihi, ilo, Bn / 16, p_dWhi, p_dWlo, ND / 8,
            p_bd2, nullptr, nullptr, p_b2,
            ohi, olo, p_cD, nullptr, nullptr, nullptr, 0);
        k_attn<<<Bn, 256>>>(vt, l, K0[l], K1[l], probs, tour);
    }
    (void)in_sizes; (void)n_in; (void)out_size;
}

// round 10
// speedup vs baseline: 1.8130x; 1.5108x over previous
#include <cuda_runtime.h>
#include <cuda_fp16.h>
#include <cstdint>
#include <math.h>

// Problem constants
#define Bn 2048
#define Sn 50
#define En 256
#define Hn 512
#define Gn 2048        // 4*H
#define Wn 256
#define Ln 50
#define ND (Gn + Wn)   // 2304 : [interleaved dec gates | W2 rows]
#define Vn 51
#define BSn (Bn * Sn)

// ---------------- device scratch (fp16 fragment-order layouts) ----------------
__device__ __half g_hhi0[Bn * Hn];
__device__ __half g_hlo0[Bn * Hn];
__device__ __half g_hhi1[Bn * Hn];
__device__ __half g_hlo1[Bn * Hn];
__device__ float  g_cE[Bn * Hn];                    // encoder cell state [m][j]
__device__ float  g_cD[Bn * Hn];                    // decoder cell state
__device__ __half g_enchi[(size_t)BSn * Hn];        // enc states, A-frag layout
__device__ __half g_enclo[(size_t)BSn * Hn];
__device__ float  g_blend1[(size_t)BSn * Wn];       // [(t*Bn+b)][w] row-major
__device__ float  g_blend2[Bn * Wn];
__device__ unsigned char g_mask[Bn * Sn];
__device__ __half g_eWhi[Gn * Hn];                  // enc Whh, B-frag layout
__device__ __half g_eWlo[Gn * Hn];
__device__ __half g_dWhi[ND * Hn];                  // dec Whh | W2, B-frag layout
__device__ __half g_dWlo[ND * Hn];
__device__ __half g_W1hi[Wn * Hn];
__device__ __half g_W1lo[Wn * Hn];
__device__ float  g_bias_dec2[Gn];
__device__ float  g_P[Vn * Gn];                     // emb@Wih^T + enc bias (fp32 exact)

// ---------------- helpers ----------------
__device__ __forceinline__ float sigf(float x) { return 1.0f / (1.0f + expf(-x)); }

__device__ __forceinline__ void hsplit(float x, __half& hi, __half& lo) {
    hi = __float2half_rn(x);
    lo = __float2half_rn(x - __half2float(hi));
}

__device__ __forceinline__ void cp16(uint32_t dst, const void* src) {
    asm volatile("cp.async.cg.shared.global [%0], [%1], 16;\n" :: "r"(dst), "l"(src));
}

// mma.sync m16n8k16 fp16: D(f32) += A(f16)*B(f16)   (row.col)
#define MMA16(accp, av, bv)                                                \
    asm volatile(                                                          \
        "mma.sync.aligned.m16n8k16.row.col.f32.f16.f16.f32 "               \
        "{%0,%1,%2,%3}, {%4,%5,%6,%7}, {%8,%9}, {%0,%1,%2,%3};"            \
        : "+f"((accp)[0]), "+f"((accp)[1]), "+f"((accp)[2]), "+f"((accp)[3]) \
        : "r"((av).x), "r"((av).y), "r"((av).z), "r"((av).w),              \
          "r"((bv).x), "r"((bv).y))

// A-fragment (m16n8k16 f16) half-element index for A[m][k]
__device__ __forceinline__ size_t afrag(size_t m, int k, int mtiles) {
    int kc = k >> 5, s = (k >> 4) & 1, k16 = k & 15;
    int tt = ((int)(m & 7)) * 4 + ((k16 >> 1) & 3);
    int r = (int)((m >> 3) & 1) + (((k16 >> 3) & 1) << 1);
    return ((((size_t)(kc * 2 + s) * mtiles + (m >> 4)) * 32 + tt) * 4 + r) * 2 + (k16 & 1);
}
// B-fragment (m16n8k16 f16) half-element index for B[n][k]
__device__ __forceinline__ size_t bfrag(int n, int k, int ntiles) {
    int kc = k >> 5, s = (k >> 4) & 1, k16 = k & 15;
    int tt = (n & 7) * 4 + ((k16 >> 1) & 3);
    int r = (k16 >> 3) & 1;
    return ((((size_t)(kc * 2 + s) * ntiles + (n >> 3)) * 32 + tt) * 2 + r) * 2 + (k16 & 1);
}

// ---------------- prep kernels ----------------
__global__ void k_prep(const float* __restrict__ eWhh,
                       const float* __restrict__ dWhh, const float* __restrict__ dbih,
                       const float* __restrict__ dbhh, const float* __restrict__ W2,
                       const float* __restrict__ W1) {
    int idx = blockIdx.x * blockDim.x + threadIdx.x;
    if (idx < Gn * Hn) {
        int n2 = idx / Hn, k = idx % Hn;
        int g = n2 & 3, j = n2 >> 2;
        __half hi, lo;
        hsplit(eWhh[(g * Hn + j) * Hn + k], hi, lo);
        size_t o = bfrag(n2, k, Gn / 8);
        g_eWhi[o] = hi; g_eWlo[o] = lo;
    }
    if (idx < ND * Hn) {
        int n2 = idx / Hn, k = idx % Hn;
        float v;
        if (n2 < Gn) {
            int g = n2 & 3, j = n2 >> 2;
            v = dWhh[(g * Hn + j) * Hn + k];
        } else {
            v = W2[(size_t)(n2 - Gn) * Hn + k];
        }
        __half hi, lo;
        hsplit(v, hi, lo);
        size_t o = bfrag(n2, k, ND / 8);
        g_dWhi[o] = hi; g_dWlo[o] = lo;
    }
    if (idx < Wn * Hn) {
        int w = idx / Hn, k = idx % Hn;
        __half hi, lo;
        hsplit(W1[idx], hi, lo);
        size_t o = bfrag(w, k, Wn / 8);
        g_W1hi[o] = hi; g_W1lo[o] = lo;
    }
    if (idx < Gn) {
        int g = idx & 3, j = idx >> 2;
        int r = g * Hn + j;
        g_bias_dec2[idx] = dbih[r] + dbhh[r];
    }
}

__global__ void k_prep_P(const float* __restrict__ emb, const float* __restrict__ eWih,
                         const float* __restrict__ ebih, const float* __restrict__ ebhh) {
    int idx = blockIdx.x * blockDim.x + threadIdx.x;
    if (idx >= Vn * Gn) return;
    int v = idx / Gn, n2 = idx % Gn;
    int g = n2 & 3, j = n2 >> 2;
    int r = g * Hn + j;
    const float4* e = reinterpret_cast<const float4*>(emb + (size_t)v * En);
    const float4* w = reinterpret_cast<const float4*>(eWih + (size_t)r * En);
    float s = 0.0f;
    #pragma unroll 8
    for (int k = 0; k < En / 4; k++) {
        float4 a = __ldg(e + k), b = __ldg(w + k);
        s += a.x * b.x + a.y * b.y + a.z * b.z + a.w * b.w;
    }
    g_P[idx] = s + ebih[r] + ebhh[r];
}

__global__ void k_init() {
    int idx = blockIdx.x * blockDim.x + threadIdx.x;
    if (idx < Bn * Hn) {
        g_hhi0[idx] = __float2half(0.0f);
        g_hlo0[idx] = __float2half(0.0f);
        g_cE[idx] = 0.0f;
    }
    if (idx < Bn * Sn) g_mask[idx] = 0;
}

// decoder first cell: gates = bias only; c0 already in g_cD (enc h49)
__global__ void k_dec0() {
    int idx = blockIdx.x * blockDim.x + threadIdx.x;
    if (idx >= Bn * Hn) return;
    int b = idx / Hn, j = idx % Hn;
    float gi = g_bias_dec2[4 * j + 0], gf = g_bias_dec2[4 * j + 1];
    float gg = g_bias_dec2[4 * j + 2], go = g_bias_dec2[4 * j + 3];
    float c0 = g_cD[idx];
    float cn = sigf(gf) * c0 + sigf(gi) * tanhf(gg);
    float hn = sigf(go) * tanhf(cn);
    g_cD[idx] = cn;
    __half hi, lo;
    hsplit(hn, hi, lo);
    size_t ao = afrag((size_t)b, j, Bn / 16);
    g_hhi0[ao] = hi; g_hlo0[ao] = lo;
}

// ---------------- fp16 mma.sync GEMM, 3-product split, fused epilogue -------
// 512 threads, 16 warps in 4x4 grid, each warp 32x32 of the 128x128 CTA tile.
// Triple-buffered cp.async (32KB/chunk), one __syncthreads per chunk.
// MODE 0: plain store (blend1)  MODE 1: encoder LSTM  MODE 2: dec LSTM | blend2
template <int MODE>
__global__ __launch_bounds__(512, 1) void gemm_mma(
    const __half* __restrict__ Ahi, const __half* __restrict__ Alo, int Mtiles,
    const __half* __restrict__ Bhi, const __half* __restrict__ Blo, int Ntiles,
    const float* __restrict__ bias2, const float* __restrict__ P,
    const int* __restrict__ tok,
    float* __restrict__ Cout,
    __half* __restrict__ hhi, __half* __restrict__ hlo,
    float* __restrict__ cst,
    __half* __restrict__ enchi, __half* __restrict__ enclo,
    float* __restrict__ cD, int t) {
    extern __shared__ char smem[];
    const int tid = threadIdx.x;
    const int lane = tid & 31, wid = tid >> 5;
    const int bm = blockIdx.y * 128, bn = blockIdx.x * 128;
    const int bm16 = bm >> 4, bn8 = bn >> 3;
    const int mw = wid & 3, nw = wid >> 2;        // mw 0..3, nw 0..3

    float acc[2][4][4];
#pragma unroll
    for (int i = 0; i < 2; i++)
#pragma unroll
        for (int jn = 0; jn < 4; jn++)
#pragma unroll
            for (int p = 0; p < 4; p++) acc[i][jn][p] = 0.0f;

    // smem per buffer: Ahi 8KB | Alo 8KB | Bhi 8KB | Blo 8KB = 32KB
    auto issue = [&](int c, int buf) {
#pragma unroll
        for (int q = 0; q < 4; q++) {
            int cid = tid + q * 512;              // 2048 x 16B chunks
            int arr = cid >> 9;                   // 0:Ahi 1:Alo 2:Bhi 3:Blo
            int within = cid & 511;
            int s = within >> 8, rest = within & 255;
            const __half* src;
            if (arr < 2) {
                const __half* base = arr ? Alo : Ahi;
                src = base + ((size_t)(c * 2 + s) * Mtiles + bm16) * 256 + rest * 8;
            } else {
                const __half* base = (arr == 2) ? Bhi : Blo;
                src = base + ((size_t)(c * 2 + s) * Ntiles + bn8) * 128 + rest * 8;
            }
            uint32_t dof = (uint32_t)(buf * 32768 + arr * 8192 + within * 16);
            cp16((uint32_t)__cvta_generic_to_shared(smem + dof), src);
        }
        asm volatile("cp.async.commit_group;\n");
    };

    issue(0, 0);
    issue(1, 1);
#pragma unroll 1
    for (int c = 0; c < 16; c++) {
        const int buf = c % 3;
        if (c < 15) { asm volatile("cp.async.wait_group 1;\n"); }
        else        { asm volatile("cp.async.wait_group 0;\n"); }
        __syncthreads();
        if (c + 2 < 16) issue(c + 2, (c + 2) % 3);
#pragma unroll
        for (int s = 0; s < 2; s++) {
            uint4 ah[2], al[2];
#pragma unroll
            for (int mt = 0; mt < 2; mt++) {
                int moff = buf * 32768 + s * 4096 + (mw * 2 + mt) * 512 + lane * 16;
                ah[mt] = *reinterpret_cast<const uint4*>(smem + moff);
                al[mt] = *reinterpret_cast<const uint4*>(smem + moff + 8192);
            }
            uint2 bh[4], bl[4];
#pragma unroll
            for (int nt = 0; nt < 4; nt++) {
                int boff = buf * 32768 + 16384 + s * 4096 + (nw * 4 + nt) * 256 + lane * 8;
                bh[nt] = *reinterpret_cast<const uint2*>(smem + boff);
                bl[nt] = *reinterpret_cast<const uint2*>(smem + boff + 8192);
            }
            // product hi*hi
#pragma unroll
            for (int nt = 0; nt < 4; nt++) {
                MMA16(acc[0][nt], ah[0], bh[nt]);
                MMA16(acc[1][nt], ah[1], bh[nt]);
            }
            // product hi*lo
#pragma unroll
            for (int nt = 0; nt < 4; nt++) {
                MMA16(acc[0][nt], ah[0], bl[nt]);
                MMA16(acc[1][nt], ah[1], bl[nt]);
            }
            // product lo*hi  (lo*lo dropped: 2^-22 class, validated in R9)
#pragma unroll
            for (int nt = 0; nt < 4; nt++) {
                MMA16(acc[0][nt], al[0], bh[nt]);
                MMA16(acc[1][nt], al[1], bh[nt]);
            }
        }
    }

    // ---------------- epilogue ----------------
    if (MODE == 0 || (MODE == 2 && bn >= Gn)) {
#pragma unroll
        for (int mt = 0; mt < 2; mt++)
#pragma unroll
            for (int nt = 0; nt < 4; nt++) {
                int row = bm + mw * 32 + mt * 16 + (lane >> 2);
                int col = bn + nw * 32 + nt * 8 + (lane & 3) * 2;
                if (MODE == 2) col -= Gn;
                float* dst = Cout + (size_t)row * Wn + col;
                *reinterpret_cast<float2*>(dst) =
                    make_float2(acc[mt][nt][0], acc[mt][nt][1]);
                *reinterpret_cast<float2*>(dst + 8 * Wn) =
                    make_float2(acc[mt][nt][2], acc[mt][nt][3]);
            }
    } else {
        float* gsm = reinterpret_cast<float*>(smem);
        __syncthreads();   // all warps done reading smem buffers before reuse
#pragma unroll
        for (int mt = 0; mt < 2; mt++)
#pragma unroll
            for (int nt = 0; nt < 4; nt++) {
                int rl = mw * 32 + mt * 16 + (lane >> 2);
                int cl = nw * 32 + nt * 8 + (lane & 3) * 2;
                *reinterpret_cast<float2*>(&gsm[rl * 132 + cl]) =
                    make_float2(acc[mt][nt][0], acc[mt][nt][1]);
                *reinterpret_cast<float2*>(&gsm[(rl + 8) * 132 + cl]) =
                    make_float2(acc[mt][nt][2], acc[mt][nt][3]);
            }
        __syncthreads();
#pragma unroll 1
        for (int q = 0; q < 8; q++) {
            int idx = q * 512 + tid;
            int ml = idx >> 5, j4 = idx & 31;
            float4 gv = *reinterpret_cast<const float4*>(&gsm[ml * 132 + j4 * 4]);
            int mrow = bm + ml;
            int n = bn + j4 * 4;
            int j = n >> 2;
            float g0 = gv.x, g1 = gv.y, g2 = gv.z, g3 = gv.w;
            if (MODE == 1) {
                int tokv = tok[mrow * Sn + t];
                float4 pv = *reinterpret_cast<const float4*>(P + (size_t)tokv * Gn + n);
                g0 += pv.x; g1 += pv.y; g2 += pv.z; g3 += pv.w;
            } else {
                float4 bv = *reinterpret_cast<const float4*>(bias2 + n);
                g0 += bv.x; g1 += bv.y; g2 += bv.z; g3 += bv.w;
            }
            float co = cst[mrow * Hn + j];
            float cn = sigf(g1) * co + sigf(g0) * tanhf(g2);
            float hn = sigf(g3) * tanhf(cn);
            cst[mrow * Hn + j] = cn;
            __half hi, lo;
            hsplit(hn, hi, lo);
            size_t ao = afrag((size_t)mrow, j, Bn / 16);
            hhi[ao] = hi; hlo[ao] = lo;
            if (MODE == 1) {
                size_t er = (size_t)t * Bn + mrow;
                size_t eo = afrag(er, j, BSn / 16);
                enchi[eo] = hi; enclo[eo] = lo;
                if (t == Sn - 1) cD[mrow * Hn + j] = hn;
            }
        }
    }
}

// ---------------- threefry2x32 (JAX-compatible) ----------------
__device__ __forceinline__ uint32_t rotl32(uint32_t v, int d) { return (v << d) | (v >> (32 - d)); }

__device__ uint32_t threefry_xor(uint32_t k0, uint32_t k1, uint32_t x0, uint32_t x1) {
    uint32_t ks2 = k0 ^ k1 ^ 0x1BD11BDAu;
    x0 += k0; x1 += k1;
    const int ra[4] = {13, 15, 26, 6}, rb[4] = {17, 29, 16, 24};
#pragma unroll
    for (int i = 0; i < 4; i++) { x0 += x1; x1 = rotl32(x1, ra[i]); x1 ^= x0; }
    x0 += k1; x1 += ks2 + 1u;
#pragma unroll
    for (int i = 0; i < 4; i++) { x0 += x1; x1 = rotl32(x1, rb[i]); x1 ^= x0; }
    x0 += ks2; x1 += k0 + 2u;
#pragma unroll
    for (int i = 0; i < 4; i++) { x0 += x1; x1 = rotl32(x1, ra[i]); x1 ^= x0; }
    x0 += k0; x1 += k1 + 3u;
#pragma unroll
    for (int i = 0; i < 4; i++) { x0 += x1; x1 = rotl32(x1, rb[i]); x1 ^= x0; }
    x0 += k1; x1 += ks2 + 4u;
#pragma unroll
    for (int i = 0; i < 4; i++) { x0 += x1; x1 = rotl32(x1, ra[i]); x1 ^= x0; }
    x0 += ks2; x1 += k0 + 5u;
    return x0 ^ x1;  // partitionable 32-bit random_bits = out0 ^ out1
}

__device__ __forceinline__ float gumbel_from_bits(uint32_t bits) {
    const float TINY = 1.17549435e-38f;
    float f = __uint_as_float((bits >> 9) | 0x3f800000u) - 1.0f;
    float u = f * (1.0f - TINY) + TINY;
    u = fmaxf(TINY, u);
    return -logf(-logf(u));
}

// ---------------- fused scores + masked log-softmax + sample ----------------
__global__ void k_attn(const float* __restrict__ vt, int l,
                       uint32_t key0, uint32_t key1,
                       float* __restrict__ probs, float* __restrict__ tour) {
    int b = blockIdx.x, tid = threadIdx.x;  // 256 threads
    __shared__ float sb[Wn], sv[Wn], ssc[64];
    sb[tid] = g_blend2[b * Wn + tid];
    sv[tid] = vt[tid];
    __syncthreads();
    int warp = tid >> 5, lane = tid & 31;
    for (int s = warp; s < Sn; s += 8) {
        const float* row = g_blend1 + ((size_t)s * Bn + b) * Wn;
        float acc = 0.0f;
#pragma unroll
        for (int q = 0; q < 8; q++) {
            int w = lane + q * 32;
            acc += tanhf(row[w] + sb[w]) * sv[w];
        }
        for (int off = 16; off; off >>= 1) acc += __shfl_xor_sync(0xffffffffu, acc, off);
        if (lane == 0) ssc[s] = acc;
    }
    __syncthreads();
    if (warp != 0) return;
    int s0 = lane, s1 = lane + 32;
    const float NEG = -3.4e38f;
    float x0 = g_mask[b * Sn + s0] ? -100000.0f : ssc[s0];
    float x1 = NEG;
    if (s1 < Sn) x1 = g_mask[b * Sn + s1] ? -100000.0f : ssc[s1];
    float m = fmaxf(x0, x1);
    for (int off = 16; off; off >>= 1) m = fmaxf(m, __shfl_xor_sync(0xffffffffu, m, off));
    float sum = expf(x0 - m) + ((s1 < Sn) ? expf(x1 - m) : 0.0f);
    for (int off = 16; off; off >>= 1) sum += __shfl_xor_sync(0xffffffffu, sum, off);
    float lse = logf(sum);
    float lp0 = x0 - m - lse;
    float lp1 = x1 - m - lse;
    float* prow = probs + ((size_t)b * Ln + l) * Sn;
    prow[s0] = lp0;
    if (s1 < Sn) prow[s1] = lp1;
    float v0 = lp0 + gumbel_from_bits(threefry_xor(key0, key1, 0u, (uint32_t)(b * Sn + s0)));
    float v1 = NEG;
    if (s1 < Sn) v1 = lp1 + gumbel_from_bits(threefry_xor(key0, key1, 0u, (uint32_t)(b * Sn + s1)));
    float bv; int bi;
    if (v1 > v0) { bv = v1; bi = s1; } else { bv = v0; bi = s0; }
    for (int off = 16; off; off >>= 1) {
        float ov = __shfl_xor_sync(0xffffffffu, bv, off);
        int   oi = __shfl_xor_sync(0xffffffffu, bi, off);
        if (ov > bv || (ov == bv && oi < bi)) { bv = ov; bi = oi; }
    }
    if (lane == 0) {
        tour[(size_t)b * Ln + l] = (float)bi;
        g_mask[b * Sn + bi] = 1;
    }
}

// ---------------- host threefry ----------------
static void tf_host(uint32_t k0, uint32_t k1, uint32_t x0, uint32_t x1,
                    uint32_t& o0, uint32_t& o1) {
    uint32_t ks2 = k0 ^ k1 ^ 0x1BD11BDAu;
    x0 += k0; x1 += k1;
    const int ra[4] = {13, 15, 26, 6}, rb[4] = {17, 29, 16, 24};
    auto rl = [](uint32_t v, int d) { return (v << d) | (v >> (32 - d)); };
    for (int i = 0; i < 4; i++) { x0 += x1; x1 = rl(x1, ra[i]); x1 ^= x0; }
    x0 += k1; x1 += ks2 + 1u;
    for (int i = 0; i < 4; i++) { x0 += x1; x1 = rl(x1, rb[i]); x1 ^= x0; }
    x0 += ks2; x1 += k0 + 2u;
    for (int i = 0; i < 4; i++) { x0 += x1; x1 = rl(x1, ra[i]); x1 ^= x0; }
    x0 += k0; x1 += k1 + 3u;
    for (int i = 0; i < 4; i++) { x0 += x1; x1 = rl(x1, rb[i]); x1 ^= x0; }
    x0 += k1; x1 += ks2 + 4u;
    for (int i = 0; i < 4; i++) { x0 += x1; x1 = rl(x1, ra[i]); x1 ^= x0; }
    x0 += ks2; x1 += k0 + 5u;
    o0 = x0; o1 = x1;
}

#define SM_TOTAL 98304

extern "C" void kernel_launch(void* const* d_in, const int* in_sizes, int n_in,
                              void* d_out, int out_size) {
    const int*   input = (const int*)d_in[0];
    const float* emb   = (const float*)d_in[1];
    const float* eWih  = (const float*)d_in[2];
    const float* eWhh  = (const float*)d_in[3];
    const float* ebih  = (const float*)d_in[4];
    const float* ebhh  = (const float*)d_in[5];
    // d_in[6] = dec_Wih (unused: decoder input is always zero)
    const float* dWhh  = (const float*)d_in[7];
    const float* dbih  = (const float*)d_in[8];
    const float* dbhh  = (const float*)d_in[9];
    const float* W1    = (const float*)d_in[10];
    const float* W2    = (const float*)d_in[11];
    const float* vt    = (const float*)d_in[12];

    float* out   = (float*)d_out;
    float* probs = out;                               // [B, L, S]
    float* tour  = out + (size_t)Bn * Ln * Sn;        // [B, L] as float

    cudaFuncSetAttribute(gemm_mma<0>, cudaFuncAttributeMaxDynamicSharedMemorySize, SM_TOTAL);
    cudaFuncSetAttribute(gemm_mma<1>, cudaFuncAttributeMaxDynamicSharedMemorySize, SM_TOTAL);
    cudaFuncSetAttribute(gemm_mma<2>, cudaFuncAttributeMaxDynamicSharedMemorySize, SM_TOTAL);

    __half *p_hhi0, *p_hlo0, *p_hhi1, *p_hlo1, *p_enchi, *p_enclo;
    __half *p_eWhi, *p_eWlo, *p_dWhi, *p_dWlo, *p_W1hi, *p_W1lo;
    float *p_cE, *p_cD, *p_b1, *p_b2, *p_bd2, *p_P;
    cudaGetSymbolAddress((void**)&p_hhi0, g_hhi0);
    cudaGetSymbolAddress((void**)&p_hlo0, g_hlo0);
    cudaGetSymbolAddress((void**)&p_hhi1, g_hhi1);
    cudaGetSymbolAddress((void**)&p_hlo1, g_hlo1);
    cudaGetSymbolAddress((void**)&p_cE, g_cE);
    cudaGetSymbolAddress((void**)&p_cD, g_cD);
    cudaGetSymbolAddress((void**)&p_enchi, g_enchi);
    cudaGetSymbolAddress((void**)&p_enclo, g_enclo);
    cudaGetSymbolAddress((void**)&p_b1, g_blend1);
    cudaGetSymbolAddress((void**)&p_b2, g_blend2);
    cudaGetSymbolAddress((void**)&p_eWhi, g_eWhi);
    cudaGetSymbolAddress((void**)&p_eWlo, g_eWlo);
    cudaGetSymbolAddress((void**)&p_dWhi, g_dWhi);
    cudaGetSymbolAddress((void**)&p_dWlo, g_dWlo);
    cudaGetSymbolAddress((void**)&p_W1hi, g_W1hi);
    cudaGetSymbolAddress((void**)&p_W1lo, g_W1lo);
    cudaGetSymbolAddress((void**)&p_bd2, g_bias_dec2);
    cudaGetSymbolAddress((void**)&p_P, g_P);

    const int BHB = (Bn * Hn + 255) / 256;

    k_prep<<<(ND * Hn + 255) / 256, 256>>>(eWhh, dWhh, dbih, dbhh, W2, W1);
    k_prep_P<<<(Vn * Gn + 255) / 256, 256>>>(emb, eWih, ebih, ebhh);
    k_init<<<BHB, 256>>>();

    // -------- encoder: 50 fused mma GEMM+cell steps --------
    for (int t = 0; t < Sn; t++) {
        __half* ihi = (t & 1) ? p_hhi1 : p_hhi0;
        __half* ilo = (t & 1) ? p_hlo1 : p_hlo0;
        __half* ohi = (t & 1) ? p_hhi0 : p_hhi1;
        __half* olo = (t & 1) ? p_hlo0 : p_hlo1;
        gemm_mma<1><<<dim3(Gn / 128, Bn / 128), 512, SM_TOTAL>>>(
            ihi, ilo, Bn / 16, p_eWhi, p_eWlo, Gn / 8,
            nullptr, p_P, input, nullptr,
            ohi, olo, p_cE, p_enchi, p_enclo, p_cD, t);
    }

    // -------- blend1 = enc_states @ W1^T : [(t*Bn+b)][W] --------
    gemm_mma<0><<<dim3(Wn / 128, BSn / 128), 512, SM_TOTAL>>>(
        p_enchi, p_enclo, BSn / 16, p_W1hi, p_W1lo, Wn / 8,
        nullptr, nullptr, nullptr, p_b1,
        nullptr, nullptr, nullptr, nullptr, nullptr, nullptr, 0);

    // -------- decoder first cell (h_prev = 0), c0 = enc h49 --------
    k_dec0<<<BHB, 256>>>();

    uint32_t K0[Ln], K1[Ln];
    for (int l = 0; l < Ln; l++) tf_host(0u, 42u, 0u, (uint32_t)l, K0[l], K1[l]);

    for (int l = 0; l < Ln; l++) {
        __half* ihi = (l & 1) ? p_hhi1 : p_hhi0;
        __half* ilo = (l & 1) ? p_hlo1 : p_hlo0;
        __half* ohi = (l & 1) ? p_hhi0 : p_hhi1;
        __half* olo = (l & 1) ? p_hlo0 : p_hlo1;
        gemm_mma<2><<<dim3(ND / 128, Bn / 128), 512, SM_TOTAL>>>(
            ihi, ilo, Bn / 16, p_dWhi, p_dWlo, ND / 8,
            p_bd2, nullptr, nullptr, p_b2,
            ohi, olo, p_cD, nullptr, nullptr, nullptr, 0);
        k_attn<<<Bn, 256>>>(vt, l, K0[l], K1[l], probs, tour);
    }
    (void)in_sizes; (void)n_in; (void)out_size;
}

// round 11
// speedup vs baseline: 1.9736x; 1.0886x over previous
#include <cuda_runtime.h>
#include <cuda_fp16.h>
#include <cstdint>
#include <math.h>

// Problem constants
#define Bn 2048
#define Sn 50
#define En 256
#define Hn 512
#define Gn 2048        // 4*H
#define Wn 256
#define Ln 50
#define ND (Gn + Wn)   // 2304 : [interleaved dec gates | W2 rows]
#define Vn 51
#define BSn (Bn * Sn)

// ---------------- device scratch (fp16 fragment-order layouts) ----------------
__device__ __half g_hhi0[Bn * Hn];
__device__ __half g_hlo0[Bn * Hn];
__device__ __half g_hhi1[Bn * Hn];
__device__ __half g_hlo1[Bn * Hn];
__device__ float  g_cE[Bn * Hn];                    // encoder cell state [m][j]
__device__ float  g_cD[Bn * Hn];                    // decoder cell state
__device__ __half g_enchi[(size_t)BSn * Hn];        // enc states, A-frag layout
__device__ __half g_enclo[(size_t)BSn * Hn];
__device__ float  g_blend1[(size_t)BSn * Wn];       // [(t*Bn+b)][w] row-major
__device__ float  g_blend2[Bn * Wn];
__device__ unsigned char g_mask[Bn * Sn];
__device__ __half g_eWhi[Gn * Hn];                  // enc Whh, B-frag layout
__device__ __half g_eWlo[Gn * Hn];
__device__ __half g_dWhi[ND * Hn];                  // dec Whh | W2, B-frag layout
__device__ __half g_dWlo[ND * Hn];
__device__ __half g_W1hi[Wn * Hn];
__device__ __half g_W1lo[Wn * Hn];
__device__ float  g_bias_dec2[Gn];
__device__ float  g_P[Vn * Gn];                     // emb@Wih^T + enc bias (fp32 exact)

// ---------------- helpers ----------------
__device__ __forceinline__ float sigf(float x) { return 1.0f / (1.0f + expf(-x)); }

__device__ __forceinline__ void hsplit(float x, __half& hi, __half& lo) {
    hi = __float2half_rn(x);
    lo = __float2half_rn(x - __half2float(hi));
}

__device__ __forceinline__ void cp16(uint32_t dst, const void* src) {
    asm volatile("cp.async.cg.shared.global [%0], [%1], 16;\n" :: "r"(dst), "l"(src));
}

// mma.sync m16n8k16 fp16: D(f32) += A(f16)*B(f16)   (row.col)
#define MMA16(accp, av, bv)                                                \
    asm volatile(                                                          \
        "mma.sync.aligned.m16n8k16.row.col.f32.f16.f16.f32 "               \
        "{%0,%1,%2,%3}, {%4,%5,%6,%7}, {%8,%9}, {%0,%1,%2,%3};"            \
        : "+f"((accp)[0]), "+f"((accp)[1]), "+f"((accp)[2]), "+f"((accp)[3]) \
        : "r"((av).x), "r"((av).y), "r"((av).z), "r"((av).w),              \
          "r"((bv).x), "r"((bv).y))

// A-fragment (m16n8k16 f16) half-element index for A[m][k]
__device__ __forceinline__ size_t afrag(size_t m, int k, int mtiles) {
    int kc = k >> 5, s = (k >> 4) & 1, k16 = k & 15;
    int tt = ((int)(m & 7)) * 4 + ((k16 >> 1) & 3);
    int r = (int)((m >> 3) & 1) + (((k16 >> 3) & 1) << 1);
    return ((((size_t)(kc * 2 + s) * mtiles + (m >> 4)) * 32 + tt) * 4 + r) * 2 + (k16 & 1);
}
// B-fragment (m16n8k16 f16) half-element index for B[n][k]
__device__ __forceinline__ size_t bfrag(int n, int k, int ntiles) {
    int kc = k >> 5, s = (k >> 4) & 1, k16 = k & 15;
    int tt = (n & 7) * 4 + ((k16 >> 1) & 3);
    int r = (k16 >> 3) & 1;
    return ((((size_t)(kc * 2 + s) * ntiles + (n >> 3)) * 32 + tt) * 2 + r) * 2 + (k16 & 1);
}

// ---------------- prep kernels ----------------
__global__ void k_prep(const float* __restrict__ eWhh,
                       const float* __restrict__ dWhh, const float* __restrict__ dbih,
                       const float* __restrict__ dbhh, const float* __restrict__ W2,
                       const float* __restrict__ W1) {
    int idx = blockIdx.x * blockDim.x + threadIdx.x;
    if (idx < Gn * Hn) {
        int n2 = idx / Hn, k = idx % Hn;
        int g = n2 & 3, j = n2 >> 2;
        __half hi, lo;
        hsplit(eWhh[(g * Hn + j) * Hn + k], hi, lo);
        size_t o = bfrag(n2, k, Gn / 8);
        g_eWhi[o] = hi; g_eWlo[o] = lo;
    }
    if (idx < ND * Hn) {
        int n2 = idx / Hn, k = idx % Hn;
        float v;
        if (n2 < Gn) {
            int g = n2 & 3, j = n2 >> 2;
            v = dWhh[(g * Hn + j) * Hn + k];
        } else {
            v = W2[(size_t)(n2 - Gn) * Hn + k];
        }
        __half hi, lo;
        hsplit(v, hi, lo);
        size_t o = bfrag(n2, k, ND / 8);
        g_dWhi[o] = hi; g_dWlo[o] = lo;
    }
    if (idx < Wn * Hn) {
        int w = idx / Hn, k = idx % Hn;
        __half hi, lo;
        hsplit(W1[idx], hi, lo);
        size_t o = bfrag(w, k, Wn / 8);
        g_W1hi[o] = hi; g_W1lo[o] = lo;
    }
    if (idx < Gn) {
        int g = idx & 3, j = idx >> 2;
        int r = g * Hn + j;
        g_bias_dec2[idx] = dbih[r] + dbhh[r];
    }
}

__global__ void k_prep_P(const float* __restrict__ emb, const float* __restrict__ eWih,
                         const float* __restrict__ ebih, const float* __restrict__ ebhh) {
    int idx = blockIdx.x * blockDim.x + threadIdx.x;
    if (idx >= Vn * Gn) return;
    int v = idx / Gn, n2 = idx % Gn;
    int g = n2 & 3, j = n2 >> 2;
    int r = g * Hn + j;
    const float4* e = reinterpret_cast<const float4*>(emb + (size_t)v * En);
    const float4* w = reinterpret_cast<const float4*>(eWih + (size_t)r * En);
    float s = 0.0f;
    #pragma unroll 8
    for (int k = 0; k < En / 4; k++) {
        float4 a = __ldg(e + k), b = __ldg(w + k);
        s += a.x * b.x + a.y * b.y + a.z * b.z + a.w * b.w;
    }
    g_P[idx] = s + ebih[r] + ebhh[r];
}

__global__ void k_init() {
    int idx = blockIdx.x * blockDim.x + threadIdx.x;
    if (idx < Bn * Hn) {
        g_hhi0[idx] = __float2half(0.0f);
        g_hlo0[idx] = __float2half(0.0f);
        g_cE[idx] = 0.0f;
    }
    if (idx < Bn * Sn) g_mask[idx] = 0;
}

// decoder first cell: gates = bias only; c0 already in g_cD (enc h49)
__global__ void k_dec0() {
    int idx = blockIdx.x * blockDim.x + threadIdx.x;
    if (idx >= Bn * Hn) return;
    int b = idx / Hn, j = idx % Hn;
    float gi = g_bias_dec2[4 * j + 0], gf = g_bias_dec2[4 * j + 1];
    float gg = g_bias_dec2[4 * j + 2], go = g_bias_dec2[4 * j + 3];
    float c0 = g_cD[idx];
    float cn = sigf(gf) * c0 + sigf(gi) * tanhf(gg);
    float hn = sigf(go) * tanhf(cn);
    g_cD[idx] = cn;
    __half hi, lo;
    hsplit(hn, hi, lo);
    size_t ao = afrag((size_t)b, j, Bn / 16);
    g_hhi0[ao] = hi; g_hlo0[ao] = lo;
}

// ---------------- fp16 mma.sync GEMM, 3-product split, 128x256 CTA tile -----
// 512 threads, 16 warps in 4x4 grid, warp tile 32x64.
// Triple-buffered cp.async (48KB/chunk), one __syncthreads per chunk.
// MODE 0: plain store (blend1)  MODE 1: encoder LSTM  MODE 2: dec LSTM | blend2
template <int MODE>
__global__ __launch_bounds__(512, 1) void gemm_mma(
    const __half* __restrict__ Ahi, const __half* __restrict__ Alo, int Mtiles,
    const __half* __restrict__ Bhi, const __half* __restrict__ Blo, int Ntiles,
    const float* __restrict__ bias2, const float* __restrict__ P,
    const int* __restrict__ tok,
    float* __restrict__ Cout,
    __half* __restrict__ hhi, __half* __restrict__ hlo,
    float* __restrict__ cst,
    __half* __restrict__ enchi, __half* __restrict__ enclo,
    float* __restrict__ cD, int t) {
    extern __shared__ char smem[];
    const int tid = threadIdx.x;
    const int lane = tid & 31, wid = tid >> 5;
    const int bm = blockIdx.y * 128, bn = blockIdx.x * 256;
    const int bm16 = bm >> 4, bn8 = bn >> 3;
    const int mw = wid & 3, nw = wid >> 2;        // mw 0..3 (32 rows), nw 0..3 (64 cols)

    float acc[2][8][4];
#pragma unroll
    for (int i = 0; i < 2; i++)
#pragma unroll
        for (int jn = 0; jn < 8; jn++)
#pragma unroll
            for (int p = 0; p < 4; p++) acc[i][jn][p] = 0.0f;

    // smem per buffer: Ahi 8KB | Alo 8KB | Bhi 16KB | Blo 16KB = 48KB
    auto issue = [&](int c, int buf) {
#pragma unroll
        for (int q = 0; q < 6; q++) {
            int cid = tid + q * 512;              // 3072 x 16B chunks
            const __half* src;
            uint32_t dof;
            if (cid < 1024) {
                int arr = cid >> 9;               // 0:Ahi 1:Alo
                int within = cid & 511;
                int s = within >> 8, rest = within & 255;
                const __half* base = arr ? Alo : Ahi;
                src = base + ((size_t)(c * 2 + s) * Mtiles + bm16) * 256 + rest * 8;
                dof = (uint32_t)(buf * 49152 + arr * 8192 + within * 16);
            } else {
                int b2 = cid - 1024;
                int arr = b2 >> 10;               // 0:Bhi 1:Blo
                int within = b2 & 1023;
                int s = within >> 9, rest = within & 511;
                const __half* base = arr ? Blo : Bhi;
                src = base + ((size_t)(c * 2 + s) * Ntiles + bn8) * 128 + rest * 8;
                dof = (uint32_t)(buf * 49152 + 16384 + arr * 16384 + within * 16);
            }
            cp16((uint32_t)__cvta_generic_to_shared(smem + dof), src);
        }
        asm volatile("cp.async.commit_group;\n");
    };

    issue(0, 0);
    issue(1, 1);
#pragma unroll 1
    for (int c = 0; c < 16; c++) {
        const int buf = c % 3;
        if (c < 15) { asm volatile("cp.async.wait_group 1;\n"); }
        else        { asm volatile("cp.async.wait_group 0;\n"); }
        __syncthreads();
        if (c + 2 < 16) issue(c + 2, (c + 2) % 3);
#pragma unroll
        for (int s = 0; s < 2; s++) {
            uint4 ah[2], al[2];
#pragma unroll
            for (int mt = 0; mt < 2; mt++) {
                int moff = buf * 49152 + s * 4096 + (mw * 2 + mt) * 512 + lane * 16;
                ah[mt] = *reinterpret_cast<const uint4*>(smem + moff);
                al[mt] = *reinterpret_cast<const uint4*>(smem + moff + 8192);
            }
#pragma unroll
            for (int nt = 0; nt < 8; nt++) {
                int boff = buf * 49152 + 16384 + s * 8192 + (nw * 8 + nt) * 256 + lane * 8;
                uint2 bh = *reinterpret_cast<const uint2*>(smem + boff);
                uint2 bl = *reinterpret_cast<const uint2*>(smem + boff + 16384);
                MMA16(acc[0][nt], ah[0], bh);
                MMA16(acc[1][nt], ah[1], bh);
                MMA16(acc[0][nt], ah[0], bl);
                MMA16(acc[1][nt], ah[1], bl);
                MMA16(acc[0][nt], al[0], bh);
                MMA16(acc[1][nt], al[1], bh);
                // lo*lo dropped: 2^-22 class, validated in R9/R10
            }
        }
    }

    // ---------------- epilogue ----------------
    if (MODE == 0 || (MODE == 2 && bn >= Gn)) {
#pragma unroll
        for (int mt = 0; mt < 2; mt++)
#pragma unroll
            for (int nt = 0; nt < 8; nt++) {
                int row = bm + mw * 32 + mt * 16 + (lane >> 2);
                int col = bn + nw * 64 + nt * 8 + (lane & 3) * 2;
                if (MODE == 2) col -= Gn;
                float* dst = Cout + (size_t)row * Wn + col;
                *reinterpret_cast<float2*>(dst) =
                    make_float2(acc[mt][nt][0], acc[mt][nt][1]);
                *reinterpret_cast<float2*>(dst + 8 * Wn) =
                    make_float2(acc[mt][nt][2], acc[mt][nt][3]);
            }
    } else {
        float* gsm = reinterpret_cast<float*>(smem);
        __syncthreads();   // all warps done reading smem buffers before reuse
#pragma unroll
        for (int mt = 0; mt < 2; mt++)
#pragma unroll
            for (int nt = 0; nt < 8; nt++) {
                int rl = mw * 32 + mt * 16 + (lane >> 2);
                int cl = nw * 64 + nt * 8 + (lane & 3) * 2;
                *reinterpret_cast<float2*>(&gsm[rl * 260 + cl]) =
                    make_float2(acc[mt][nt][0], acc[mt][nt][1]);
                *reinterpret_cast<float2*>(&gsm[(rl + 8) * 260 + cl]) =
                    make_float2(acc[mt][nt][2], acc[mt][nt][3]);
            }
        __syncthreads();
#pragma unroll 1
        for (int q = 0; q < 16; q++) {
            int idx = q * 512 + tid;
            int ml = idx >> 6, j4 = idx & 63;
            float4 gv = *reinterpret_cast<const float4*>(&gsm[ml * 260 + j4 * 4]);
            int mrow = bm + ml;
            int n = bn + j4 * 4;
            int j = n >> 2;
            float g0 = gv.x, g1 = gv.y, g2 = gv.z, g3 = gv.w;
            if (MODE == 1) {
                int tokv = tok[mrow * Sn + t];
                float4 pv = *reinterpret_cast<const float4*>(P + (size_t)tokv * Gn + n);
                g0 += pv.x; g1 += pv.y; g2 += pv.z; g3 += pv.w;
            } else {
                float4 bv = *reinterpret_cast<const float4*>(bias2 + n);
                g0 += bv.x; g1 += bv.y; g2 += bv.z; g3 += bv.w;
            }
            float co = cst[mrow * Hn + j];
            float cn = sigf(g1) * co + sigf(g0) * tanhf(g2);
            float hn = sigf(g3) * tanhf(cn);
            cst[mrow * Hn + j] = cn;
            __half hi, lo;
            hsplit(hn, hi, lo);
            size_t ao = afrag((size_t)mrow, j, Bn / 16);
            hhi[ao] = hi; hlo[ao] = lo;
            if (MODE == 1) {
                size_t er = (size_t)t * Bn + mrow;
                size_t eo = afrag(er, j, BSn / 16);
                enchi[eo] = hi; enclo[eo] = lo;
                if (t == Sn - 1) cD[mrow * Hn + j] = hn;
            }
        }
    }
}

// ---------------- threefry2x32 (JAX-compatible) ----------------
__device__ __forceinline__ uint32_t rotl32(uint32_t v, int d) { return (v << d) | (v >> (32 - d)); }

__device__ uint32_t threefry_xor(uint32_t k0, uint32_t k1, uint32_t x0, uint32_t x1) {
    uint32_t ks2 = k0 ^ k1 ^ 0x1BD11BDAu;
    x0 += k0; x1 += k1;
    const int ra[4] = {13, 15, 26, 6}, rb[4] = {17, 29, 16, 24};
#pragma unroll
    for (int i = 0; i < 4; i++) { x0 += x1; x1 = rotl32(x1, ra[i]); x1 ^= x0; }
    x0 += k1; x1 += ks2 + 1u;
#pragma unroll
    for (int i = 0; i < 4; i++) { x0 += x1; x1 = rotl32(x1, rb[i]); x1 ^= x0; }
    x0 += ks2; x1 += k0 + 2u;
#pragma unroll
    for (int i = 0; i < 4; i++) { x0 += x1; x1 = rotl32(x1, ra[i]); x1 ^= x0; }
    x0 += k0; x1 += k1 + 3u;
#pragma unroll
    for (int i = 0; i < 4; i++) { x0 += x1; x1 = rotl32(x1, rb[i]); x1 ^= x0; }
    x0 += k1; x1 += ks2 + 4u;
#pragma unroll
    for (int i = 0; i < 4; i++) { x0 += x1; x1 = rotl32(x1, ra[i]); x1 ^= x0; }
    x0 += ks2; x1 += k0 + 5u;
    return x0 ^ x1;  // partitionable 32-bit random_bits = out0 ^ out1
}

__device__ __forceinline__ float gumbel_from_bits(uint32_t bits) {
    const float TINY = 1.17549435e-38f;
    float f = __uint_as_float((bits >> 9) | 0x3f800000u) - 1.0f;
    float u = f * (1.0f - TINY) + TINY;
    u = fmaxf(TINY, u);
    return -logf(-logf(u));
}

// ---------------- fused scores + masked log-softmax + sample ----------------
__global__ void k_attn(const float* __restrict__ vt, int l,
                       uint32_t key0, uint32_t key1,
                       float* __restrict__ probs, float* __restrict__ tour) {
    int b = blockIdx.x, tid = threadIdx.x;  // 256 threads
    __shared__ float sb[Wn], sv[Wn], ssc[64];
    sb[tid] = g_blend2[b * Wn + tid];
    sv[tid] = vt[tid];
    __syncthreads();
    int warp = tid >> 5, lane = tid & 31;
    for (int s = warp; s < Sn; s += 8) {
        const float* row = g_blend1 + ((size_t)s * Bn + b) * Wn;
        float acc = 0.0f;
#pragma unroll
        for (int q = 0; q < 8; q++) {
            int w = lane + q * 32;
            acc += tanhf(row[w] + sb[w]) * sv[w];
        }
        for (int off = 16; off; off >>= 1) acc += __shfl_xor_sync(0xffffffffu, acc, off);
        if (lane == 0) ssc[s] = acc;
    }
    __syncthreads();
    if (warp != 0) return;
    int s0 = lane, s1 = lane + 32;
    const float NEG = -3.4e38f;
    float x0 = g_mask[b * Sn + s0] ? -100000.0f : ssc[s0];
    float x1 = NEG;
    if (s1 < Sn) x1 = g_mask[b * Sn + s1] ? -100000.0f : ssc[s1];
    float m = fmaxf(x0, x1);
    for (int off = 16; off; off >>= 1) m = fmaxf(m, __shfl_xor_sync(0xffffffffu, m, off));
    float sum = expf(x0 - m) + ((s1 < Sn) ? expf(x1 - m) : 0.0f);
    for (int off = 16; off; off >>= 1) sum += __shfl_xor_sync(0xffffffffu, sum, off);
    float lse = logf(sum);
    float lp0 = x0 - m - lse;
    float lp1 = x1 - m - lse;
    float* prow = probs + ((size_t)b * Ln + l) * Sn;
    prow[s0] = lp0;
    if (s1 < Sn) prow[s1] = lp1;
    float v0 = lp0 + gumbel_from_bits(threefry_xor(key0, key1, 0u, (uint32_t)(b * Sn + s0)));
    float v1 = NEG;
    if (s1 < Sn) v1 = lp1 + gumbel_from_bits(threefry_xor(key0, key1, 0u, (uint32_t)(b * Sn + s1)));
    float bv; int bi;
    if (v1 > v0) { bv = v1; bi = s1; } else { bv = v0; bi = s0; }
    for (int off = 16; off; off >>= 1) {
        float ov = __shfl_xor_sync(0xffffffffu, bv, off);
        int   oi = __shfl_xor_sync(0xffffffffu, bi, off);
        if (ov > bv || (ov == bv && oi < bi)) { bv = ov; bi = oi; }
    }
    if (lane == 0) {
        tour[(size_t)b * Ln + l] = (float)bi;
        g_mask[b * Sn + bi] = 1;
    }
}

// ---------------- host threefry ----------------
static void tf_host(uint32_t k0, uint32_t k1, uint32_t x0, uint32_t x1,
                    uint32_t& o0, uint32_t& o1) {
    uint32_t ks2 = k0 ^ k1 ^ 0x1BD11BDAu;
    x0 += k0; x1 += k1;
    const int ra[4] = {13, 15, 26, 6}, rb[4] = {17, 29, 16, 24};
    auto rl = [](uint32_t v, int d) { return (v << d) | (v >> (32 - d)); };
    for (int i = 0; i < 4; i++) { x0 += x1; x1 = rl(x1, ra[i]); x1 ^= x0; }
    x0 += k1; x1 += ks2 + 1u;
    for (int i = 0; i < 4; i++) { x0 += x1; x1 = rl(x1, rb[i]); x1 ^= x0; }
    x0 += ks2; x1 += k0 + 2u;
    for (int i = 0; i < 4; i++) { x0 += x1; x1 = rl(x1, ra[i]); x1 ^= x0; }
    x0 += k0; x1 += k1 + 3u;
    for (int i = 0; i < 4; i++) { x0 += x1; x1 = rl(x1, rb[i]); x1 ^= x0; }
    x0 += k1; x1 += ks2 + 4u;
    for (int i = 0; i < 4; i++) { x0 += x1; x1 = rl(x1, ra[i]); x1 ^= x0; }
    x0 += ks2; x1 += k0 + 5u;
    o0 = x0; o1 = x1;
}

#define SM_TOTAL 147456

extern "C" void kernel_launch(void* const* d_in, const int* in_sizes, int n_in,
                              void* d_out, int out_size) {
    const int*   input = (const int*)d_in[0];
    const float* emb   = (const float*)d_in[1];
    const float* eWih  = (const float*)d_in[2];
    const float* eWhh  = (const float*)d_in[3];
    const float* ebih  = (const float*)d_in[4];
    const float* ebhh  = (const float*)d_in[5];
    // d_in[6] = dec_Wih (unused: decoder input is always zero)
    const float* dWhh  = (const float*)d_in[7];
    const float* dbih  = (const float*)d_in[8];
    const float* dbhh  = (const float*)d_in[9];
    const float* W1    = (const float*)d_in[10];
    const float* W2    = (const float*)d_in[11];
    const float* vt    = (const float*)d_in[12];

    float* out   = (float*)d_out;
    float* probs = out;                               // [B, L, S]
    float* tour  = out + (size_t)Bn * Ln * Sn;        // [B, L] as float

    cudaFuncSetAttribute(gemm_mma<0>, cudaFuncAttributeMaxDynamicSharedMemorySize, SM_TOTAL);
    cudaFuncSetAttribute(gemm_mma<1>, cudaFuncAttributeMaxDynamicSharedMemorySize, SM_TOTAL);
    cudaFuncSetAttribute(gemm_mma<2>, cudaFuncAttributeMaxDynamicSharedMemorySize, SM_TOTAL);

    __half *p_hhi0, *p_hlo0, *p_hhi1, *p_hlo1, *p_enchi, *p_enclo;
    __half *p_eWhi, *p_eWlo, *p_dWhi, *p_dWlo, *p_W1hi, *p_W1lo;
    float *p_cE, *p_cD, *p_b1, *p_b2, *p_bd2, *p_P;
    cudaGetSymbolAddress((void**)&p_hhi0, g_hhi0);
    cudaGetSymbolAddress((void**)&p_hlo0, g_hlo0);
    cudaGetSymbolAddress((void**)&p_hhi1, g_hhi1);
    cudaGetSymbolAddress((void**)&p_hlo1, g_hlo1);
    cudaGetSymbolAddress((void**)&p_cE, g_cE);
    cudaGetSymbolAddress((void**)&p_cD, g_cD);
    cudaGetSymbolAddress((void**)&p_enchi, g_enchi);
    cudaGetSymbolAddress((void**)&p_enclo, g_enclo);
    cudaGetSymbolAddress((void**)&p_b1, g_blend1);
    cudaGetSymbolAddress((void**)&p_b2, g_blend2);
    cudaGetSymbolAddress((void**)&p_eWhi, g_eWhi);
    cudaGetSymbolAddress((void**)&p_eWlo, g_eWlo);
    cudaGetSymbolAddress((void**)&p_dWhi, g_dWhi);
    cudaGetSymbolAddress((void**)&p_dWlo, g_dWlo);
    cudaGetSymbolAddress((void**)&p_W1hi, g_W1hi);
    cudaGetSymbolAddress((void**)&p_W1lo, g_W1lo);
    cudaGetSymbolAddress((void**)&p_bd2, g_bias_dec2);
    cudaGetSymbolAddress((void**)&p_P, g_P);

    const int BHB = (Bn * Hn + 255) / 256;

    k_prep<<<(ND * Hn + 255) / 256, 256>>>(eWhh, dWhh, dbih, dbhh, W2, W1);
    k_prep_P<<<(Vn * Gn + 255) / 256, 256>>>(emb, eWih, ebih, ebhh);
    k_init<<<BHB, 256>>>();

    // -------- encoder: 50 fused mma GEMM+cell steps (grid 8x16 = 128 CTAs) --
    for (int t = 0; t < Sn; t++) {
        __half* ihi = (t & 1) ? p_hhi1 : p_hhi0;
        __half* ilo = (t & 1) ? p_hlo1 : p_hlo0;
        __half* ohi = (t & 1) ? p_hhi0 : p_hhi1;
        __half* olo = (t & 1) ? p_hlo0 : p_hlo1;
        gemm_mma<1><<<dim3(Gn / 256, Bn / 128), 512, SM_TOTAL>>>(
            ihi, ilo, Bn / 16, p_eWhi, p_eWlo, Gn / 8,
            nullptr, p_P, input, nullptr,
            ohi, olo, p_cE, p_enchi, p_enclo, p_cD, t);
    }

    // -------- blend1 = enc_states @ W1^T : [(t*Bn+b)][W] --------
    gemm_mma<0><<<dim3(Wn / 256, BSn / 128), 512, SM_TOTAL>>>(
        p_enchi, p_enclo, BSn / 16, p_W1hi, p_W1lo, Wn / 8,
        nullptr, nullptr, nullptr, p_b1,
        nullptr, nullptr, nullptr, nullptr, nullptr, nullptr, 0);

    // -------- decoder first cell (h_prev = 0), c0 = enc h49 --------
    k_dec0<<<BHB, 256>>>();

    uint32_t K0[Ln], K1[Ln];
    for (int l = 0; l < Ln; l++) tf_host(0u, 42u, 0u, (uint32_t)l, K0[l], K1[l]);

    for (int l = 0; l < Ln; l++) {
        __half* ihi = (l & 1) ? p_hhi1 : p_hhi0;
        __half* ilo = (l & 1) ? p_hlo1 : p_hlo0;
        __half* ohi = (l & 1) ? p_hhi0 : p_hhi1;
        __half* olo = (l & 1) ? p_hlo0 : p_hlo1;
        // grid 9x16 = 144 CTAs: blocks x<8 gates, x==8 blend2
        gemm_mma<2><<<dim3(ND / 256, Bn / 128), 512, SM_TOTAL>>>(
            ihi, ilo, Bn / 16, p_dWhi, p_dWlo, ND / 8,
            p_bd2, nullptr, nullptr, p_b2,
            ohi, olo, p_cD, nullptr, nullptr, nullptr, 0);
        k_attn<<<Bn, 256>>>(vt, l, K0[l], K1[l], probs, tour);
    }
    (void)in_sizes; (void)n_in; (void)out_size;
}

// round 12
// speedup vs baseline: 1.9899x; 1.0083x over previous
#include <cuda_runtime.h>
#include <cuda_fp16.h>
#include <cstdint>
#include <math.h>

// Problem constants
#define Bn 2048
#define Sn 50
#define En 256
#define Hn 512
#define Gn 2048        // 4*H
#define Wn 256
#define Ln 50
#define ND (Gn + Wn)   // 2304 : [interleaved dec gates | W2 rows]
#define Vn 51
#define BSn (Bn * Sn)

// ---------------- device scratch (fp16 fragment-order layouts) ----------------
__device__ __half g_hhi0[Bn * Hn];
__device__ __half g_hlo0[Bn * Hn];
__device__ __half g_hhi1[Bn * Hn];
__device__ __half g_hlo1[Bn * Hn];
__device__ float  g_cE[Bn * Hn];                    // encoder cell state [m][j]
__device__ float  g_cD[Bn * Hn];                    // decoder cell state
__device__ __half g_enchi[(size_t)BSn * Hn];        // enc states, A-frag layout
__device__ __half g_enclo[(size_t)BSn * Hn];
__device__ float  g_blend1[(size_t)BSn * Wn];       // [(t*Bn+b)][w] row-major
__device__ float  g_blend2[Bn * Wn];
__device__ unsigned char g_mask[Bn * Sn];
__device__ __half g_eWhi[Gn * Hn];                  // enc Whh, B-frag layout
__device__ __half g_eWlo[Gn * Hn];
__device__ __half g_dWhi[ND * Hn];                  // dec Whh | W2, B-frag layout
__device__ __half g_dWlo[ND * Hn];
__device__ __half g_W1hi[Wn * Hn];
__device__ __half g_W1lo[Wn * Hn];
__device__ float  g_bias_dec2[Gn];
__device__ float  g_P[Vn * Gn];                     // emb@Wih^T + enc bias (fp32 exact)

// ---------------- helpers ----------------
__device__ __forceinline__ float sigf(float x) { return 1.0f / (1.0f + expf(-x)); }

__device__ __forceinline__ void hsplit(float x, __half& hi, __half& lo) {
    hi = __float2half_rn(x);
    lo = __float2half_rn(x - __half2float(hi));
}

__device__ __forceinline__ void cp16(uint32_t dst, const void* src) {
    asm volatile("cp.async.cg.shared.global [%0], [%1], 16;\n" :: "r"(dst), "l"(src));
}

// mma.sync m16n8k16 fp16: D(f32) += A(f16)*B(f16)   (row.col)
#define MMA16(accp, av, bv)                                                \
    asm volatile(                                                          \
        "mma.sync.aligned.m16n8k16.row.col.f32.f16.f16.f32 "               \
        "{%0,%1,%2,%3}, {%4,%5,%6,%7}, {%8,%9}, {%0,%1,%2,%3};"            \
        : "+f"((accp)[0]), "+f"((accp)[1]), "+f"((accp)[2]), "+f"((accp)[3]) \
        : "r"((av).x), "r"((av).y), "r"((av).z), "r"((av).w),              \
          "r"((bv).x), "r"((bv).y))

// A-fragment (m16n8k16 f16) half-element index for A[m][k]
__device__ __forceinline__ size_t afrag(size_t m, int k, int mtiles) {
    int kc = k >> 5, s = (k >> 4) & 1, k16 = k & 15;
    int tt = ((int)(m & 7)) * 4 + ((k16 >> 1) & 3);
    int r = (int)((m >> 3) & 1) + (((k16 >> 3) & 1) << 1);
    return ((((size_t)(kc * 2 + s) * mtiles + (m >> 4)) * 32 + tt) * 4 + r) * 2 + (k16 & 1);
}
// B-fragment (m16n8k16 f16) half-element index for B[n][k]
__device__ __forceinline__ size_t bfrag(int n, int k, int ntiles) {
    int kc = k >> 5, s = (k >> 4) & 1, k16 = k & 15;
    int tt = (n & 7) * 4 + ((k16 >> 1) & 3);
    int r = (k16 >> 3) & 1;
    return ((((size_t)(kc * 2 + s) * ntiles + (n >> 3)) * 32 + tt) * 2 + r) * 2 + (k16 & 1);
}

// ---------------- prep kernels ----------------
__global__ void k_prep(const float* __restrict__ eWhh,
                       const float* __restrict__ dWhh, const float* __restrict__ dbih,
                       const float* __restrict__ dbhh, const float* __restrict__ W2,
                       const float* __restrict__ W1) {
    int idx = blockIdx.x * blockDim.x + threadIdx.x;
    if (idx < Gn * Hn) {
        int n2 = idx / Hn, k = idx % Hn;
        int g = n2 & 3, j = n2 >> 2;
        __half hi, lo;
        hsplit(eWhh[(g * Hn + j) * Hn + k], hi, lo);
        size_t o = bfrag(n2, k, Gn / 8);
        g_eWhi[o] = hi; g_eWlo[o] = lo;
    }
    if (idx < ND * Hn) {
        int n2 = idx / Hn, k = idx % Hn;
        float v;
        if (n2 < Gn) {
            int g = n2 & 3, j = n2 >> 2;
            v = dWhh[(g * Hn + j) * Hn + k];
        } else {
            v = W2[(size_t)(n2 - Gn) * Hn + k];
        }
        __half hi, lo;
        hsplit(v, hi, lo);
        size_t o = bfrag(n2, k, ND / 8);
        g_dWhi[o] = hi; g_dWlo[o] = lo;
    }
    if (idx < Wn * Hn) {
        int w = idx / Hn, k = idx % Hn;
        __half hi, lo;
        hsplit(W1[idx], hi, lo);
        size_t o = bfrag(w, k, Wn / 8);
        g_W1hi[o] = hi; g_W1lo[o] = lo;
    }
    if (idx < Gn) {
        int g = idx & 3, j = idx >> 2;
        int r = g * Hn + j;
        g_bias_dec2[idx] = dbih[r] + dbhh[r];
    }
}

__global__ void k_prep_P(const float* __restrict__ emb, const float* __restrict__ eWih,
                         const float* __restrict__ ebih, const float* __restrict__ ebhh) {
    int idx = blockIdx.x * blockDim.x + threadIdx.x;
    if (idx >= Vn * Gn) return;
    int v = idx / Gn, n2 = idx % Gn;
    int g = n2 & 3, j = n2 >> 2;
    int r = g * Hn + j;
    const float4* e = reinterpret_cast<const float4*>(emb + (size_t)v * En);
    const float4* w = reinterpret_cast<const float4*>(eWih + (size_t)r * En);
    float s = 0.0f;
    #pragma unroll 8
    for (int k = 0; k < En / 4; k++) {
        float4 a = __ldg(e + k), b = __ldg(w + k);
        s += a.x * b.x + a.y * b.y + a.z * b.z + a.w * b.w;
    }
    g_P[idx] = s + ebih[r] + ebhh[r];
}

__global__ void k_init() {
    int idx = blockIdx.x * blockDim.x + threadIdx.x;
    if (idx < Bn * Hn) {
        g_hhi0[idx] = __float2half(0.0f);
        g_hlo0[idx] = __float2half(0.0f);
        g_cE[idx] = 0.0f;
    }
    if (idx < Bn * Sn) g_mask[idx] = 0;
}

// decoder first cell: gates = bias only; c0 already in g_cD (enc h49)
__global__ void k_dec0() {
    int idx = blockIdx.x * blockDim.x + threadIdx.x;
    if (idx >= Bn * Hn) return;
    int b = idx / Hn, j = idx % Hn;
    float gi = g_bias_dec2[4 * j + 0], gf = g_bias_dec2[4 * j + 1];
    float gg = g_bias_dec2[4 * j + 2], go = g_bias_dec2[4 * j + 3];
    float c0 = g_cD[idx];
    float cn = sigf(gf) * c0 + sigf(gi) * tanhf(gg);
    float hn = sigf(go) * tanhf(cn);
    g_cD[idx] = cn;
    __half hi, lo;
    hsplit(hn, hi, lo);
    size_t ao = afrag((size_t)b, j, Bn / 16);
    g_hhi0[ao] = hi; g_hlo0[ao] = lo;
}

// ---------------- fp16 mma.sync GEMM, 3-product split, 128x128 CTA tile -----
// 256 threads, 8 warps (4m x 2n), warp tile 32x64, 2 CTAs/SM.
// Triple-buffered cp.async (32KB/chunk), one __syncthreads per chunk.
// Product-major MMA order: same-acc reuse distance = 16 instructions.
// MODE 0: plain store (blend1)  MODE 1: encoder LSTM  MODE 2: dec LSTM | blend2
template <int MODE>
__global__ __launch_bounds__(256, 2) void gemm_mma(
    const __half* __restrict__ Ahi, const __half* __restrict__ Alo, int Mtiles,
    const __half* __restrict__ Bhi, const __half* __restrict__ Blo, int Ntiles,
    const float* __restrict__ bias2, const float* __restrict__ P,
    const int* __restrict__ tok,
    float* __restrict__ Cout,
    __half* __restrict__ hhi, __half* __restrict__ hlo,
    float* __restrict__ cst,
    __half* __restrict__ enchi, __half* __restrict__ enclo,
    float* __restrict__ cD, int t) {
    extern __shared__ char smem[];
    const int tid = threadIdx.x;
    const int lane = tid & 31, wid = tid >> 5;
    const int bm = blockIdx.y * 128, bn = blockIdx.x * 128;
    const int bm16 = bm >> 4, bn8 = bn >> 3;
    const int mw = wid & 3, nw = wid >> 2;        // mw 0..3 (32 rows), nw 0..1 (64 cols)

    float acc[2][8][4];
#pragma unroll
    for (int i = 0; i < 2; i++)
#pragma unroll
        for (int jn = 0; jn < 8; jn++)
#pragma unroll
            for (int p = 0; p < 4; p++) acc[i][jn][p] = 0.0f;

    // smem per buffer: Ahi 8KB | Alo 8KB | Bhi 8KB | Blo 8KB = 32KB
    auto issue = [&](int c, int buf) {
#pragma unroll
        for (int q = 0; q < 8; q++) {
            int cid = tid + q * 256;              // 2048 x 16B chunks
            int arr = cid >> 9;                   // 0:Ahi 1:Alo 2:Bhi 3:Blo
            int within = cid & 511;
            int s = within >> 8, rest = within & 255;
            const __half* src;
            if (arr < 2) {
                const __half* base = arr ? Alo : Ahi;
                src = base + ((size_t)(c * 2 + s) * Mtiles + bm16) * 256 + rest * 8;
            } else {
                const __half* base = (arr == 2) ? Bhi : Blo;
                src = base + ((size_t)(c * 2 + s) * Ntiles + bn8) * 128 + rest * 8;
            }
            uint32_t dof = (uint32_t)(buf * 32768 + arr * 8192 + within * 16);
            cp16((uint32_t)__cvta_generic_to_shared(smem + dof), src);
        }
        asm volatile("cp.async.commit_group;\n");
    };

    issue(0, 0);
    issue(1, 1);
#pragma unroll 1
    for (int c = 0; c < 16; c++) {
        const int buf = c % 3;
        if (c < 15) { asm volatile("cp.async.wait_group 1;\n"); }
        else        { asm volatile("cp.async.wait_group 0;\n"); }
        __syncthreads();
        if (c + 2 < 16) issue(c + 2, (c + 2) % 3);
#pragma unroll
        for (int s = 0; s < 2; s++) {
            uint4 ah[2], al[2];
#pragma unroll
            for (int mt = 0; mt < 2; mt++) {
                int moff = buf * 32768 + s * 4096 + (mw * 2 + mt) * 512 + lane * 16;
                ah[mt] = *reinterpret_cast<const uint4*>(smem + moff);
                al[mt] = *reinterpret_cast<const uint4*>(smem + moff + 8192);
            }
            uint2 bh[8], bl[8];
#pragma unroll
            for (int nt = 0; nt < 8; nt++) {
                int boff = buf * 32768 + 16384 + s * 4096 + (nw * 8 + nt) * 256 + lane * 8;
                bh[nt] = *reinterpret_cast<const uint2*>(smem + boff);
                bl[nt] = *reinterpret_cast<const uint2*>(smem + boff + 8192);
            }
            // product-major: same-acc reuse distance = 16 MMAs
#pragma unroll
            for (int nt = 0; nt < 8; nt++) {
                MMA16(acc[0][nt], ah[0], bh[nt]);
                MMA16(acc[1][nt], ah[1], bh[nt]);
            }
#pragma unroll
            for (int nt = 0; nt < 8; nt++) {
                MMA16(acc[0][nt], ah[0], bl[nt]);
                MMA16(acc[1][nt], ah[1], bl[nt]);
            }
#pragma unroll
            for (int nt = 0; nt < 8; nt++) {
                MMA16(acc[0][nt], al[0], bh[nt]);
                MMA16(acc[1][nt], al[1], bh[nt]);
                // lo*lo dropped: 2^-22 class, validated in R9/R10
            }
        }
    }

    // ---------------- epilogue ----------------
    if (MODE == 0 || (MODE == 2 && bn >= Gn)) {
#pragma unroll
        for (int mt = 0; mt < 2; mt++)
#pragma unroll
            for (int nt = 0; nt < 8; nt++) {
                int row = bm + mw * 32 + mt * 16 + (lane >> 2);
                int col = bn + nw * 64 + nt * 8 + (lane & 3) * 2;
                if (MODE == 2) col -= Gn;
                float* dst = Cout + (size_t)row * Wn + col;
                *reinterpret_cast<float2*>(dst) =
                    make_float2(acc[mt][nt][0], acc[mt][nt][1]);
                *reinterpret_cast<float2*>(dst + 8 * Wn) =
                    make_float2(acc[mt][nt][2], acc[mt][nt][3]);
            }
    } else {
        float* gsm = reinterpret_cast<float*>(smem);
        __syncthreads();   // all warps done reading smem buffers before reuse
#pragma unroll
        for (int mt = 0; mt < 2; mt++)
#pragma unroll
            for (int nt = 0; nt < 8; nt++) {
                int rl = mw * 32 + mt * 16 + (lane >> 2);
                int cl = nw * 64 + nt * 8 + (lane & 3) * 2;
                *reinterpret_cast<float2*>(&gsm[rl * 132 + cl]) =
                    make_float2(acc[mt][nt][0], acc[mt][nt][1]);
                *reinterpret_cast<float2*>(&gsm[(rl + 8) * 132 + cl]) =
                    make_float2(acc[mt][nt][2], acc[mt][nt][3]);
            }
        __syncthreads();
#pragma unroll 1
        for (int q = 0; q < 16; q++) {
            int idx = q * 256 + tid;
            int ml = idx >> 5, j4 = idx & 31;
            float4 gv = *reinterpret_cast<const float4*>(&gsm[ml * 132 + j4 * 4]);
            int mrow = bm + ml;
            int n = bn + j4 * 4;
            int j = n >> 2;
            float g0 = gv.x, g1 = gv.y, g2 = gv.z, g3 = gv.w;
            if (MODE == 1) {
                int tokv = tok[mrow * Sn + t];
                float4 pv = *reinterpret_cast<const float4*>(P + (size_t)tokv * Gn + n);
                g0 += pv.x; g1 += pv.y; g2 += pv.z; g3 += pv.w;
            } else {
                float4 bv = *reinterpret_cast<const float4*>(bias2 + n);
                g0 += bv.x; g1 += bv.y; g2 += bv.z; g3 += bv.w;
            }
            float co = cst[mrow * Hn + j];
            float cn = sigf(g1) * co + sigf(g0) * tanhf(g2);
            float hn = sigf(g3) * tanhf(cn);
            cst[mrow * Hn + j] = cn;
            __half hi, lo;
            hsplit(hn, hi, lo);
            size_t ao = afrag((size_t)mrow, j, Bn / 16);
            hhi[ao] = hi; hlo[ao] = lo;
            if (MODE == 1) {
                size_t er = (size_t)t * Bn + mrow;
                size_t eo = afrag(er, j, BSn / 16);
                enchi[eo] = hi; enclo[eo] = lo;
                if (t == Sn - 1) cD[mrow * Hn + j] = hn;
            }
        }
    }
}

// ---------------- threefry2x32 (JAX-compatible) ----------------
__device__ __forceinline__ uint32_t rotl32(uint32_t v, int d) { return (v << d) | (v >> (32 - d)); }

__device__ uint32_t threefry_xor(uint32_t k0, uint32_t k1, uint32_t x0, uint32_t x1) {
    uint32_t ks2 = k0 ^ k1 ^ 0x1BD11BDAu;
    x0 += k0; x1 += k1;
    const int ra[4] = {13, 15, 26, 6}, rb[4] = {17, 29, 16, 24};
#pragma unroll
    for (int i = 0; i < 4; i++) { x0 += x1; x1 = rotl32(x1, ra[i]); x1 ^= x0; }
    x0 += k1; x1 += ks2 + 1u;
#pragma unroll
    for (int i = 0; i < 4; i++) { x0 += x1; x1 = rotl32(x1, rb[i]); x1 ^= x0; }
    x0 += ks2; x1 += k0 + 2u;
#pragma unroll
    for (int i = 0; i < 4; i++) { x0 += x1; x1 = rotl32(x1, ra[i]); x1 ^= x0; }
    x0 += k0; x1 += k1 + 3u;
#pragma unroll
    for (int i = 0; i < 4; i++) { x0 += x1; x1 = rotl32(x1, rb[i]); x1 ^= x0; }
    x0 += k1; x1 += ks2 + 4u;
#pragma unroll
    for (int i = 0; i < 4; i++) { x0 += x1; x1 = rotl32(x1, ra[i]); x1 ^= x0; }
    x0 += ks2; x1 += k0 + 5u;
    return x0 ^ x1;  // partitionable 32-bit random_bits = out0 ^ out1
}

__device__ __forceinline__ float gumbel_from_bits(uint32_t bits) {
    const float TINY = 1.17549435e-38f;
    float f = __uint_as_float((bits >> 9) | 0x3f800000u) - 1.0f;
    float u = f * (1.0f - TINY) + TINY;
    u = fmaxf(TINY, u);
    return -logf(-logf(u));
}

// ---------------- fused scores + masked log-softmax + sample ----------------
__global__ void k_attn(const float* __restrict__ vt, int l,
                       uint32_t key0, uint32_t key1,
                       float* __restrict__ probs, float* __restrict__ tour) {
    int b = blockIdx.x, tid = threadIdx.x;  // 256 threads
    __shared__ float sb[Wn], sv[Wn], ssc[64];
    sb[tid] = g_blend2[b * Wn + tid];
    sv[tid] = vt[tid];
    __syncthreads();
    int warp = tid >> 5, lane = tid & 31;
    for (int s = warp; s < Sn; s += 8) {
        const float* row = g_blend1 + ((size_t)s * Bn + b) * Wn;
        float acc = 0.0f;
#pragma unroll
        for (int q = 0; q < 8; q++) {
            int w = lane + q * 32;
            acc += tanhf(row[w] + sb[w]) * sv[w];
        }
        for (int off = 16; off; off >>= 1) acc += __shfl_xor_sync(0xffffffffu, acc, off);
        if (lane == 0) ssc[s] = acc;
    }
    __syncthreads();
    if (warp != 0) return;
    int s0 = lane, s1 = lane + 32;
    const float NEG = -3.4e38f;
    float x0 = g_mask[b * Sn + s0] ? -100000.0f : ssc[s0];
    float x1 = NEG;
    if (s1 < Sn) x1 = g_mask[b * Sn + s1] ? -100000.0f : ssc[s1];
    float m = fmaxf(x0, x1);
    for (int off = 16; off; off >>= 1) m = fmaxf(m, __shfl_xor_sync(0xffffffffu, m, off));
    float sum = expf(x0 - m) + ((s1 < Sn) ? expf(x1 - m) : 0.0f);
    for (int off = 16; off; off >>= 1) sum += __shfl_xor_sync(0xffffffffu, sum, off);
    float lse = logf(sum);
    float lp0 = x0 - m - lse;
    float lp1 = x1 - m - lse;
    float* prow = probs + ((size_t)b * Ln + l) * Sn;
    prow[s0] = lp0;
    if (s1 < Sn) prow[s1] = lp1;
    float v0 = lp0 + gumbel_from_bits(threefry_xor(key0, key1, 0u, (uint32_t)(b * Sn + s0)));
    float v1 = NEG;
    if (s1 < Sn) v1 = lp1 + gumbel_from_bits(threefry_xor(key0, key1, 0u, (uint32_t)(b * Sn + s1)));
    float bv; int bi;
    if (v1 > v0) { bv = v1; bi = s1; } else { bv = v0; bi = s0; }
    for (int off = 16; off; off >>= 1) {
        float ov = __shfl_xor_sync(0xffffffffu, bv, off);
        int   oi = __shfl_xor_sync(0xffffffffu, bi, off);
        if (ov > bv || (ov == bv && oi < bi)) { bv = ov; bi = oi; }
    }
    if (lane == 0) {
        tour[(size_t)b * Ln + l] = (float)bi;
        g_mask[b * Sn + bi] = 1;
    }
}

// ---------------- host threefry ----------------
static void tf_host(uint32_t k0, uint32_t k1, uint32_t x0, uint32_t x1,
                    uint32_t& o0, uint32_t& o1) {
    uint32_t ks2 = k0 ^ k1 ^ 0x1BD11BDAu;
    x0 += k0; x1 += k1;
    const int ra[4] = {13, 15, 26, 6}, rb[4] = {17, 29, 16, 24};
    auto rl = [](uint32_t v, int d) { return (v << d) | (v >> (32 - d)); };
    for (int i = 0; i < 4; i++) { x0 += x1; x1 = rl(x1, ra[i]); x1 ^= x0; }
    x0 += k1; x1 += ks2 + 1u;
    for (int i = 0; i < 4; i++) { x0 += x1; x1 = rl(x1, rb[i]); x1 ^= x0; }
    x0 += ks2; x1 += k0 + 2u;
    for (int i = 0; i < 4; i++) { x0 += x1; x1 = rl(x1, ra[i]); x1 ^= x0; }
    x0 += k0; x1 += k1 + 3u;
    for (int i = 0; i < 4; i++) { x0 += x1; x1 = rl(x1, rb[i]); x1 ^= x0; }
    x0 += k1; x1 += ks2 + 4u;
    for (int i = 0; i < 4; i++) { x0 += x1; x1 = rl(x1, ra[i]); x1 ^= x0; }
    x0 += ks2; x1 += k0 + 5u;
    o0 = x0; o1 = x1;
}

#define SM_TOTAL 98304

extern "C" void kernel_launch(void* const* d_in, const int* in_sizes, int n_in,
                              void* d_out, int out_size) {
    const int*   input = (const int*)d_in[0];
    const float* emb   = (const float*)d_in[1];
    const float* eWih  = (const float*)d_in[2];
    const float* eWhh  = (const float*)d_in[3];
    const float* ebih  = (const float*)d_in[4];
    const float* ebhh  = (const float*)d_in[5];
    // d_in[6] = dec_Wih (unused: decoder input is always zero)
    const float* dWhh  = (const float*)d_in[7];
    const float* dbih  = (const float*)d_in[8];
    const float* dbhh  = (const float*)d_in[9];
    const float* W1    = (const float*)d_in[10];
    const float* W2    = (const float*)d_in[11];
    const float* vt    = (const float*)d_in[12];

    float* out   = (float*)d_out;
    float* probs = out;                               // [B, L, S]
    float* tour  = out + (size_t)Bn * Ln * Sn;        // [B, L] as float

    cudaFuncSetAttribute(gemm_mma<0>, cudaFuncAttributeMaxDynamicSharedMemorySize, SM_TOTAL);
    cudaFuncSetAttribute(gemm_mma<1>, cudaFuncAttributeMaxDynamicSharedMemorySize, SM_TOTAL);
    cudaFuncSetAttribute(gemm_mma<2>, cudaFuncAttributeMaxDynamicSharedMemorySize, SM_TOTAL);

    __half *p_hhi0, *p_hlo0, *p_hhi1, *p_hlo1, *p_enchi, *p_enclo;
    __half *p_eWhi, *p_eWlo, *p_dWhi, *p_dWlo, *p_W1hi, *p_W1lo;
    float *p_cE, *p_cD, *p_b1, *p_b2, *p_bd2, *p_P;
    cudaGetSymbolAddress((void**)&p_hhi0, g_hhi0);
    cudaGetSymbolAddress((void**)&p_hlo0, g_hlo0);
    cudaGetSymbolAddress((void**)&p_hhi1, g_hhi1);
    cudaGetSymbolAddress((void**)&p_hlo1, g_hlo1);
    cudaGetSymbolAddress((void**)&p_cE, g_cE);
    cudaGetSymbolAddress((void**)&p_cD, g_cD);
    cudaGetSymbolAddress((void**)&p_enchi, g_enchi);
    cudaGetSymbolAddress((void**)&p_enclo, g_enclo);
    cudaGetSymbolAddress((void**)&p_b1, g_blend1);
    cudaGetSymbolAddress((void**)&p_b2, g_blend2);
    cudaGetSymbolAddress((void**)&p_eWhi, g_eWhi);
    cudaGetSymbolAddress((void**)&p_eWlo, g_eWlo);
    cudaGetSymbolAddress((void**)&p_dWhi, g_dWhi);
    cudaGetSymbolAddress((void**)&p_dWlo, g_dWlo);
    cudaGetSymbolAddress((void**)&p_W1hi, g_W1hi);
    cudaGetSymbolAddress((void**)&p_W1lo, g_W1lo);
    cudaGetSymbolAddress((void**)&p_bd2, g_bias_dec2);
    cudaGetSymbolAddress((void**)&p_P, g_P);

    const int BHB = (Bn * Hn + 255) / 256;

    k_prep<<<(ND * Hn + 255) / 256, 256>>>(eWhh, dWhh, dbih, dbhh, W2, W1);
    k_prep_P<<<(Vn * Gn + 255) / 256, 256>>>(emb, eWih, ebih, ebhh);
    k_init<<<BHB, 256>>>();

    // -------- encoder: 50 fused mma GEMM+cell steps (grid 16x16, 2 CTAs/SM) --
    for (int t = 0; t < Sn; t++) {
        __half* ihi = (t & 1) ? p_hhi1 : p_hhi0;
        __half* ilo = (t & 1) ? p_hlo1 : p_hlo0;
        __half* ohi = (t & 1) ? p_hhi0 : p_hhi1;
        __half* olo = (t & 1) ? p_hlo0 : p_hlo1;
        gemm_mma<1><<<dim3(Gn / 128, Bn / 128), 256, SM_TOTAL>>>(
            ihi, ilo, Bn / 16, p_eWhi, p_eWlo, Gn / 8,
            nullptr, p_P, input, nullptr,
            ohi, olo, p_cE, p_enchi, p_enclo, p_cD, t);
    }

    // -------- blend1 = enc_states @ W1^T : [(t*Bn+b)][W] --------
    gemm_mma<0><<<dim3(Wn / 128, BSn / 128), 256, SM_TOTAL>>>(
        p_enchi, p_enclo, BSn / 16, p_W1hi, p_W1lo, Wn / 8,
        nullptr, nullptr, nullptr, p_b1,
        nullptr, nullptr, nullptr, nullptr, nullptr, nullptr, 0);

    // -------- decoder first cell (h_prev = 0), c0 = enc h49 --------
    k_dec0<<<BHB, 256>>>();

    uint32_t K0[Ln], K1[Ln];
    for (int l = 0; l < Ln; l++) tf_host(0u, 42u, 0u, (uint32_t)l, K0[l], K1[l]);

    for (int l = 0; l < Ln; l++) {
        __half* ihi = (l & 1) ? p_hhi1 : p_hhi0;
        __half* ilo = (l & 1) ? p_hlo1 : p_hlo0;
        __half* ohi = (l & 1) ? p_hhi0 : p_hhi1;
        __half* olo = (l & 1) ? p_hlo0 : p_hlo1;
        // grid 18x16 = 288 CTAs resident: blocks x<16 gates, x>=16 blend2
        gemm_mma<2><<<dim3(ND / 128, Bn / 128), 256, SM_TOTAL>>>(
            ihi, ilo, Bn / 16, p_dWhi, p_dWlo, ND / 8,
            p_bd2, nullptr, nullptr, p_b2,
            ohi, olo, p_cD, nullptr, nullptr, nullptr, 0);
        k_attn<<<Bn, 256>>>(vt, l, K0[l], K1[l], probs, tour);
    }
    (void)in_sizes; (void)n_in; (void)out_size;
}

// round 13
// speedup vs baseline: 2.0003x; 1.0052x over previous
#include <cuda_runtime.h>
#include <cuda_fp16.h>
#include <cstdint>
#include <math.h>

// Problem constants
#define Bn 2048
#define Sn 50
#define En 256
#define Hn 512
#define Gn 2048        // 4*H
#define Wn 256
#define Ln 50
#define ND (Gn + Wn)   // 2304 : [interleaved dec gates | W2 rows]
#define Vn 51
#define BSn (Bn * Sn)

// ---------------- device scratch (fp16 fragment-order layouts) ----------------
__device__ __half g_hhi0[Bn * Hn];
__device__ __half g_hlo0[Bn * Hn];
__device__ __half g_hhi1[Bn * Hn];
__device__ __half g_hlo1[Bn * Hn];
__device__ float  g_cE[Bn * Hn];                    // encoder cell state [m][j]
__device__ float  g_cD[Bn * Hn];                    // decoder cell state
__device__ __half g_enchi[(size_t)BSn * Hn];        // enc states, A-frag layout
__device__ __half g_enclo[(size_t)BSn * Hn];
__device__ float  g_blend1[(size_t)BSn * Wn];       // [(t*Bn+b)][w] row-major
__device__ float  g_blend2[2 * Bn * Wn];            // double-buffered by step parity
__device__ unsigned char g_mask[Bn * Sn];
__device__ __half g_eWhi[Gn * Hn];                  // enc Whh, B-frag layout
__device__ __half g_eWlo[Gn * Hn];
__device__ __half g_dWhi[ND * Hn];                  // dec Whh | W2, B-frag layout
__device__ __half g_dWlo[ND * Hn];
__device__ __half g_W1hi[Wn * Hn];
__device__ __half g_W1lo[Wn * Hn];
__device__ float  g_bias_dec2[Gn];
__device__ float  g_P[Vn * Gn];                     // emb@Wih^T + enc bias (fp32 exact)

// ---------------- helpers ----------------
__device__ __forceinline__ float sigf(float x) { return 1.0f / (1.0f + expf(-x)); }

__device__ __forceinline__ void hsplit(float x, __half& hi, __half& lo) {
    hi = __float2half_rn(x);
    lo = __float2half_rn(x - __half2float(hi));
}

__device__ __forceinline__ void cp16(uint32_t dst, const void* src) {
    asm volatile("cp.async.cg.shared.global [%0], [%1], 16;\n" :: "r"(dst), "l"(src));
}

// mma.sync m16n8k16 fp16: D(f32) += A(f16)*B(f16)   (row.col)
#define MMA16(accp, av, bv)                                                \
    asm volatile(                                                          \
        "mma.sync.aligned.m16n8k16.row.col.f32.f16.f16.f32 "               \
        "{%0,%1,%2,%3}, {%4,%5,%6,%7}, {%8,%9}, {%0,%1,%2,%3};"            \
        : "+f"((accp)[0]), "+f"((accp)[1]), "+f"((accp)[2]), "+f"((accp)[3]) \
        : "r"((av).x), "r"((av).y), "r"((av).z), "r"((av).w),              \
          "r"((bv).x), "r"((bv).y))

// A-fragment (m16n8k16 f16) half-element index for A[m][k]
__device__ __forceinline__ size_t afrag(size_t m, int k, int mtiles) {
    int kc = k >> 5, s = (k >> 4) & 1, k16 = k & 15;
    int tt = ((int)(m & 7)) * 4 + ((k16 >> 1) & 3);
    int r = (int)((m >> 3) & 1) + (((k16 >> 3) & 1) << 1);
    return ((((size_t)(kc * 2 + s) * mtiles + (m >> 4)) * 32 + tt) * 4 + r) * 2 + (k16 & 1);
}
// B-fragment (m16n8k16 f16) half-element index for B[n][k]
__device__ __forceinline__ size_t bfrag(int n, int k, int ntiles) {
    int kc = k >> 5, s = (k >> 4) & 1, k16 = k & 15;
    int tt = (n & 7) * 4 + ((k16 >> 1) & 3);
    int r = (k16 >> 3) & 1;
    return ((((size_t)(kc * 2 + s) * ntiles + (n >> 3)) * 32 + tt) * 2 + r) * 2 + (k16 & 1);
}

// ---------------- prep kernels ----------------
__global__ void k_prep(const float* __restrict__ eWhh,
                       const float* __restrict__ dWhh, const float* __restrict__ dbih,
                       const float* __restrict__ dbhh, const float* __restrict__ W2,
                       const float* __restrict__ W1) {
    int idx = blockIdx.x * blockDim.x + threadIdx.x;
    if (idx < Gn * Hn) {
        int n2 = idx / Hn, k = idx % Hn;
        int g = n2 & 3, j = n2 >> 2;
        __half hi, lo;
        hsplit(eWhh[(g * Hn + j) * Hn + k], hi, lo);
        size_t o = bfrag(n2, k, Gn / 8);
        g_eWhi[o] = hi; g_eWlo[o] = lo;
    }
    if (idx < ND * Hn) {
        int n2 = idx / Hn, k = idx % Hn;
        float v;
        if (n2 < Gn) {
            int g = n2 & 3, j = n2 >> 2;
            v = dWhh[(g * Hn + j) * Hn + k];
        } else {
            v = W2[(size_t)(n2 - Gn) * Hn + k];
        }
        __half hi, lo;
        hsplit(v, hi, lo);
        size_t o = bfrag(n2, k, ND / 8);
        g_dWhi[o] = hi; g_dWlo[o] = lo;
    }
    if (idx < Wn * Hn) {
        int w = idx / Hn, k = idx % Hn;
        __half hi, lo;
        hsplit(W1[idx], hi, lo);
        size_t o = bfrag(w, k, Wn / 8);
        g_W1hi[o] = hi; g_W1lo[o] = lo;
    }
    if (idx < Gn) {
        int g = idx & 3, j = idx >> 2;
        int r = g * Hn + j;
        g_bias_dec2[idx] = dbih[r] + dbhh[r];
    }
}

__global__ void k_prep_P(const float* __restrict__ emb, const float* __restrict__ eWih,
                         const float* __restrict__ ebih, const float* __restrict__ ebhh) {
    int idx = blockIdx.x * blockDim.x + threadIdx.x;
    if (idx >= Vn * Gn) return;
    int v = idx / Gn, n2 = idx % Gn;
    int g = n2 & 3, j = n2 >> 2;
    int r = g * Hn + j;
    const float4* e = reinterpret_cast<const float4*>(emb + (size_t)v * En);
    const float4* w = reinterpret_cast<const float4*>(eWih + (size_t)r * En);
    float s = 0.0f;
    #pragma unroll 8
    for (int k = 0; k < En / 4; k++) {
        float4 a = __ldg(e + k), b = __ldg(w + k);
        s += a.x * b.x + a.y * b.y + a.z * b.z + a.w * b.w;
    }
    g_P[idx] = s + ebih[r] + ebhh[r];
}

__global__ void k_init() {
    int idx = blockIdx.x * blockDim.x + threadIdx.x;
    if (idx < Bn * Hn) {
        g_hhi0[idx] = __float2half(0.0f);
        g_hlo0[idx] = __float2half(0.0f);
        g_cE[idx] = 0.0f;
    }
    if (idx < Bn * Sn) g_mask[idx] = 0;
}

// decoder first cell: gates = bias only; c0 already in g_cD (enc h49)
__global__ void k_dec0() {
    int idx = blockIdx.x * blockDim.x + threadIdx.x;
    if (idx >= Bn * Hn) return;
    int b = idx / Hn, j = idx % Hn;
    float gi = g_bias_dec2[4 * j + 0], gf = g_bias_dec2[4 * j + 1];
    float gg = g_bias_dec2[4 * j + 2], go = g_bias_dec2[4 * j + 3];
    float c0 = g_cD[idx];
    float cn = sigf(gf) * c0 + sigf(gi) * tanhf(gg);
    float hn = sigf(go) * tanhf(cn);
    g_cD[idx] = cn;
    __half hi, lo;
    hsplit(hn, hi, lo);
    size_t ao = afrag((size_t)b, j, Bn / 16);
    g_hhi0[ao] = hi; g_hlo0[ao] = lo;
}

// ---------------- fp16 mma.sync GEMM, 3-product split, 128x128 CTA tile -----
// 256 threads, 8 warps (4m x 2n), warp tile 32x64.
// Triple-buffered cp.async (32KB/chunk), one __syncthreads per chunk.
// MODE 0: plain store (blend1)  MODE 1: encoder LSTM  MODE 2: dec LSTM | blend2
template <int MODE>
__global__ __launch_bounds__(256, 2) void gemm_mma(
    const __half* __restrict__ Ahi, const __half* __restrict__ Alo, int Mtiles,
    const __half* __restrict__ Bhi, const __half* __restrict__ Blo, int Ntiles,
    const float* __restrict__ bias2, const float* __restrict__ P,
    const int* __restrict__ tok,
    float* __restrict__ Cout,
    __half* __restrict__ hhi, __half* __restrict__ hlo,
    float* __restrict__ cst,
    __half* __restrict__ enchi, __half* __restrict__ enclo,
    float* __restrict__ cD, int t) {
    extern __shared__ char smem[];
    const int tid = threadIdx.x;
    const int lane = tid & 31, wid = tid >> 5;
    const int bm = blockIdx.y * 128, bn = blockIdx.x * 128;
    const int bm16 = bm >> 4, bn8 = bn >> 3;
    const int mw = wid & 3, nw = wid >> 2;        // mw 0..3 (32 rows), nw 0..1 (64 cols)

    float acc[2][8][4];
#pragma unroll
    for (int i = 0; i < 2; i++)
#pragma unroll
        for (int jn = 0; jn < 8; jn++)
#pragma unroll
            for (int p = 0; p < 4; p++) acc[i][jn][p] = 0.0f;

    // smem per buffer: Ahi 8KB | Alo 8KB | Bhi 8KB | Blo 8KB = 32KB
    auto issue = [&](int c, int buf) {
#pragma unroll
        for (int q = 0; q < 8; q++) {
            int cid = tid + q * 256;              // 2048 x 16B chunks
            int arr = cid >> 9;                   // 0:Ahi 1:Alo 2:Bhi 3:Blo
            int within = cid & 511;
            int s = within >> 8, rest = within & 255;
            const __half* src;
            if (arr < 2) {
                const __half* base = arr ? Alo : Ahi;
                src = base + ((size_t)(c * 2 + s) * Mtiles + bm16) * 256 + rest * 8;
            } else {
                const __half* base = (arr == 2) ? Bhi : Blo;
                src = base + ((size_t)(c * 2 + s) * Ntiles + bn8) * 128 + rest * 8;
            }
            uint32_t dof = (uint32_t)(buf * 32768 + arr * 8192 + within * 16);
            cp16((uint32_t)__cvta_generic_to_shared(smem + dof), src);
        }
        asm volatile("cp.async.commit_group;\n");
    };

    issue(0, 0);
    issue(1, 1);
#pragma unroll 1
    for (int c = 0; c < 16; c++) {
        const int buf = c % 3;
        if (c < 15) { asm volatile("cp.async.wait_group 1;\n"); }
        else        { asm volatile("cp.async.wait_group 0;\n"); }
        __syncthreads();
        if (c + 2 < 16) issue(c + 2, (c + 2) % 3);
#pragma unroll
        for (int s = 0; s < 2; s++) {
            uint4 ah[2], al[2];
#pragma unroll
            for (int mt = 0; mt < 2; mt++) {
                int moff = buf * 32768 + s * 4096 + (mw * 2 + mt) * 512 + lane * 16;
                ah[mt] = *reinterpret_cast<const uint4*>(smem + moff);
                al[mt] = *reinterpret_cast<const uint4*>(smem + moff + 8192);
            }
            uint2 bh[8], bl[8];
#pragma unroll
            for (int nt = 0; nt < 8; nt++) {
                int boff = buf * 32768 + 16384 + s * 4096 + (nw * 8 + nt) * 256 + lane * 8;
                bh[nt] = *reinterpret_cast<const uint2*>(smem + boff);
                bl[nt] = *reinterpret_cast<const uint2*>(smem + boff + 8192);
            }
            // product-major: same-acc reuse distance = 16 MMAs
#pragma unroll
            for (int nt = 0; nt < 8; nt++) {
                MMA16(acc[0][nt], ah[0], bh[nt]);
                MMA16(acc[1][nt], ah[1], bh[nt]);
            }
#pragma unroll
            for (int nt = 0; nt < 8; nt++) {
                MMA16(acc[0][nt], ah[0], bl[nt]);
                MMA16(acc[1][nt], ah[1], bl[nt]);
            }
#pragma unroll
            for (int nt = 0; nt < 8; nt++) {
                MMA16(acc[0][nt], al[0], bh[nt]);
                MMA16(acc[1][nt], al[1], bh[nt]);
                // lo*lo dropped: 2^-22 class, validated in R9/R10
            }
        }
    }

    // ---------------- epilogue ----------------
    if (MODE == 0 || (MODE == 2 && bn >= Gn)) {
#pragma unroll
        for (int mt = 0; mt < 2; mt++)
#pragma unroll
            for (int nt = 0; nt < 8; nt++) {
                int row = bm + mw * 32 + mt * 16 + (lane >> 2);
                int col = bn + nw * 64 + nt * 8 + (lane & 3) * 2;
                if (MODE == 2) col -= Gn;
                float* dst = Cout + (size_t)row * Wn + col;
                *reinterpret_cast<float2*>(dst) =
                    make_float2(acc[mt][nt][0], acc[mt][nt][1]);
                *reinterpret_cast<float2*>(dst + 8 * Wn) =
                    make_float2(acc[mt][nt][2], acc[mt][nt][3]);
            }
    } else {
        float* gsm = reinterpret_cast<float*>(smem);
        __syncthreads();   // all warps done reading smem buffers before reuse
#pragma unroll
        for (int mt = 0; mt < 2; mt++)
#pragma unroll
            for (int nt = 0; nt < 8; nt++) {
                int rl = mw * 32 + mt * 16 + (lane >> 2);
                int cl = nw * 64 + nt * 8 + (lane & 3) * 2;
                *reinterpret_cast<float2*>(&gsm[rl * 132 + cl]) =
                    make_float2(acc[mt][nt][0], acc[mt][nt][1]);
                *reinterpret_cast<float2*>(&gsm[(rl + 8) * 132 + cl]) =
                    make_float2(acc[mt][nt][2], acc[mt][nt][3]);
            }
        __syncthreads();
#pragma unroll 1
        for (int q = 0; q < 16; q++) {
            int idx = q * 256 + tid;
            int ml = idx >> 5, j4 = idx & 31;
            float4 gv = *reinterpret_cast<const float4*>(&gsm[ml * 132 + j4 * 4]);
            int mrow = bm + ml;
            int n = bn + j4 * 4;
            int j = n >> 2;
            float g0 = gv.x, g1 = gv.y, g2 = gv.z, g3 = gv.w;
            if (MODE == 1) {
                int tokv = tok[mrow * Sn + t];
                float4 pv = *reinterpret_cast<const float4*>(P + (size_t)tokv * Gn + n);
                g0 += pv.x; g1 += pv.y; g2 += pv.z; g3 += pv.w;
            } else {
                float4 bv = *reinterpret_cast<const float4*>(bias2 + n);
                g0 += bv.x; g1 += bv.y; g2 += bv.z; g3 += bv.w;
            }
            float co = cst[mrow * Hn + j];
            float cn = sigf(g1) * co + sigf(g0) * tanhf(g2);
            float hn = sigf(g3) * tanhf(cn);
            cst[mrow * Hn + j] = cn;
            __half hi, lo;
            hsplit(hn, hi, lo);
            size_t ao = afrag((size_t)mrow, j, Bn / 16);
            hhi[ao] = hi; hlo[ao] = lo;
            if (MODE == 1) {
                size_t er = (size_t)t * Bn + mrow;
                size_t eo = afrag(er, j, BSn / 16);
                enchi[eo] = hi; enclo[eo] = lo;
                if (t == Sn - 1) cD[mrow * Hn + j] = hn;
            }
        }
    }
}

// ---------------- threefry2x32 (JAX-compatible) ----------------
__device__ __forceinline__ uint32_t rotl32(uint32_t v, int d) { return (v << d) | (v >> (32 - d)); }

__device__ uint32_t threefry_xor(uint32_t k0, uint32_t k1, uint32_t x0, uint32_t x1) {
    uint32_t ks2 = k0 ^ k1 ^ 0x1BD11BDAu;
    x0 += k0; x1 += k1;
    const int ra[4] = {13, 15, 26, 6}, rb[4] = {17, 29, 16, 24};
#pragma unroll
    for (int i = 0; i < 4; i++) { x0 += x1; x1 = rotl32(x1, ra[i]); x1 ^= x0; }
    x0 += k1; x1 += ks2 + 1u;
#pragma unroll
    for (int i = 0; i < 4; i++) { x0 += x1; x1 = rotl32(x1, rb[i]); x1 ^= x0; }
    x0 += ks2; x1 += k0 + 2u;
#pragma unroll
    for (int i = 0; i < 4; i++) { x0 += x1; x1 = rotl32(x1, ra[i]); x1 ^= x0; }
    x0 += k0; x1 += k1 + 3u;
#pragma unroll
    for (int i = 0; i < 4; i++) { x0 += x1; x1 = rotl32(x1, rb[i]); x1 ^= x0; }
    x0 += k1; x1 += ks2 + 4u;
#pragma unroll
    for (int i = 0; i < 4; i++) { x0 += x1; x1 = rotl32(x1, ra[i]); x1 ^= x0; }
    x0 += ks2; x1 += k0 + 5u;
    return x0 ^ x1;  // partitionable 32-bit random_bits = out0 ^ out1
}

__device__ __forceinline__ float gumbel_from_bits(uint32_t bits) {
    const float TINY = 1.17549435e-38f;
    float f = __uint_as_float((bits >> 9) | 0x3f800000u) - 1.0f;
    float u = f * (1.0f - TINY) + TINY;
    u = fmaxf(TINY, u);
    return -logf(-logf(u));
}

// ---------------- fused scores + masked log-softmax + sample ----------------
__global__ void k_attn(const float* __restrict__ b2, const float* __restrict__ vt,
                       int l, uint32_t key0, uint32_t key1,
                       float* __restrict__ probs, float* __restrict__ tour) {
    int b = blockIdx.x, tid = threadIdx.x;  // 256 threads
    __shared__ float sb[Wn], sv[Wn], ssc[64];
    sb[tid] = b2[b * Wn + tid];
    sv[tid] = vt[tid];
    __syncthreads();
    int warp = tid >> 5, lane = tid & 31;
    for (int s = warp; s < Sn; s += 8) {
        const float* row = g_blend1 + ((size_t)s * Bn + b) * Wn;
        float acc = 0.0f;
#pragma unroll
        for (int q = 0; q < 8; q++) {
            int w = lane + q * 32;
            acc += tanhf(row[w] + sb[w]) * sv[w];
        }
        for (int off = 16; off; off >>= 1) acc += __shfl_xor_sync(0xffffffffu, acc, off);
        if (lane == 0) ssc[s] = acc;
    }
    __syncthreads();
    if (warp != 0) return;
    int s0 = lane, s1 = lane + 32;
    const float NEG = -3.4e38f;
    float x0 = g_mask[b * Sn + s0] ? -100000.0f : ssc[s0];
    float x1 = NEG;
    if (s1 < Sn) x1 = g_mask[b * Sn + s1] ? -100000.0f : ssc[s1];
    float m = fmaxf(x0, x1);
    for (int off = 16; off; off >>= 1) m = fmaxf(m, __shfl_xor_sync(0xffffffffu, m, off));
    float sum = expf(x0 - m) + ((s1 < Sn) ? expf(x1 - m) : 0.0f);
    for (int off = 16; off; off >>= 1) sum += __shfl_xor_sync(0xffffffffu, sum, off);
    float lse = logf(sum);
    float lp0 = x0 - m - lse;
    float lp1 = x1 - m - lse;
    float* prow = probs + ((size_t)b * Ln + l) * Sn;
    prow[s0] = lp0;
    if (s1 < Sn) prow[s1] = lp1;
    float v0 = lp0 + gumbel_from_bits(threefry_xor(key0, key1, 0u, (uint32_t)(b * Sn + s0)));
    float v1 = NEG;
    if (s1 < Sn) v1 = lp1 + gumbel_from_bits(threefry_xor(key0, key1, 0u, (uint32_t)(b * Sn + s1)));
    float bv; int bi;
    if (v1 > v0) { bv = v1; bi = s1; } else { bv = v0; bi = s0; }
    for (int off = 16; off; off >>= 1) {
        float ov = __shfl_xor_sync(0xffffffffu, bv, off);
        int   oi = __shfl_xor_sync(0xffffffffu, bi, off);
        if (ov > bv || (ov == bv && oi < bi)) { bv = ov; bi = oi; }
    }
    if (lane == 0) {
        tour[(size_t)b * Ln + l] = (float)bi;
        g_mask[b * Sn + bi] = 1;
    }
}

// ---------------- host threefry ----------------
static void tf_host(uint32_t k0, uint32_t k1, uint32_t x0, uint32_t x1,
                    uint32_t& o0, uint32_t& o1) {
    uint32_t ks2 = k0 ^ k1 ^ 0x1BD11BDAu;
    x0 += k0; x1 += k1;
    const int ra[4] = {13, 15, 26, 6}, rb[4] = {17, 29, 16, 24};
    auto rl = [](uint32_t v, int d) { return (v << d) | (v >> (32 - d)); };
    for (int i = 0; i < 4; i++) { x0 += x1; x1 = rl(x1, ra[i]); x1 ^= x0; }
    x0 += k1; x1 += ks2 + 1u;
    for (int i = 0; i < 4; i++) { x0 += x1; x1 = rl(x1, rb[i]); x1 ^= x0; }
    x0 += ks2; x1 += k0 + 2u;
    for (int i = 0; i < 4; i++) { x0 += x1; x1 = rl(x1, ra[i]); x1 ^= x0; }
    x0 += k0; x1 += k1 + 3u;
    for (int i = 0; i < 4; i++) { x0 += x1; x1 = rl(x1, rb[i]); x1 ^= x0; }
    x0 += k1; x1 += ks2 + 4u;
    for (int i = 0; i < 4; i++) { x0 += x1; x1 = rl(x1, ra[i]); x1 ^= x0; }
    x0 += ks2; x1 += k0 + 5u;
    o0 = x0; o1 = x1;
}

#define SM_TOTAL 98304

extern "C" void kernel_launch(void* const* d_in, const int* in_sizes, int n_in,
                              void* d_out, int out_size) {
    const int*   input = (const int*)d_in[0];
    const float* emb   = (const float*)d_in[1];
    const float* eWih  = (const float*)d_in[2];
    const float* eWhh  = (const float*)d_in[3];
    const float* ebih  = (const float*)d_in[4];
    const float* ebhh  = (const float*)d_in[5];
    // d_in[6] = dec_Wih (unused: decoder input is always zero)
    const float* dWhh  = (const float*)d_in[7];
    const float* dbih  = (const float*)d_in[8];
    const float* dbhh  = (const float*)d_in[9];
    const float* W1    = (const float*)d_in[10];
    const float* W2    = (const float*)d_in[11];
    const float* vt    = (const float*)d_in[12];

    float* out   = (float*)d_out;
    float* probs = out;                               // [B, L, S]
    float* tour  = out + (size_t)Bn * Ln * Sn;        // [B, L] as float

    // one-time host-side objects (no device memory)
    static cudaStream_t s1 = nullptr;
    static cudaEvent_t evF, evG[Ln], evA[Ln];
    if (!s1) {
        cudaStreamCreateWithFlags(&s1, cudaStreamNonBlocking);
        cudaEventCreateWithFlags(&evF, cudaEventDisableTiming);
        for (int l = 0; l < Ln; l++) {
            cudaEventCreateWithFlags(&evG[l], cudaEventDisableTiming);
            cudaEventCreateWithFlags(&evA[l], cudaEventDisableTiming);
        }
        cudaFuncSetAttribute(gemm_mma<0>, cudaFuncAttributeMaxDynamicSharedMemorySize, SM_TOTAL);
        cudaFuncSetAttribute(gemm_mma<1>, cudaFuncAttributeMaxDynamicSharedMemorySize, SM_TOTAL);
        cudaFuncSetAttribute(gemm_mma<2>, cudaFuncAttributeMaxDynamicSharedMemorySize, SM_TOTAL);
    }

    __half *p_hhi0, *p_hlo0, *p_hhi1, *p_hlo1, *p_enchi, *p_enclo;
    __half *p_eWhi, *p_eWlo, *p_dWhi, *p_dWlo, *p_W1hi, *p_W1lo;
    float *p_cE, *p_cD, *p_b1, *p_b2, *p_bd2, *p_P;
    cudaGetSymbolAddress((void**)&p_hhi0, g_hhi0);
    cudaGetSymbolAddress((void**)&p_hlo0, g_hlo0);
    cudaGetSymbolAddress((void**)&p_hhi1, g_hhi1);
    cudaGetSymbolAddress((void**)&p_hlo1, g_hlo1);
    cudaGetSymbolAddress((void**)&p_cE, g_cE);
    cudaGetSymbolAddress((void**)&p_cD, g_cD);
    cudaGetSymbolAddress((void**)&p_enchi, g_enchi);
    cudaGetSymbolAddress((void**)&p_enclo, g_enclo);
    cudaGetSymbolAddress((void**)&p_b1, g_blend1);
    cudaGetSymbolAddress((void**)&p_b2, g_blend2);
    cudaGetSymbolAddress((void**)&p_eWhi, g_eWhi);
    cudaGetSymbolAddress((void**)&p_eWlo, g_eWlo);
    cudaGetSymbolAddress((void**)&p_dWhi, g_dWhi);
    cudaGetSymbolAddress((void**)&p_dWlo, g_dWlo);
    cudaGetSymbolAddress((void**)&p_W1hi, g_W1hi);
    cudaGetSymbolAddress((void**)&p_W1lo, g_W1lo);
    cudaGetSymbolAddress((void**)&p_bd2, g_bias_dec2);
    cudaGetSymbolAddress((void**)&p_P, g_P);

    const int BHB = (Bn * Hn + 255) / 256;

    k_prep<<<(ND * Hn + 255) / 256, 256>>>(eWhh, dWhh, dbih, dbhh, W2, W1);
    k_prep_P<<<(Vn * Gn + 255) / 256, 256>>>(emb, eWih, ebih, ebhh);
    k_init<<<BHB, 256>>>();

    // -------- encoder: 50 fused mma GEMM+cell steps --------
    for (int t = 0; t < Sn; t++) {
        __half* ihi = (t & 1) ? p_hhi1 : p_hhi0;
        __half* ilo = (t & 1) ? p_hlo1 : p_hlo0;
        __half* ohi = (t & 1) ? p_hhi0 : p_hhi1;
        __half* olo = (t & 1) ? p_hlo0 : p_hlo1;
        gemm_mma<1><<<dim3(Gn / 128, Bn / 128), 256, SM_TOTAL>>>(
            ihi, ilo, Bn / 16, p_eWhi, p_eWlo, Gn / 8,
            nullptr, p_P, input, nullptr,
            ohi, olo, p_cE, p_enchi, p_enclo, p_cD, t);
    }

    // -------- fork: blend1 + attn chain run on s1, decoder chain on s0 ------
    cudaEventRecord(evF, 0);
    cudaStreamWaitEvent(s1, evF, 0);

    // blend1 = enc_states @ W1^T  (independent of decoder h-chain)
    gemm_mma<0><<<dim3(Wn / 128, BSn / 128), 256, SM_TOTAL, s1>>>(
        p_enchi, p_enclo, BSn / 16, p_W1hi, p_W1lo, Wn / 8,
        nullptr, nullptr, nullptr, p_b1,
        nullptr, nullptr, nullptr, nullptr, nullptr, nullptr, 0);

    // decoder first cell (h_prev = 0), c0 = enc h49
    k_dec0<<<BHB, 256>>>();

    uint32_t K0[Ln], K1[Ln];
    for (int l = 0; l < Ln; l++) tf_host(0u, 42u, 0u, (uint32_t)l, K0[l], K1[l]);

    for (int l = 0; l < Ln; l++) {
        __half* ihi = (l & 1) ? p_hhi1 : p_hhi0;
        __half* ilo = (l & 1) ? p_hlo1 : p_hlo0;
        __half* ohi = (l & 1) ? p_hhi0 : p_hhi1;
        __half* olo = (l & 1) ? p_hlo0 : p_hlo1;
        float* b2buf = p_b2 + (size_t)(l & 1) * Bn * Wn;
        // blend2 parity buffer reused every 2 steps: wait for attn_{l-2}
        if (l >= 2) cudaStreamWaitEvent(0, evA[l - 2], 0);
        gemm_mma<2><<<dim3(ND / 128, Bn / 128), 256, SM_TOTAL>>>(
            ihi, ilo, Bn / 16, p_dWhi, p_dWlo, ND / 8,
            p_bd2, nullptr, nullptr, b2buf,
            ohi, olo, p_cD, nullptr, nullptr, nullptr, 0);
        cudaEventRecord(evG[l], 0);
        cudaStreamWaitEvent(s1, evG[l], 0);
        k_attn<<<Bn, 256, 0, s1>>>(b2buf, vt, l, K0[l], K1[l], probs, tour);
        cudaEventRecord(evA[l], s1);
    }
    // join: main stream waits for the last attn
    cudaStreamWaitEvent(0, evA[Ln - 1], 0);
    (void)in_sizes; (void)n_in; (void)out_size;
}

// round 15
// speedup vs baseline: 2.4211x; 1.2104x over previous
#include <cuda_runtime.h>
#include <cuda_fp16.h>
#include <cstdint>
#include <math.h>

// Problem constants
#define Bn 2048
#define Sn 50
#define En 256
#define Hn 512
#define Gn 2048        // 4*H
#define Wn 256
#define Ln 50
#define ND (Gn + Wn)   // 2304 : [interleaved dec gates | W2 rows]
#define Vn 51
#define BSn (Bn * Sn)

// ---------------- device scratch (fp16 fragment-order layouts) ----------------
__device__ __half g_hhi0[Bn * Hn];
__device__ __half g_hlo0[Bn * Hn];
__device__ __half g_hhi1[Bn * Hn];
__device__ __half g_hlo1[Bn * Hn];
__device__ float  g_cE[Bn * Hn];                    // encoder cell state [m][j]
__device__ float  g_cD[Bn * Hn];                    // decoder cell state
__device__ __half g_enchi[(size_t)BSn * Hn];        // enc states, A-frag layout
__device__ __half g_enclo[(size_t)BSn * Hn];
__device__ float  g_blend1[(size_t)BSn * Wn];       // [(t*Bn+b)][w] row-major
__device__ float  g_blend2[2 * Bn * Wn];            // double-buffered by step parity
__device__ unsigned char g_mask[Bn * Sn];
__device__ __half g_eWhi[Gn * Hn];                  // enc Whh, B-frag layout
__device__ __half g_eWlo[Gn * Hn];
__device__ __half g_dWhi[ND * Hn];                  // dec Whh | W2, B-frag layout
__device__ __half g_dWlo[ND * Hn];
__device__ __half g_W1hi[Wn * Hn];
__device__ __half g_W1lo[Wn * Hn];
__device__ float  g_bias_dec2[Gn];
__device__ float  g_P[Vn * Gn];                     // emb@Wih^T + enc bias (fp32 exact)

// ---------------- helpers ----------------
__device__ __forceinline__ float sigf(float x) { return 1.0f / (1.0f + expf(-x)); }

__device__ __forceinline__ void hsplit(float x, __half& hi, __half& lo) {
    hi = __float2half_rn(x);
    lo = __float2half_rn(x - __half2float(hi));
}

__device__ __forceinline__ void cp16(uint32_t dst, const void* src) {
    asm volatile("cp.async.cg.shared.global [%0], [%1], 16;\n" :: "r"(dst), "l"(src));
}

// mma.sync m16n8k16 fp16: D(f32) += A(f16)*B(f16)   (row.col)
#define MMA16(accp, av, bv)                                                \
    asm volatile(                                                          \
        "mma.sync.aligned.m16n8k16.row.col.f32.f16.f16.f32 "               \
        "{%0,%1,%2,%3}, {%4,%5,%6,%7}, {%8,%9}, {%0,%1,%2,%3};"            \
        : "+f"((accp)[0]), "+f"((accp)[1]), "+f"((accp)[2]), "+f"((accp)[3]) \
        : "r"((av).x), "r"((av).y), "r"((av).z), "r"((av).w),              \
          "r"((bv).x), "r"((bv).y))

// A-fragment (m16n8k16 f16) half-element index for A[m][k]
__device__ __forceinline__ size_t afrag(size_t m, int k, int mtiles) {
    int kc = k >> 5, s = (k >> 4) & 1, k16 = k & 15;
    int tt = ((int)(m & 7)) * 4 + ((k16 >> 1) & 3);
    int r = (int)((m >> 3) & 1) + (((k16 >> 3) & 1) << 1);
    return ((((size_t)(kc * 2 + s) * mtiles + (m >> 4)) * 32 + tt) * 4 + r) * 2 + (k16 & 1);
}
// B-fragment (m16n8k16 f16) half-element index for B[n][k]
__device__ __forceinline__ size_t bfrag(int n, int k, int ntiles) {
    int kc = k >> 5, s = (k >> 4) & 1, k16 = k & 15;
    int tt = (n & 7) * 4 + ((k16 >> 1) & 3);
    int r = (k16 >> 3) & 1;
    return ((((size_t)(kc * 2 + s) * ntiles + (n >> 3)) * 32 + tt) * 2 + r) * 2 + (k16 & 1);
}

// ---------------- prep kernels ----------------
__global__ void k_prep(const float* __restrict__ eWhh,
                       const float* __restrict__ dWhh, const float* __restrict__ dbih,
                       const float* __restrict__ dbhh, const float* __restrict__ W2,
                       const float* __restrict__ W1) {
    int idx = blockIdx.x * blockDim.x + threadIdx.x;
    if (idx < Gn * Hn) {
        int n2 = idx / Hn, k = idx % Hn;
        int g = n2 & 3, j = n2 >> 2;
        __half hi, lo;
        hsplit(eWhh[(g * Hn + j) * Hn + k], hi, lo);
        size_t o = bfrag(n2, k, Gn / 8);
        g_eWhi[o] = hi; g_eWlo[o] = lo;
    }
    if (idx < ND * Hn) {
        int n2 = idx / Hn, k = idx % Hn;
        float v;
        if (n2 < Gn) {
            int g = n2 & 3, j = n2 >> 2;
            v = dWhh[(g * Hn + j) * Hn + k];
        } else {
            v = W2[(size_t)(n2 - Gn) * Hn + k];
        }
        __half hi, lo;
        hsplit(v, hi, lo);
        size_t o = bfrag(n2, k, ND / 8);
        g_dWhi[o] = hi; g_dWlo[o] = lo;
    }
    if (idx < Wn * Hn) {
        int w = idx / Hn, k = idx % Hn;
        __half hi, lo;
        hsplit(W1[idx], hi, lo);
        size_t o = bfrag(w, k, Wn / 8);
        g_W1hi[o] = hi; g_W1lo[o] = lo;
    }
    if (idx < Gn) {
        int g = idx & 3, j = idx >> 2;
        int r = g * Hn + j;
        g_bias_dec2[idx] = dbih[r] + dbhh[r];
    }
}

__global__ void k_prep_P(const float* __restrict__ emb, const float* __restrict__ eWih,
                         const float* __restrict__ ebih, const float* __restrict__ ebhh) {
    int idx = blockIdx.x * blockDim.x + threadIdx.x;
    if (idx >= Vn * Gn) return;
    int v = idx / Gn, n2 = idx % Gn;
    int g = n2 & 3, j = n2 >> 2;
    int r = g * Hn + j;
    const float4* e = reinterpret_cast<const float4*>(emb + (size_t)v * En);
    const float4* w = reinterpret_cast<const float4*>(eWih + (size_t)r * En);
    float s = 0.0f;
    #pragma unroll 8
    for (int k = 0; k < En / 4; k++) {
        float4 a = __ldg(e + k), b = __ldg(w + k);
        s += a.x * b.x + a.y * b.y + a.z * b.z + a.w * b.w;
    }
    g_P[idx] = s + ebih[r] + ebhh[r];
}

__global__ void k_init() {
    int idx = blockIdx.x * blockDim.x + threadIdx.x;
    if (idx < Bn * Hn) {
        g_hhi0[idx] = __float2half(0.0f);
        g_hlo0[idx] = __float2half(0.0f);
        g_cE[idx] = 0.0f;
    }
    if (idx < Bn * Sn) g_mask[idx] = 0;
}

// decoder first cell: gates = bias only; c0 already in g_cD (enc h49)
__global__ void k_dec0() {
    int idx = blockIdx.x * blockDim.x + threadIdx.x;
    if (idx >= Bn * Hn) return;
    int b = idx / Hn, j = idx % Hn;
    float gi = g_bias_dec2[4 * j + 0], gf = g_bias_dec2[4 * j + 1];
    float gg = g_bias_dec2[4 * j + 2], go = g_bias_dec2[4 * j + 3];
    float c0 = g_cD[idx];
    float cn = sigf(gf) * c0 + sigf(gi) * tanhf(gg);
    float hn = sigf(go) * tanhf(cn);
    g_cD[idx] = cn;
    __half hi, lo;
    hsplit(hn, hi, lo);
    size_t ao = afrag((size_t)b, j, Bn / 16);
    g_hhi0[ao] = hi; g_hlo0[ao] = lo;
}

// ---------------- fp16 mma.sync GEMM, 3-product split, 128x128 CTA tile -----
// 256 threads, 8 warps (4m x 2n), warp tile 32x64.
// Triple-buffered cp.async (32KB/chunk), one __syncthreads per chunk.
// MODE 0: plain store (blend1 slice; t = global row offset)
// MODE 1: encoder LSTM   MODE 2: dec LSTM | blend2
template <int MODE>
__global__ __launch_bounds__(256, 2) void gemm_mma(
    const __half* __restrict__ Ahi, const __half* __restrict__ Alo, int Mtiles,
    const __half* __restrict__ Bhi, const __half* __restrict__ Blo, int Ntiles,
    const float* __restrict__ bias2, const float* __restrict__ P,
    const int* __restrict__ tok,
    float* __restrict__ Cout,
    __half* __restrict__ hhi, __half* __restrict__ hlo,
    float* __restrict__ cst,
    __half* __restrict__ enchi, __half* __restrict__ enclo,
    float* __restrict__ cD, int t) {
    extern __shared__ char smem[];
    const int tid = threadIdx.x;
    const int lane = tid & 31, wid = tid >> 5;
    const int bm = blockIdx.y * 128 + (MODE == 0 ? t : 0);  // MODE0: t = row offset
    const int bn = blockIdx.x * 128;
    const int bm16 = bm >> 4, bn8 = bn >> 3;
    const int mw = wid & 3, nw = wid >> 2;        // mw 0..3 (32 rows), nw 0..1 (64 cols)

    float acc[2][8][4];
#pragma unroll
    for (int i = 0; i < 2; i++)
#pragma unroll
        for (int jn = 0; jn < 8; jn++)
#pragma unroll
            for (int p = 0; p < 4; p++) acc[i][jn][p] = 0.0f;

    // smem per buffer: Ahi 8KB | Alo 8KB | Bhi 8KB | Blo 8KB = 32KB
    auto issue = [&](int c, int buf) {
#pragma unroll
        for (int q = 0; q < 8; q++) {
            int cid = tid + q * 256;              // 2048 x 16B chunks
            int arr = cid >> 9;                   // 0:Ahi 1:Alo 2:Bhi 3:Blo
            int within = cid & 511;
            int s = within >> 8, rest = within & 255;
            const __half* src;
            if (arr < 2) {
                const __half* base = arr ? Alo : Ahi;
                src = base + ((size_t)(c * 2 + s) * Mtiles + bm16) * 256 + rest * 8;
            } else {
                const __half* base = (arr == 2) ? Bhi : Blo;
                src = base + ((size_t)(c * 2 + s) * Ntiles + bn8) * 128 + rest * 8;
            }
            uint32_t dof = (uint32_t)(buf * 32768 + arr * 8192 + within * 16);
            cp16((uint32_t)__cvta_generic_to_shared(smem + dof), src);
        }
        asm volatile("cp.async.commit_group;\n");
    };

    issue(0, 0);
    issue(1, 1);
#pragma unroll 1
    for (int c = 0; c < 16; c++) {
        const int buf = c % 3;
        if (c < 15) { asm volatile("cp.async.wait_group 1;\n"); }
        else        { asm volatile("cp.async.wait_group 0;\n"); }
        __syncthreads();
        if (c + 2 < 16) issue(c + 2, (c + 2) % 3);
#pragma unroll
        for (int s = 0; s < 2; s++) {
            uint4 ah[2], al[2];
#pragma unroll
            for (int mt = 0; mt < 2; mt++) {
                int moff = buf * 32768 + s * 4096 + (mw * 2 + mt) * 512 + lane * 16;
                ah[mt] = *reinterpret_cast<const uint4*>(smem + moff);
                al[mt] = *reinterpret_cast<const uint4*>(smem + moff + 8192);
            }
            uint2 bh[8], bl[8];
#pragma unroll
            for (int nt = 0; nt < 8; nt++) {
                int boff = buf * 32768 + 16384 + s * 4096 + (nw * 8 + nt) * 256 + lane * 8;
                bh[nt] = *reinterpret_cast<const uint2*>(smem + boff);
                bl[nt] = *reinterpret_cast<const uint2*>(smem + boff + 8192);
            }
            // product-major: same-acc reuse distance = 16 MMAs
#pragma unroll
            for (int nt = 0; nt < 8; nt++) {
                MMA16(acc[0][nt], ah[0], bh[nt]);
                MMA16(acc[1][nt], ah[1], bh[nt]);
            }
#pragma unroll
            for (int nt = 0; nt < 8; nt++) {
                MMA16(acc[0][nt], ah[0], bl[nt]);
                MMA16(acc[1][nt], ah[1], bl[nt]);
            }
#pragma unroll
            for (int nt = 0; nt < 8; nt++) {
                MMA16(acc[0][nt], al[0], bh[nt]);
                MMA16(acc[1][nt], al[1], bh[nt]);
                // lo*lo dropped: 2^-22 class, validated in R9/R10
            }
        }
    }

    // ---------------- epilogue ----------------
    if (MODE == 0 || (MODE == 2 && bn >= Gn)) {
#pragma unroll
        for (int mt = 0; mt < 2; mt++)
#pragma unroll
            for (int nt = 0; nt < 8; nt++) {
                int row = bm + mw * 32 + mt * 16 + (lane >> 2);
                int col = bn + nw * 64 + nt * 8 + (lane & 3) * 2;
                if (MODE == 2) col -= Gn;
                float* dst = Cout + (size_t)row * Wn + col;
                *reinterpret_cast<float2*>(dst) =
                    make_float2(acc[mt][nt][0], acc[mt][nt][1]);
                *reinterpret_cast<float2*>(dst + 8 * Wn) =
                    make_float2(acc[mt][nt][2], acc[mt][nt][3]);
            }
    } else {
        float* gsm = reinterpret_cast<float*>(smem);
        __syncthreads();   // all warps done reading smem buffers before reuse
#pragma unroll
        for (int mt = 0; mt < 2; mt++)
#pragma unroll
            for (int nt = 0; nt < 8; nt++) {
                int rl = mw * 32 + mt * 16 + (lane >> 2);
                int cl = nw * 64 + nt * 8 + (lane & 3) * 2;
                *reinterpret_cast<float2*>(&gsm[rl * 132 + cl]) =
                    make_float2(acc[mt][nt][0], acc[mt][nt][1]);
                *reinterpret_cast<float2*>(&gsm[(rl + 8) * 132 + cl]) =
                    make_float2(acc[mt][nt][2], acc[mt][nt][3]);
            }
        __syncthreads();
#pragma unroll 1
        for (int q = 0; q < 16; q++) {
            int idx = q * 256 + tid;
            int ml = idx >> 5, j4 = idx & 31;
            float4 gv = *reinterpret_cast<const float4*>(&gsm[ml * 132 + j4 * 4]);
            int mrow = bm + ml;
            int n = bn + j4 * 4;
            int j = n >> 2;
            float g0 = gv.x, g1 = gv.y, g2 = gv.z, g3 = gv.w;
            if (MODE == 1) {
                int tokv = tok[mrow * Sn + t];
                float4 pv = *reinterpret_cast<const float4*>(P + (size_t)tokv * Gn + n);
                g0 += pv.x; g1 += pv.y; g2 += pv.z; g3 += pv.w;
            } else {
                float4 bv = *reinterpret_cast<const float4*>(bias2 + n);
                g0 += bv.x; g1 += bv.y; g2 += bv.z; g3 += bv.w;
            }
            float co = cst[mrow * Hn + j];
            float cn = sigf(g1) * co + sigf(g0) * tanhf(g2);
            float hn = sigf(g3) * tanhf(cn);
            cst[mrow * Hn + j] = cn;
            __half hi, lo;
            hsplit(hn, hi, lo);
            size_t ao = afrag((size_t)mrow, j, Bn / 16);
            hhi[ao] = hi; hlo[ao] = lo;
            if (MODE == 1) {
                size_t er = (size_t)t * Bn + mrow;
                size_t eo = afrag(er, j, BSn / 16);
                enchi[eo] = hi; enclo[eo] = lo;
                if (t == Sn - 1) cD[mrow * Hn + j] = hn;
            }
        }
    }
}

// ---------------- threefry2x32 (JAX-compatible) ----------------
__device__ __forceinline__ uint32_t rotl32(uint32_t v, int d) { return (v << d) | (v >> (32 - d)); }

__device__ uint32_t threefry_xor(uint32_t k0, uint32_t k1, uint32_t x0, uint32_t x1) {
    uint32_t ks2 = k0 ^ k1 ^ 0x1BD11BDAu;
    x0 += k0; x1 += k1;
    const int ra[4] = {13, 15, 26, 6}, rb[4] = {17, 29, 16, 24};
#pragma unroll
    for (int i = 0; i < 4; i++) { x0 += x1; x1 = rotl32(x1, ra[i]); x1 ^= x0; }
    x0 += k1; x1 += ks2 + 1u;
#pragma unroll
    for (int i = 0; i < 4; i++) { x0 += x1; x1 = rotl32(x1, rb[i]); x1 ^= x0; }
    x0 += ks2; x1 += k0 + 2u;
#pragma unroll
    for (int i = 0; i < 4; i++) { x0 += x1; x1 = rotl32(x1, ra[i]); x1 ^= x0; }
    x0 += k0; x1 += k1 + 3u;
#pragma unroll
    for (int i = 0; i < 4; i++) { x0 += x1; x1 = rotl32(x1, rb[i]); x1 ^= x0; }
    x0 += k1; x1 += ks2 + 4u;
#pragma unroll
    for (int i = 0; i < 4; i++) { x0 += x1; x1 = rotl32(x1, ra[i]); x1 ^= x0; }
    x0 += ks2; x1 += k0 + 5u;
    return x0 ^ x1;  // partitionable 32-bit random_bits = out0 ^ out1
}

__device__ __forceinline__ float gumbel_from_bits(uint32_t bits) {
    const float TINY = 1.17549435e-38f;
    float f = __uint_as_float((bits >> 9) | 0x3f800000u) - 1.0f;
    float u = f * (1.0f - TINY) + TINY;
    u = fmaxf(TINY, u);
    return -logf(-logf(u));
}

// ---------------- fused scores + masked log-softmax + sample ----------------
__global__ void k_attn(const float* __restrict__ b2, const float* __restrict__ vt,
                       int l, uint32_t key0, uint32_t key1,
                       float* __restrict__ probs, float* __restrict__ tour) {
    int b = blockIdx.x, tid = threadIdx.x;  // 256 threads
    __shared__ float sb[Wn], sv[Wn], ssc[64];
    sb[tid] = b2[b * Wn + tid];
    sv[tid] = vt[tid];
    __syncthreads();
    int warp = tid >> 5, lane = tid & 31;
    for (int s = warp; s < Sn; s += 8) {
        if (g_mask[b * Sn + s]) continue;   // masked: score replaced by -1e5 anyway
        const float* row = g_blend1 + ((size_t)s * Bn + b) * Wn;
        float acc = 0.0f;
#pragma unroll
        for (int q = 0; q < 8; q++) {
            int w = lane + q * 32;
            acc += tanhf(row[w] + sb[w]) * sv[w];
        }
        for (int off = 16; off; off >>= 1) acc += __shfl_xor_sync(0xffffffffu, acc, off);
        if (lane == 0) ssc[s] = acc;
    }
    __syncthreads();
    if (warp != 0) return;
    int s0 = lane, s1 = lane + 32;
    const float NEG = -3.4e38f;
    float x0 = g_mask[b * Sn + s0] ? -100000.0f : ssc[s0];
    float x1 = NEG;
    if (s1 < Sn) x1 = g_mask[b * Sn + s1] ? -100000.0f : ssc[s1];
    float m = fmaxf(x0, x1);
    for (int off = 16; off; off >>= 1) m = fmaxf(m, __shfl_xor_sync(0xffffffffu, m, off));
    float sum = expf(x0 - m) + ((s1 < Sn) ? expf(x1 - m) : 0.0f);
    for (int off = 16; off; off >>= 1) sum += __shfl_xor_sync(0xffffffffu, sum, off);
    float lse = logf(sum);
    float lp0 = x0 - m - lse;
    float lp1 = x1 - m - lse;
    float* prow = probs + ((size_t)b * Ln + l) * Sn;
    prow[s0] = lp0;
    if (s1 < Sn) prow[s1] = lp1;
    float v0 = lp0 + gumbel_from_bits(threefry_xor(key0, key1, 0u, (uint32_t)(b * Sn + s0)));
    float v1 = NEG;
    if (s1 < Sn) v1 = lp1 + gumbel_from_bits(threefry_xor(key0, key1, 0u, (uint32_t)(b * Sn + s1)));
    float bv; int bi;
    if (v1 > v0) { bv = v1; bi = s1; } else { bv = v0; bi = s0; }
    for (int off = 16; off; off >>= 1) {
        float ov = __shfl_xor_sync(0xffffffffu, bv, off);
        int   oi = __shfl_xor_sync(0xffffffffu, bi, off);
        if (ov > bv || (ov == bv && oi < bi)) { bv = ov; bi = oi; }
    }
    if (lane == 0) {
        tour[(size_t)b * Ln + l] = (float)bi;
        g_mask[b * Sn + bi] = 1;
    }
}

// ---------------- host threefry ----------------
static void tf_host(uint32_t k0, uint32_t k1, uint32_t x0, uint32_t x1,
                    uint32_t& o0, uint32_t& o1) {
    uint32_t ks2 = k0 ^ k1 ^ 0x1BD11BDAu;
    x0 += k0; x1 += k1;
    const int ra[4] = {13, 15, 26, 6}, rb[4] = {17, 29, 16, 24};
    auto rl = [](uint32_t v, int d) { return (v << d) | (v >> (32 - d)); };
    for (int i = 0; i < 4; i++) { x0 += x1; x1 = rl(x1, ra[i]); x1 ^= x0; }
    x0 += k1; x1 += ks2 + 1u;
    for (int i = 0; i < 4; i++) { x0 += x1; x1 = rl(x1, rb[i]); x1 ^= x0; }
    x0 += ks2; x1 += k0 + 2u;
    for (int i = 0; i < 4; i++) { x0 += x1; x1 = rl(x1, ra[i]); x1 ^= x0; }
    x0 += k0; x1 += k1 + 3u;
    for (int i = 0; i < 4; i++) { x0 += x1; x1 = rl(x1, rb[i]); x1 ^= x0; }
    x0 += k1; x1 += ks2 + 4u;
    for (int i = 0; i < 4; i++) { x0 += x1; x1 = rl(x1, ra[i]); x1 ^= x0; }
    x0 += ks2; x1 += k0 + 5u;
    o0 = x0; o1 = x1;
}

#define SM_TOTAL 98304

extern "C" void kernel_launch(void* const* d_in, const int* in_sizes, int n_in,
                              void* d_out, int out_size) {
    const int*   input = (const int*)d_in[0];
    const float* emb   = (const float*)d_in[1];
    const float* eWih  = (const float*)d_in[2];
    const float* eWhh  = (const float*)d_in[3];
    const float* ebih  = (const float*)d_in[4];
    const float* ebhh  = (const float*)d_in[5];
    // d_in[6] = dec_Wih (unused: decoder input is always zero)
    const float* dWhh  = (const float*)d_in[7];
    const float* dbih  = (const float*)d_in[8];
    const float* dbhh  = (const float*)d_in[9];
    const float* W1    = (const float*)d_in[10];
    const float* W2    = (const float*)d_in[11];
    const float* vt    = (const float*)d_in[12];

    float* out   = (float*)d_out;
    float* probs = out;                               // [B, L, S]
    float* tour  = out + (size_t)Bn * Ln * Sn;        // [B, L] as float

    // one-time host-side objects (no device memory)
    static cudaStream_t s1 = nullptr;
    static cudaEvent_t evE[Sn], evG[Ln], evA[Ln];
    if (!s1) {
        cudaStreamCreateWithFlags(&s1, cudaStreamNonBlocking);
        for (int t = 0; t < Sn; t++) cudaEventCreateWithFlags(&evE[t], cudaEventDisableTiming);
        for (int l = 0; l < Ln; l++) {
            cudaEventCreateWithFlags(&evG[l], cudaEventDisableTiming);
            cudaEventCreateWithFlags(&evA[l], cudaEventDisableTiming);
        }
        cudaFuncSetAttribute(gemm_mma<0>, cudaFuncAttributeMaxDynamicSharedMemorySize, SM_TOTAL);
        cudaFuncSetAttribute(gemm_mma<1>, cudaFuncAttributeMaxDynamicSharedMemorySize, SM_TOTAL);
        cudaFuncSetAttribute(gemm_mma<2>, cudaFuncAttributeMaxDynamicSharedMemorySize, SM_TOTAL);
    }

    __half *p_hhi0, *p_hlo0, *p_hhi1, *p_hlo1, *p_enchi, *p_enclo;
    __half *p_eWhi, *p_eWlo, *p_dWhi, *p_dWlo, *p_W1hi, *p_W1lo;
    float *p_cE, *p_cD, *p_b1, *p_b2, *p_bd2, *p_P;
    cudaGetSymbolAddress((void**)&p_hhi0, g_hhi0);
    cudaGetSymbolAddress((void**)&p_hlo0, g_hlo0);
    cudaGetSymbolAddress((void**)&p_hhi1, g_hhi1);
    cudaGetSymbolAddress((void**)&p_hlo1, g_hlo1);
    cudaGetSymbolAddress((void**)&p_cE, g_cE);
    cudaGetSymbolAddress((void**)&p_cD, g_cD);
    cudaGetSymbolAddress((void**)&p_enchi, g_enchi);
    cudaGetSymbolAddress((void**)&p_enclo, g_enclo);
    cudaGetSymbolAddress((void**)&p_b1, g_blend1);
    cudaGetSymbolAddress((void**)&p_b2, g_blend2);
    cudaGetSymbolAddress((void**)&p_eWhi, g_eWhi);
    cudaGetSymbolAddress((void**)&p_eWlo, g_eWlo);
    cudaGetSymbolAddress((void**)&p_dWhi, g_dWhi);
    cudaGetSymbolAddress((void**)&p_dWlo, g_dWlo);
    cudaGetSymbolAddress((void**)&p_W1hi, g_W1hi);
    cudaGetSymbolAddress((void**)&p_W1lo, g_W1lo);
    cudaGetSymbolAddress((void**)&p_bd2, g_bias_dec2);
    cudaGetSymbolAddress((void**)&p_P, g_P);

    const int BHB = (Bn * Hn + 255) / 256;

    k_prep<<<(ND * Hn + 255) / 256, 256>>>(eWhh, dWhh, dbih, dbhh, W2, W1);
    k_prep_P<<<(Vn * Gn + 255) / 256, 256>>>(emb, eWih, ebih, ebhh);
    k_init<<<BHB, 256>>>();

    // -------- encoder: 50 fused GEMM+cell steps; blend1 slice t overlaps on
    //          s1 using the 40 idle CTA slots of the encoder wave ------------
    for (int t = 0; t < Sn; t++) {
        __half* ihi = (t & 1) ? p_hhi1 : p_hhi0;
        __half* ilo = (t & 1) ? p_hlo1 : p_hlo0;
        __half* ohi = (t & 1) ? p_hhi0 : p_hhi1;
        __half* olo = (t & 1) ? p_hlo0 : p_hlo1;
        gemm_mma<1><<<dim3(Gn / 128, Bn / 128), 256, SM_TOTAL>>>(
            ihi, ilo, Bn / 16, p_eWhi, p_eWlo, Gn / 8,
            nullptr, p_P, input, nullptr,
            ohi, olo, p_cE, p_enchi, p_enclo, p_cD, t);
        cudaEventRecord(evE[t], 0);
        cudaStreamWaitEvent(s1, evE[t], 0);
        // blend1 rows [t*Bn, (t+1)*Bn): grid 2x16 = 32 CTAs
        gemm_mma<0><<<dim3(Wn / 128, Bn / 128), 256, SM_TOTAL, s1>>>(
            p_enchi, p_enclo, BSn / 16, p_W1hi, p_W1lo, Wn / 8,
            nullptr, nullptr, nullptr, p_b1,
            nullptr, nullptr, nullptr, nullptr, nullptr, nullptr, t * Bn);
    }

    // decoder first cell (h_prev = 0), c0 = enc h49
    k_dec0<<<BHB, 256>>>();

    uint32_t K0[Ln], K1[Ln];
    for (int l = 0; l < Ln; l++) tf_host(0u, 42u, 0u, (uint32_t)l, K0[l], K1[l]);

    for (int l = 0; l < Ln; l++) {
        __half* ihi = (l & 1) ? p_hhi1 : p_hhi0;
        __half* ilo = (l & 1) ? p_hlo1 : p_hlo0;
        __half* ohi = (l & 1) ? p_hhi0 : p_hhi1;
        __half* olo = (l & 1) ? p_hlo0 : p_hlo1;
        float* b2buf = p_b2 + (size_t)(l & 1) * Bn * Wn;
        // blend2 parity buffer reused every 2 steps: wait for attn_{l-2}
        if (l >= 2) cudaStreamWaitEvent(0, evA[l - 2], 0);
        gemm_mma<2><<<dim3(ND / 128, Bn / 128), 256, SM_TOTAL>>>(
            ihi, ilo, Bn / 16, p_dWhi, p_dWlo, ND / 8,
            p_bd2, nullptr, nullptr, b2buf,
            ohi, olo, p_cD, nullptr, nullptr, nullptr, 0);
        cudaEventRecord(evG[l], 0);
        cudaStreamWaitEvent(s1, evG[l], 0);
        k_attn<<<Bn, 256, 0, s1>>>(b2buf, vt, l, K0[l], K1[l], probs, tour);
        cudaEventRecord(evA[l], s1);
    }
    // join: main stream waits for the last attn
    cudaStreamWaitEvent(0, evA[Ln - 1], 0);
    (void)in_sizes; (void)n_in; (void)out_size;
}

// round 16
// speedup vs baseline: 2.4958x; 1.0309x over previous
#include <cuda_runtime.h>
#include <cuda_fp16.h>
#include <cstdint>
#include <math.h>

// Problem constants
#define Bn 2048
#define Sn 50
#define En 256
#define Hn 512
#define Gn 2048        // 4*H
#define Wn 256
#define Ln 50
#define ND (Gn + Wn)   // 2304 : [interleaved dec gates | W2 rows]
#define Vn 51
#define BSn (Bn * Sn)

// ---------------- device scratch (fp16 fragment-order layouts) ----------------
__device__ __half g_hhi0[Bn * Hn];
__device__ __half g_hlo0[Bn * Hn];
__device__ __half g_hhi1[Bn * Hn];
__device__ __half g_hlo1[Bn * Hn];
__device__ float  g_cE[Bn * Hn];                    // encoder cell state [m][j]
__device__ float  g_cD[Bn * Hn];                    // decoder cell state
__device__ __half g_enchi[(size_t)BSn * Hn];        // enc states, A-frag layout
__device__ __half g_enclo[(size_t)BSn * Hn];
__device__ float  g_blend1[(size_t)BSn * Wn];       // [(t*Bn+b)][w] row-major
__device__ float  g_blend2[2 * Bn * Wn];            // double-buffered by step parity
__device__ unsigned char g_mask[Bn * Sn];
__device__ __half g_eW[(size_t)Gn * Hn * 2];        // enc Whh, B-frag, hi|lo interleaved
__device__ __half g_dW[(size_t)ND * Hn * 2];        // dec Whh | W2, hi|lo interleaved
__device__ __half g_W1c[Wn * Hn * 2];               // W1, hi|lo interleaved
__device__ float  g_bias_dec2[Gn];
__device__ float  g_P[Vn * Gn];                     // emb@Wih^T + enc bias (fp32 exact)

// ---------------- helpers ----------------
// fast sigmoid/tanh: MUFU.EX2 + MUFU.RCP paths, ~2-4e-7 relative error
// (same error class as the validated 3-product fp16 GEMM split)
__device__ __forceinline__ float sigf(float x) {
    return __fdividef(1.0f, 1.0f + exp2f(x * -1.44269504f));
}
__device__ __forceinline__ float tanhfast(float x) {
    float xc = fminf(fmaxf(x, -20.0f), 20.0f);
    float a = exp2f(xc * 2.88539008f);   // e^{2x}, finite for |x|<=20
    return __fdividef(a - 1.0f, a + 1.0f);
}

__device__ __forceinline__ void hsplit(float x, __half& hi, __half& lo) {
    hi = __float2half_rn(x);
    lo = __float2half_rn(x - __half2float(hi));
}

__device__ __forceinline__ void cp16(uint32_t dst, const void* src) {
    asm volatile("cp.async.cg.shared.global [%0], [%1], 16;\n" :: "r"(dst), "l"(src));
}

// mma.sync m16n8k16 fp16: D(f32) += A(f16)*B(f16)   (row.col)
#define MMA16(accp, av, b0, b1)                                            \
    asm volatile(                                                          \
        "mma.sync.aligned.m16n8k16.row.col.f32.f16.f16.f32 "               \
        "{%0,%1,%2,%3}, {%4,%5,%6,%7}, {%8,%9}, {%0,%1,%2,%3};"            \
        : "+f"((accp)[0]), "+f"((accp)[1]), "+f"((accp)[2]), "+f"((accp)[3]) \
        : "r"((av).x), "r"((av).y), "r"((av).z), "r"((av).w),              \
          "r"(b0), "r"(b1))

// A-fragment (m16n8k16 f16) half-element index for A[m][k]
__device__ __forceinline__ size_t afrag(size_t m, int k, int mtiles) {
    int kc = k >> 5, s = (k >> 4) & 1, k16 = k & 15;
    int tt = ((int)(m & 7)) * 4 + ((k16 >> 1) & 3);
    int r = (int)((m >> 3) & 1) + (((k16 >> 3) & 1) << 1);
    return ((((size_t)(kc * 2 + s) * mtiles + (m >> 4)) * 32 + tt) * 4 + r) * 2 + (k16 & 1);
}
// B-fragment combined hi|lo layout: 16B unit per (tile,thread) = [hi 8B | lo 8B]
__device__ __forceinline__ size_t bfragc(int n, int k, int ntiles, int lo) {
    int kc = k >> 5, s = (k >> 4) & 1, k16 = k & 15;
    int tt = (n & 7) * 4 + ((k16 >> 1) & 3);
    int r = (k16 >> 3) & 1;
    return (((size_t)(kc * 2 + s) * ntiles + (n >> 3)) * 32 + tt) * 8 + lo * 4 + r * 2 + (k16 & 1);
}

// ---------------- prep kernels ----------------
__global__ void k_prep(const float* __restrict__ eWhh,
                       const float* __restrict__ dWhh, const float* __restrict__ dbih,
                       const float* __restrict__ dbhh, const float* __restrict__ W2,
                       const float* __restrict__ W1) {
    int idx = blockIdx.x * blockDim.x + threadIdx.x;
    if (idx < Gn * Hn) {
        int n2 = idx / Hn, k = idx % Hn;
        int g = n2 & 3, j = n2 >> 2;
        __half hi, lo;
        hsplit(eWhh[(g * Hn + j) * Hn + k], hi, lo);
        g_eW[bfragc(n2, k, Gn / 8, 0)] = hi;
        g_eW[bfragc(n2, k, Gn / 8, 1)] = lo;
    }
    if (idx < ND * Hn) {
        int n2 = idx / Hn, k = idx % Hn;
        float v;
        if (n2 < Gn) {
            int g = n2 & 3, j = n2 >> 2;
            v = dWhh[(g * Hn + j) * Hn + k];
        } else {
            v = W2[(size_t)(n2 - Gn) * Hn + k];
        }
        __half hi, lo;
        hsplit(v, hi, lo);
        g_dW[bfragc(n2, k, ND / 8, 0)] = hi;
        g_dW[bfragc(n2, k, ND / 8, 1)] = lo;
    }
    if (idx < Wn * Hn) {
        int w = idx / Hn, k = idx % Hn;
        __half hi, lo;
        hsplit(W1[idx], hi, lo);
        g_W1c[bfragc(w, k, Wn / 8, 0)] = hi;
        g_W1c[bfragc(w, k, Wn / 8, 1)] = lo;
    }
    if (idx < Gn) {
        int g = idx & 3, j = idx >> 2;
        int r = g * Hn + j;
        g_bias_dec2[idx] = dbih[r] + dbhh[r];
    }
}

__global__ void k_prep_P(const float* __restrict__ emb, const float* __restrict__ eWih,
                         const float* __restrict__ ebih, const float* __restrict__ ebhh) {
    int idx = blockIdx.x * blockDim.x + threadIdx.x;
    if (idx >= Vn * Gn) return;
    int v = idx / Gn, n2 = idx % Gn;
    int g = n2 & 3, j = n2 >> 2;
    int r = g * Hn + j;
    const float4* e = reinterpret_cast<const float4*>(emb + (size_t)v * En);
    const float4* w = reinterpret_cast<const float4*>(eWih + (size_t)r * En);
    float s = 0.0f;
    #pragma unroll 8
    for (int k = 0; k < En / 4; k++) {
        float4 a = __ldg(e + k), b = __ldg(w + k);
        s += a.x * b.x + a.y * b.y + a.z * b.z + a.w * b.w;
    }
    g_P[idx] = s + ebih[r] + ebhh[r];
}

__global__ void k_init() {
    int idx = blockIdx.x * blockDim.x + threadIdx.x;
    if (idx < Bn * Hn) {
        g_hhi0[idx] = __float2half(0.0f);
        g_hlo0[idx] = __float2half(0.0f);
        g_cE[idx] = 0.0f;
    }
    if (idx < Bn * Sn) g_mask[idx] = 0;
}

// decoder first cell: gates = bias only; c0 already in g_cD (enc h49)
__global__ void k_dec0() {
    int idx = blockIdx.x * blockDim.x + threadIdx.x;
    if (idx >= Bn * Hn) return;
    int b = idx / Hn, j = idx % Hn;
    float gi = g_bias_dec2[4 * j + 0], gf = g_bias_dec2[4 * j + 1];
    float gg = g_bias_dec2[4 * j + 2], go = g_bias_dec2[4 * j + 3];
    float c0 = g_cD[idx];
    float cn = sigf(gf) * c0 + sigf(gi) * tanhfast(gg);
    float hn = sigf(go) * tanhfast(cn);
    g_cD[idx] = cn;
    __half hi, lo;
    hsplit(hn, hi, lo);
    size_t ao = afrag((size_t)b, j, Bn / 16);
    g_hhi0[ao] = hi; g_hlo0[ao] = lo;
}

// ---------------- fp16 mma.sync GEMM, 3-product split, 128x128 CTA tile -----
// 256 threads, 8 warps (4m x 2n), warp tile 32x64.
// Triple-buffered cp.async (32KB/chunk), one __syncthreads per chunk.
// B hi|lo interleaved: one LDS.128 yields both fragments.
// MODE 0: plain store (blend1 slice; t = global row offset)
// MODE 1: encoder LSTM   MODE 2: dec LSTM | blend2
template <int MODE>
__global__ __launch_bounds__(256, 2) void gemm_mma(
    const __half* __restrict__ Ahi, const __half* __restrict__ Alo, int Mtiles,
    const __half* __restrict__ Bc, int Ntiles,
    const float* __restrict__ bias2, const float* __restrict__ P,
    const int* __restrict__ tok,
    float* __restrict__ Cout,
    __half* __restrict__ hhi, __half* __restrict__ hlo,
    float* __restrict__ cst,
    __half* __restrict__ enchi, __half* __restrict__ enclo,
    float* __restrict__ cD, int t) {
    extern __shared__ char smem[];
    const int tid = threadIdx.x;
    const int lane = tid & 31, wid = tid >> 5;
    const int bm = blockIdx.y * 128 + (MODE == 0 ? t : 0);  // MODE0: t = row offset
    const int bn = blockIdx.x * 128;
    const int bm16 = bm >> 4, bn8 = bn >> 3;
    const int mw = wid & 3, nw = wid >> 2;        // mw 0..3 (32 rows), nw 0..1 (64 cols)

    float acc[2][8][4];
#pragma unroll
    for (int i = 0; i < 2; i++)
#pragma unroll
        for (int jn = 0; jn < 8; jn++)
#pragma unroll
            for (int p = 0; p < 4; p++) acc[i][jn][p] = 0.0f;

    // smem per buffer: Ahi 8KB | Alo 8KB | B(combined) 16KB = 32KB
    auto issue = [&](int c, int buf) {
#pragma unroll
        for (int q = 0; q < 8; q++) {
            int cid = tid + q * 256;              // 2048 x 16B chunks
            const __half* src;
            uint32_t dof;
            if (cid < 1024) {
                int arr = cid >> 9;               // 0:Ahi 1:Alo
                int within = cid & 511;
                int s = within >> 8, rest = within & 255;
                const __half* base = arr ? Alo : Ahi;
                src = base + ((size_t)(c * 2 + s) * Mtiles + bm16) * 256 + rest * 8;
                dof = (uint32_t)(buf * 32768 + arr * 8192 + within * 16);
            } else {
                int within = cid - 1024;          // 0..1023
                int s = within >> 9, rest = within & 511;
                src = Bc + ((size_t)(c * 2 + s) * Ntiles + bn8) * 256 + rest * 8;
                dof = (uint32_t)(buf * 32768 + 16384 + within * 16);
            }
            cp16((uint32_t)__cvta_generic_to_shared(smem + dof), src);
        }
        asm volatile("cp.async.commit_group;\n");
    };

    issue(0, 0);
    issue(1, 1);
#pragma unroll 1
    for (int c = 0; c < 16; c++) {
        const int buf = c % 3;
        if (c < 15) { asm volatile("cp.async.wait_group 1;\n"); }
        else        { asm volatile("cp.async.wait_group 0;\n"); }
        __syncthreads();
        if (c + 2 < 16) issue(c + 2, (c + 2) % 3);
#pragma unroll
        for (int s = 0; s < 2; s++) {
            uint4 ah[2], al[2];
#pragma unroll
            for (int mt = 0; mt < 2; mt++) {
                int moff = buf * 32768 + s * 4096 + (mw * 2 + mt) * 512 + lane * 16;
                ah[mt] = *reinterpret_cast<const uint4*>(smem + moff);
                al[mt] = *reinterpret_cast<const uint4*>(smem + moff + 8192);
            }
            uint4 bq[8];
#pragma unroll
            for (int nt = 0; nt < 8; nt++) {
                int boff = buf * 32768 + 16384 + s * 8192 + (nw * 8 + nt) * 512 + lane * 16;
                bq[nt] = *reinterpret_cast<const uint4*>(smem + boff);
            }
            // product-major: same-acc reuse distance = 16 MMAs
#pragma unroll
            for (int nt = 0; nt < 8; nt++) {
                MMA16(acc[0][nt], ah[0], bq[nt].x, bq[nt].y);
                MMA16(acc[1][nt], ah[1], bq[nt].x, bq[nt].y);
            }
#pragma unroll
            for (int nt = 0; nt < 8; nt++) {
                MMA16(acc[0][nt], ah[0], bq[nt].z, bq[nt].w);
                MMA16(acc[1][nt], ah[1], bq[nt].z, bq[nt].w);
            }
#pragma unroll
            for (int nt = 0; nt < 8; nt++) {
                MMA16(acc[0][nt], al[0], bq[nt].x, bq[nt].y);
                MMA16(acc[1][nt], al[1], bq[nt].x, bq[nt].y);
                // lo*lo dropped: 2^-22 class, validated in R9/R10
            }
        }
    }

    // ---------------- epilogue ----------------
    if (MODE == 0 || (MODE == 2 && bn >= Gn)) {
#pragma unroll
        for (int mt = 0; mt < 2; mt++)
#pragma unroll
            for (int nt = 0; nt < 8; nt++) {
                int row = bm + mw * 32 + mt * 16 + (lane >> 2);
                int col = bn + nw * 64 + nt * 8 + (lane & 3) * 2;
                if (MODE == 2) col -= Gn;
                float* dst = Cout + (size_t)row * Wn + col;
                *reinterpret_cast<float2*>(dst) =
                    make_float2(acc[mt][nt][0], acc[mt][nt][1]);
                *reinterpret_cast<float2*>(dst + 8 * Wn) =
                    make_float2(acc[mt][nt][2], acc[mt][nt][3]);
            }
    } else {
        float* gsm = reinterpret_cast<float*>(smem);
        __syncthreads();   // all warps done reading smem buffers before reuse
#pragma unroll
        for (int mt = 0; mt < 2; mt++)
#pragma unroll
            for (int nt = 0; nt < 8; nt++) {
                int rl = mw * 32 + mt * 16 + (lane >> 2);
                int cl = nw * 64 + nt * 8 + (lane & 3) * 2;
                *reinterpret_cast<float2*>(&gsm[rl * 132 + cl]) =
                    make_float2(acc[mt][nt][0], acc[mt][nt][1]);
                *reinterpret_cast<float2*>(&gsm[(rl + 8) * 132 + cl]) =
                    make_float2(acc[mt][nt][2], acc[mt][nt][3]);
            }
        __syncthreads();
#pragma unroll 1
        for (int q = 0; q < 16; q++) {
            int idx = q * 256 + tid;
            int ml = idx >> 5, j4 = idx & 31;
            float4 gv = *reinterpret_cast<const float4*>(&gsm[ml * 132 + j4 * 4]);
            int mrow = bm + ml;
            int n = bn + j4 * 4;
            int j = n >> 2;
            float g0 = gv.x, g1 = gv.y, g2 = gv.z, g3 = gv.w;
            if (MODE == 1) {
                int tokv = tok[mrow * Sn + t];
                float4 pv = *reinterpret_cast<const float4*>(P + (size_t)tokv * Gn + n);
                g0 += pv.x; g1 += pv.y; g2 += pv.z; g3 += pv.w;
            } else {
                float4 bv = *reinterpret_cast<const float4*>(bias2 + n);
                g0 += bv.x; g1 += bv.y; g2 += bv.z; g3 += bv.w;
            }
            float co = cst[mrow * Hn + j];
            float cn = sigf(g1) * co + sigf(g0) * tanhfast(g2);
            float hn = sigf(g3) * tanhfast(cn);
            cst[mrow * Hn + j] = cn;
            __half hi, lo;
            hsplit(hn, hi, lo);
            size_t ao = afrag((size_t)mrow, j, Bn / 16);
            hhi[ao] = hi; hlo[ao] = lo;
            if (MODE == 1) {
                size_t er = (size_t)t * Bn + mrow;
                size_t eo = afrag(er, j, BSn / 16);
                enchi[eo] = hi; enclo[eo] = lo;
                if (t == Sn - 1) cD[mrow * Hn + j] = hn;
            }
        }
    }
}

// ---------------- threefry2x32 (JAX-compatible) ----------------
__device__ __forceinline__ uint32_t rotl32(uint32_t v, int d) { return (v << d) | (v >> (32 - d)); }

__device__ uint32_t threefry_xor(uint32_t k0, uint32_t k1, uint32_t x0, uint32_t x1) {
    uint32_t ks2 = k0 ^ k1 ^ 0x1BD11BDAu;
    x0 += k0; x1 += k1;
    const int ra[4] = {13, 15, 26, 6}, rb[4] = {17, 29, 16, 24};
#pragma unroll
    for (int i = 0; i < 4; i++) { x0 += x1; x1 = rotl32(x1, ra[i]); x1 ^= x0; }
    x0 += k1; x1 += ks2 + 1u;
#pragma unroll
    for (int i = 0; i < 4; i++) { x0 += x1; x1 = rotl32(x1, rb[i]); x1 ^= x0; }
    x0 += ks2; x1 += k0 + 2u;
#pragma unroll
    for (int i = 0; i < 4; i++) { x0 += x1; x1 = rotl32(x1, ra[i]); x1 ^= x0; }
    x0 += k0; x1 += k1 + 3u;
#pragma unroll
    for (int i = 0; i < 4; i++) { x0 += x1; x1 = rotl32(x1, rb[i]); x1 ^= x0; }
    x0 += k1; x1 += ks2 + 4u;
#pragma unroll
    for (int i = 0; i < 4; i++) { x0 += x1; x1 = rotl32(x1, ra[i]); x1 ^= x0; }
    x0 += ks2; x1 += k0 + 5u;
    return x0 ^ x1;  // partitionable 32-bit random_bits = out0 ^ out1
}

__device__ __forceinline__ float gumbel_from_bits(uint32_t bits) {
    const float TINY = 1.17549435e-38f;
    float f = __uint_as_float((bits >> 9) | 0x3f800000u) - 1.0f;
    float u = f * (1.0f - TINY) + TINY;
    u = fmaxf(TINY, u);
    return -logf(-logf(u));
}

// ---------------- fused scores + masked log-softmax + sample ----------------
__global__ void k_attn(const float* __restrict__ b2, const float* __restrict__ vt,
                       int l, uint32_t key0, uint32_t key1,
                       float* __restrict__ probs, float* __restrict__ tour) {
    int b = blockIdx.x, tid = threadIdx.x;  // 256 threads
    __shared__ float sb[Wn], sv[Wn], ssc[64];
    sb[tid] = b2[b * Wn + tid];
    sv[tid] = vt[tid];
    __syncthreads();
    int warp = tid >> 5, lane = tid & 31;
    for (int s = warp; s < Sn; s += 8) {
        if (g_mask[b * Sn + s]) continue;   // masked: score replaced by -1e5 anyway
        const float* row = g_blend1 + ((size_t)s * Bn + b) * Wn;
        float acc = 0.0f;
#pragma unroll
        for (int q = 0; q < 8; q++) {
            int w = lane + q * 32;
            acc += tanhf(row[w] + sb[w]) * sv[w];
        }
        for (int off = 16; off; off >>= 1) acc += __shfl_xor_sync(0xffffffffu, acc, off);
        if (lane == 0) ssc[s] = acc;
    }
    __syncthreads();
    if (warp != 0) return;
    int s0 = lane, s1 = lane + 32;
    const float NEG = -3.4e38f;
    float x0 = g_mask[b * Sn + s0] ? -100000.0f : ssc[s0];
    float x1 = NEG;
    if (s1 < Sn) x1 = g_mask[b * Sn + s1] ? -100000.0f : ssc[s1];
    float m = fmaxf(x0, x1);
    for (int off = 16; off; off >>= 1) m = fmaxf(m, __shfl_xor_sync(0xffffffffu, m, off));
    float sum = expf(x0 - m) + ((s1 < Sn) ? expf(x1 - m) : 0.0f);
    for (int off = 16; off; off >>= 1) sum += __shfl_xor_sync(0xffffffffu, sum, off);
    float lse = logf(sum);
    float lp0 = x0 - m - lse;
    float lp1 = x1 - m - lse;
    float* prow = probs + ((size_t)b * Ln + l) * Sn;
    prow[s0] = lp0;
    if (s1 < Sn) prow[s1] = lp1;
    float v0 = lp0 + gumbel_from_bits(threefry_xor(key0, key1, 0u, (uint32_t)(b * Sn + s0)));
    float v1 = NEG;
    if (s1 < Sn) v1 = lp1 + gumbel_from_bits(threefry_xor(key0, key1, 0u, (uint32_t)(b * Sn + s1)));
    float bv; int bi;
    if (v1 > v0) { bv = v1; bi = s1; } else { bv = v0; bi = s0; }
    for (int off = 16; off; off >>= 1) {
        float ov = __shfl_xor_sync(0xffffffffu, bv, off);
        int   oi = __shfl_xor_sync(0xffffffffu, bi, off);
        if (ov > bv || (ov == bv && oi < bi)) { bv = ov; bi = oi; }
    }
    if (lane == 0) {
        tour[(size_t)b * Ln + l] = (float)bi;
        g_mask[b * Sn + bi] = 1;
    }
}

// ---------------- host threefry ----------------
static void tf_host(uint32_t k0, uint32_t k1, uint32_t x0, uint32_t x1,
                    uint32_t& o0, uint32_t& o1) {
    uint32_t ks2 = k0 ^ k1 ^ 0x1BD11BDAu;
    x0 += k0; x1 += k1;
    const int ra[4] = {13, 15, 26, 6}, rb[4] = {17, 29, 16, 24};
    auto rl = [](uint32_t v, int d) { return (v << d) | (v >> (32 - d)); };
    for (int i = 0; i < 4; i++) { x0 += x1; x1 = rl(x1, ra[i]); x1 ^= x0; }
    x0 += k1; x1 += ks2 + 1u;
    for (int i = 0; i < 4; i++) { x0 += x1; x1 = rl(x1, rb[i]); x1 ^= x0; }
    x0 += ks2; x1 += k0 + 2u;
    for (int i = 0; i < 4; i++) { x0 += x1; x1 = rl(x1, ra[i]); x1 ^= x0; }
    x0 += k0; x1 += k1 + 3u;
    for (int i = 0; i < 4; i++) { x0 += x1; x1 = rl(x1, rb[i]); x1 ^= x0; }
    x0 += k1; x1 += ks2 + 4u;
    for (int i = 0; i < 4; i++) { x0 += x1; x1 = rl(x1, ra[i]); x1 ^= x0; }
    x0 += ks2; x1 += k0 + 5u;
    o0 = x0; o1 = x1;
}

#define SM_TOTAL 98304

extern "C" void kernel_launch(void* const* d_in, const int* in_sizes, int n_in,
                              void* d_out, int out_size) {
    const int*   input = (const int*)d_in[0];
    const float* emb   = (const float*)d_in[1];
    const float* eWih  = (const float*)d_in[2];
    const float* eWhh  = (const float*)d_in[3];
    const float* ebih  = (const float*)d_in[4];
    const float* ebhh  = (const float*)d_in[5];
    // d_in[6] = dec_Wih (unused: decoder input is always zero)
    const float* dWhh  = (const float*)d_in[7];
    const float* dbih  = (const float*)d_in[8];
    const float* dbhh  = (const float*)d_in[9];
    const float* W1    = (const float*)d_in[10];
    const float* W2    = (const float*)d_in[11];
    const float* vt    = (const float*)d_in[12];

    float* out   = (float*)d_out;
    float* probs = out;                               // [B, L, S]
    float* tour  = out + (size_t)Bn * Ln * Sn;        // [B, L] as float

    // one-time host-side objects (no device memory)
    static cudaStream_t s1 = nullptr;
    static cudaEvent_t evE[Sn], evG[Ln], evA[Ln];
    if (!s1) {
        cudaStreamCreateWithFlags(&s1, cudaStreamNonBlocking);
        for (int t = 0; t < Sn; t++) cudaEventCreateWithFlags(&evE[t], cudaEventDisableTiming);
        for (int l = 0; l < Ln; l++) {
            cudaEventCreateWithFlags(&evG[l], cudaEventDisableTiming);
            cudaEventCreateWithFlags(&evA[l], cudaEventDisableTiming);
        }
        cudaFuncSetAttribute(gemm_mma<0>, cudaFuncAttributeMaxDynamicSharedMemorySize, SM_TOTAL);
        cudaFuncSetAttribute(gemm_mma<1>, cudaFuncAttributeMaxDynamicSharedMemorySize, SM_TOTAL);
        cudaFuncSetAttribute(gemm_mma<2>, cudaFuncAttributeMaxDynamicSharedMemorySize, SM_TOTAL);
    }

    __half *p_hhi0, *p_hlo0, *p_hhi1, *p_hlo1, *p_enchi, *p_enclo;
    __half *p_eW, *p_dW, *p_W1c;
    float *p_cE, *p_cD, *p_b1, *p_b2, *p_bd2, *p_P;
    cudaGetSymbolAddress((void**)&p_hhi0, g_hhi0);
    cudaGetSymbolAddress((void**)&p_hlo0, g_hlo0);
    cudaGetSymbolAddress((void**)&p_hhi1, g_hhi1);
    cudaGetSymbolAddress((void**)&p_hlo1, g_hlo1);
    cudaGetSymbolAddress((void**)&p_cE, g_cE);
    cudaGetSymbolAddress((void**)&p_cD, g_cD);
    cudaGetSymbolAddress((void**)&p_enchi, g_enchi);
    cudaGetSymbolAddress((void**)&p_enclo, g_enclo);
    cudaGetSymbolAddress((void**)&p_b1, g_blend1);
    cudaGetSymbolAddress((void**)&p_b2, g_blend2);
    cudaGetSymbolAddress((void**)&p_eW, g_eW);
    cudaGetSymbolAddress((void**)&p_dW, g_dW);
    cudaGetSymbolAddress((void**)&p_W1c, g_W1c);
    cudaGetSymbolAddress((void**)&p_bd2, g_bias_dec2);
    cudaGetSymbolAddress((void**)&p_P, g_P);

    const int BHB = (Bn * Hn + 255) / 256;

    k_prep<<<(ND * Hn + 255) / 256, 256>>>(eWhh, dWhh, dbih, dbhh, W2, W1);
    k_prep_P<<<(Vn * Gn + 255) / 256, 256>>>(emb, eWih, ebih, ebhh);
    k_init<<<BHB, 256>>>();

    // -------- encoder: 50 fused GEMM+cell steps; blend1 slice t overlaps on
    //          s1 using the idle CTA slots of the encoder wave ---------------
    for (int t = 0; t < Sn; t++) {
        __half* ihi = (t & 1) ? p_hhi1 : p_hhi0;
        __half* ilo = (t & 1) ? p_hlo1 : p_hlo0;
        __half* ohi = (t & 1) ? p_hhi0 : p_hhi1;
        __half* olo = (t & 1) ? p_hlo0 : p_hlo1;
        gemm_mma<1><<<dim3(Gn / 128, Bn / 128), 256, SM_TOTAL>>>(
            ihi, ilo, Bn / 16, p_eW, Gn / 8,
            nullptr, p_P, input, nullptr,
            ohi, olo, p_cE, p_enchi, p_enclo, p_cD, t);
        cudaEventRecord(evE[t], 0);
        cudaStreamWaitEvent(s1, evE[t], 0);
        // blend1 rows [t*Bn, (t+1)*Bn): grid 2x16 = 32 CTAs
        gemm_mma<0><<<dim3(Wn / 128, Bn / 128), 256, SM_TOTAL, s1>>>(
            p_enchi, p_enclo, BSn / 16, p_W1c, Wn / 8,
            nullptr, nullptr, nullptr, p_b1,
            nullptr, nullptr, nullptr, nullptr, nullptr, nullptr, t * Bn);
    }

    // decoder first cell (h_prev = 0), c0 = enc h49
    k_dec0<<<BHB, 256>>>();

    uint32_t K0[Ln], K1[Ln];
    for (int l = 0; l < Ln; l++) tf_host(0u, 42u, 0u, (uint32_t)l, K0[l], K1[l]);

    for (int l = 0; l < Ln; l++) {
        __half* ihi = (l & 1) ? p_hhi1 : p_hhi0;
        __half* ilo = (l & 1) ? p_hlo1 : p_hlo0;
        __half* ohi = (l & 1) ? p_hhi0 : p_hhi1;
        __half* olo = (l & 1) ? p_hlo0 : p_hlo1;
        float* b2buf = p_b2 + (size_t)(l & 1) * Bn * Wn;
        // blend2 parity buffer reused every 2 steps: wait for attn_{l-2}
        if (l >= 2) cudaStreamWaitEvent(0, evA[l - 2], 0);
        gemm_mma<2><<<dim3(ND / 128, Bn / 128), 256, SM_TOTAL>>>(
            ihi, ilo, Bn / 16, p_dW, ND / 8,
            p_bd2, nullptr, nullptr, b2buf,
            ohi, olo, p_cD, nullptr, nullptr, nullptr, 0);
        cudaEventRecord(evG[l], 0);
        cudaStreamWaitEvent(s1, evG[l], 0);
        k_attn<<<Bn, 256, 0, s1>>>(b2buf, vt, l, K0[l], K1[l], probs, tour);
        cudaEventRecord(evA[l], s1);
    }
    // join: main stream waits for the last attn
    cudaStreamWaitEvent(0, evA[Ln - 1], 0);
    (void)in_sizes; (void)n_in; (void)out_size;
}